// round 1
// baseline (speedup 1.0000x reference)
#include <cuda_runtime.h>
#include <cuda_bf16.h>
#include <math.h>

// ---------------------------------------------------------------------------
// Problem constants
// ---------------------------------------------------------------------------
#define BB 4
#define TT 2048
#define DD 1024
#define HH 16
#define HD 64
#define FF 4096
#define MM (BB * TT)       // 8192 rows
#define EPS 1e-5f

// ---------------------------------------------------------------------------
// Scratch (allocation-free: __device__ globals)
// ---------------------------------------------------------------------------
__device__ float g_h   [(size_t)MM * DD];
__device__ float g_q   [(size_t)MM * DD];
__device__ float g_k   [(size_t)MM * DD];
__device__ float g_v   [(size_t)MM * DD];
__device__ float g_attn[(size_t)MM * DD];
__device__ float g_x2  [(size_t)MM * DD];
__device__ float g_h2  [(size_t)MM * DD];
__device__ float g_ff1 [(size_t)MM * FF];

// ---------------------------------------------------------------------------
// LayerNorm: one block (256 threads) per row of 1024
// ---------------------------------------------------------------------------
__global__ __launch_bounds__(256) void layernorm_kernel(
    const float* __restrict__ x, const float* __restrict__ gamma,
    const float* __restrict__ beta, float* __restrict__ out)
{
    __shared__ float shs[8], shss[8];
    __shared__ float s_mean, s_inv;
    const int row = blockIdx.x;
    const int tid = threadIdx.x;

    const float4 xv = *(const float4*)(x + (size_t)row * DD + tid * 4);
    float s  = xv.x + xv.y + xv.z + xv.w;
    float ss = xv.x * xv.x + xv.y * xv.y + xv.z * xv.z + xv.w * xv.w;
    #pragma unroll
    for (int o = 16; o > 0; o >>= 1) {
        s  += __shfl_down_sync(0xffffffffu, s, o);
        ss += __shfl_down_sync(0xffffffffu, ss, o);
    }
    if ((tid & 31) == 0) { shs[tid >> 5] = s; shss[tid >> 5] = ss; }
    __syncthreads();
    if (tid == 0) {
        float S = 0.f, SS = 0.f;
        #pragma unroll
        for (int i = 0; i < 8; i++) { S += shs[i]; SS += shss[i]; }
        float mean = S * (1.0f / DD);
        float var  = SS * (1.0f / DD) - mean * mean;
        s_mean = mean;
        s_inv  = rsqrtf(var + EPS);
    }
    __syncthreads();
    const float mean = s_mean, inv = s_inv;
    const float4 gv = *(const float4*)(gamma + tid * 4);
    const float4 bv = *(const float4*)(beta  + tid * 4);
    float4 o;
    o.x = gv.x * (xv.x - mean) * inv + bv.x;
    o.y = gv.y * (xv.y - mean) * inv + bv.y;
    o.z = gv.z * (xv.z - mean) * inv + bv.z;
    o.w = gv.w * (xv.w - mean) * inv + bv.w;
    *(float4*)(out + (size_t)row * DD + tid * 4) = o;
}

// ---------------------------------------------------------------------------
// GELU (tanh approximation, matches reference)
// ---------------------------------------------------------------------------
__device__ __forceinline__ float gelu_f(float x)
{
    const float c = 0.7978845608028654f;  // sqrt(2/pi)
    float inner = c * (x + 0.044715f * x * x * x);
    return 0.5f * x * (1.0f + tanhf(inner));
}

// ---------------------------------------------------------------------------
// Tiled SGEMM: C[M,N] = A[M,K] @ B[K,N]  (+bias) (+gelu) (+residual)
// BM=BN=128, BK=16, 256 threads, 8x8 microtile per thread.
// M,N divisible by 128; K divisible by 16 (true for all calls here).
// ---------------------------------------------------------------------------
#define GBM 128
#define GBN 128
#define GBK 16
#define APAD 4

__global__ __launch_bounds__(256) void gemm_kernel(
    const float* __restrict__ A, const float* __restrict__ Bm,
    const float* __restrict__ bias,   // may be null
    const float* __restrict__ resid,  // may be null
    float* __restrict__ C,
    int Mdim, int Ndim, int Kdim, int do_gelu)
{
    __shared__ float As[GBK][GBM + APAD];
    __shared__ float Bs[GBK][GBN];

    const int tid = threadIdx.x;
    const int tx = tid & 15;        // 0..15
    const int ty = tid >> 4;        // 0..15
    const int m0 = blockIdx.y * GBM;
    const int n0 = blockIdx.x * GBN;

    // loader indices
    const int arow = tid >> 2;            // 0..63
    const int acol = (tid & 3) << 2;      // 0,4,8,12
    const int brow = tid >> 5;            // 0..7
    const int bcol = (tid & 31) << 2;     // 0..124

    const float* Abase = A + (size_t)m0 * Kdim;

    float acc[8][8];
    #pragma unroll
    for (int i = 0; i < 8; i++)
        #pragma unroll
        for (int j = 0; j < 8; j++) acc[i][j] = 0.f;

    for (int k0 = 0; k0 < Kdim; k0 += GBK) {
        // global loads (issued before sync to overlap with previous compute)
        float4 a0 = *(const float4*)(Abase + (size_t)arow        * Kdim + k0 + acol);
        float4 a1 = *(const float4*)(Abase + (size_t)(arow + 64) * Kdim + k0 + acol);
        float4 b0 = *(const float4*)(Bm + (size_t)(k0 + brow)     * Ndim + n0 + bcol);
        float4 b1 = *(const float4*)(Bm + (size_t)(k0 + brow + 8) * Ndim + n0 + bcol);

        __syncthreads();
        As[acol + 0][arow] = a0.x; As[acol + 1][arow] = a0.y;
        As[acol + 2][arow] = a0.z; As[acol + 3][arow] = a0.w;
        As[acol + 0][arow + 64] = a1.x; As[acol + 1][arow + 64] = a1.y;
        As[acol + 2][arow + 64] = a1.z; As[acol + 3][arow + 64] = a1.w;
        *(float4*)&Bs[brow][bcol]     = b0;
        *(float4*)&Bs[brow + 8][bcol] = b1;
        __syncthreads();

        #pragma unroll
        for (int kk = 0; kk < GBK; kk++) {
            float4 av0 = *(const float4*)&As[kk][ty * 8];
            float4 av1 = *(const float4*)&As[kk][ty * 8 + 4];
            float4 bv0 = *(const float4*)&Bs[kk][tx * 8];
            float4 bv1 = *(const float4*)&Bs[kk][tx * 8 + 4];
            float a[8] = {av0.x, av0.y, av0.z, av0.w, av1.x, av1.y, av1.z, av1.w};
            float b[8] = {bv0.x, bv0.y, bv0.z, bv0.w, bv1.x, bv1.y, bv1.z, bv1.w};
            #pragma unroll
            for (int i = 0; i < 8; i++)
                #pragma unroll
                for (int j = 0; j < 8; j++)
                    acc[i][j] += a[i] * b[j];
        }
    }

    // epilogue
    #pragma unroll
    for (int i = 0; i < 8; i++) {
        const int row = m0 + ty * 8 + i;
        #pragma unroll
        for (int j = 0; j < 8; j++) {
            const int col = n0 + tx * 8 + j;
            float val = acc[i][j];
            if (bias)    val += bias[col];
            if (do_gelu) val = gelu_f(val);
            if (resid)   val += resid[(size_t)row * Ndim + col];
            C[(size_t)row * Ndim + col] = val;
        }
    }
}

// ---------------------------------------------------------------------------
// Causal flash attention. q,k,v,out are [M, D] laid out as (b, t, h, hd).
// Tile: 64 queries x 64 keys, HD = 64. One block per (qtile, b*H).
// Online softmax with running max/denominator.
// ---------------------------------------------------------------------------
#define ATILE 64
#define APD 65   // padded row stride (floats)

__global__ __launch_bounds__(256) void attn_kernel(
    const float* __restrict__ q, const float* __restrict__ k,
    const float* __restrict__ v, float* __restrict__ out)
{
    extern __shared__ float sm[];
    float* Qs  = sm;                       // 64*65
    float* Ks  = Qs + ATILE * APD;
    float* Vs  = Ks + ATILE * APD;
    float* Ss  = Vs + ATILE * APD;
    float* m_s = Ss + ATILE * APD;         // 64
    float* l_s = m_s + ATILE;              // 64
    float* al_s = l_s + ATILE;             // 64

    const int tid = threadIdx.x;
    const int tx = tid & 15;
    const int ty = tid >> 4;
    const int bh = blockIdx.y;
    const int b  = bh / HH;
    const int h  = bh % HH;
    const int qt = blockIdx.x;
    const int q0 = qt * ATILE;

    const size_t base = ((size_t)b * TT) * DD + (size_t)h * HD;

    // load Q tile (64x64)
    #pragma unroll
    for (int i = 0; i < 16; i++) {
        int idx = tid + i * 256;
        int r = idx >> 6, c = idx & 63;
        Qs[r * APD + c] = q[base + (size_t)(q0 + r) * DD + c];
    }
    if (tid < ATILE) { m_s[tid] = -1e30f; l_s[tid] = 0.f; }

    float acc[4][4];
    #pragma unroll
    for (int i = 0; i < 4; i++)
        #pragma unroll
        for (int j = 0; j < 4; j++) acc[i][j] = 0.f;

    __syncthreads();

    for (int kt = 0; kt <= qt; kt++) {
        const int k0 = kt * ATILE;
        // load K and V tiles
        #pragma unroll
        for (int i = 0; i < 16; i++) {
            int idx = tid + i * 256;
            int r = idx >> 6, c = idx & 63;
            Ks[r * APD + c] = k[base + (size_t)(k0 + r) * DD + c];
            Vs[r * APD + c] = v[base + (size_t)(k0 + r) * DD + c];
        }
        __syncthreads();

        // S = Q @ K^T  (each thread 4x4)
        float s[4][4];
        #pragma unroll
        for (int i = 0; i < 4; i++)
            #pragma unroll
            for (int j = 0; j < 4; j++) s[i][j] = 0.f;
        #pragma unroll 8
        for (int d = 0; d < ATILE; d++) {
            float aq[4], bk[4];
            #pragma unroll
            for (int i = 0; i < 4; i++) aq[i] = Qs[(ty * 4 + i) * APD + d];
            #pragma unroll
            for (int j = 0; j < 4; j++) bk[j] = Ks[(tx * 4 + j) * APD + d];
            #pragma unroll
            for (int i = 0; i < 4; i++)
                #pragma unroll
                for (int j = 0; j < 4; j++)
                    s[i][j] += aq[i] * bk[j];
        }

        // scale + causal mask, write S to smem
        const float scale = 0.125f;  // 1/sqrt(64)
        const bool diag = (kt == qt);
        #pragma unroll
        for (int i = 0; i < 4; i++) {
            const int r = ty * 4 + i;
            #pragma unroll
            for (int j = 0; j < 4; j++) {
                const int c = tx * 4 + j;
                float val = s[i][j] * scale;
                if (diag && c > r) val = -1e30f;
                Ss[r * APD + c] = val;
            }
        }
        __syncthreads();

        // online softmax row pass (64 threads, one row each)
        if (tid < ATILE) {
            const int r = tid;
            float mp = m_s[r];
            float mm = mp;
            #pragma unroll 8
            for (int c = 0; c < ATILE; c++) mm = fmaxf(mm, Ss[r * APD + c]);
            float al = __expf(mp - mm);
            float sum = 0.f;
            #pragma unroll 8
            for (int c = 0; c < ATILE; c++) {
                float p = __expf(Ss[r * APD + c] - mm);
                Ss[r * APD + c] = p;
                sum += p;
            }
            l_s[r] = l_s[r] * al + sum;
            m_s[r] = mm;
            al_s[r] = al;
        }
        __syncthreads();

        // rescale accumulator, then O += P @ V
        #pragma unroll
        for (int i = 0; i < 4; i++) {
            float al = al_s[ty * 4 + i];
            #pragma unroll
            for (int j = 0; j < 4; j++) acc[i][j] *= al;
        }
        #pragma unroll 8
        for (int d = 0; d < ATILE; d++) {
            float p[4], vv[4];
            #pragma unroll
            for (int i = 0; i < 4; i++) p[i] = Ss[(ty * 4 + i) * APD + d];
            #pragma unroll
            for (int j = 0; j < 4; j++) vv[j] = Vs[d * APD + tx * 4 + j];
            #pragma unroll
            for (int i = 0; i < 4; i++)
                #pragma unroll
                for (int j = 0; j < 4; j++)
                    acc[i][j] += p[i] * vv[j];
        }
        __syncthreads();
    }

    // write normalized output
    #pragma unroll
    for (int i = 0; i < 4; i++) {
        const int r = ty * 4 + i;
        const float invl = 1.0f / l_s[r];
        #pragma unroll
        for (int j = 0; j < 4; j++) {
            const int c = tx * 4 + j;
            out[base + (size_t)(q0 + r) * DD + c] = acc[i][j] * invl;
        }
    }
}

// ---------------------------------------------------------------------------
// Host launch
// ---------------------------------------------------------------------------
extern "C" void kernel_launch(void* const* d_in, const int* in_sizes, int n_in,
                              void* d_out, int out_size)
{
    const float* x    = (const float*)d_in[0];
    const float* Wq   = (const float*)d_in[1];
    const float* Wk   = (const float*)d_in[2];
    const float* Wv   = (const float*)d_in[3];
    const float* Wo   = (const float*)d_in[4];
    const float* bo   = (const float*)d_in[5];
    const float* W1   = (const float*)d_in[6];
    const float* b1   = (const float*)d_in[7];
    const float* W2   = (const float*)d_in[8];
    const float* b2   = (const float*)d_in[9];
    const float* g1   = (const float*)d_in[10];
    const float* be1  = (const float*)d_in[11];
    const float* g2   = (const float*)d_in[12];
    const float* be2  = (const float*)d_in[13];
    float* out = (float*)d_out;

    float *h, *q, *k, *v, *attn, *x2, *h2, *ff1;
    cudaGetSymbolAddress((void**)&h,    g_h);
    cudaGetSymbolAddress((void**)&q,    g_q);
    cudaGetSymbolAddress((void**)&k,    g_k);
    cudaGetSymbolAddress((void**)&v,    g_v);
    cudaGetSymbolAddress((void**)&attn, g_attn);
    cudaGetSymbolAddress((void**)&x2,   g_x2);
    cudaGetSymbolAddress((void**)&h2,   g_h2);
    cudaGetSymbolAddress((void**)&ff1,  g_ff1);

    const int ATTN_SMEM = (4 * ATILE * APD + 3 * ATILE) * (int)sizeof(float);
    cudaFuncSetAttribute(attn_kernel,
                         cudaFuncAttributeMaxDynamicSharedMemorySize, ATTN_SMEM);

    // 1) LN1
    layernorm_kernel<<<MM, 256>>>(x, g1, be1, h);

    // 2) QKV projections
    dim3 gDD(DD / GBN, MM / GBM);
    gemm_kernel<<<gDD, 256>>>(h, Wq, nullptr, nullptr, q, MM, DD, DD, 0);
    gemm_kernel<<<gDD, 256>>>(h, Wk, nullptr, nullptr, k, MM, DD, DD, 0);
    gemm_kernel<<<gDD, 256>>>(h, Wv, nullptr, nullptr, v, MM, DD, DD, 0);

    // 3) causal attention
    attn_kernel<<<dim3(TT / ATILE, BB * HH), 256, ATTN_SMEM>>>(q, k, v, attn);

    // 4) output projection + bias + residual(x)
    gemm_kernel<<<gDD, 256>>>(attn, Wo, bo, x, x2, MM, DD, DD, 0);

    // 5) LN2
    layernorm_kernel<<<MM, 256>>>(x2, g2, be2, h2);

    // 6) FFN1 + bias + GELU
    dim3 gFF(FF / GBN, MM / GBM);
    gemm_kernel<<<gFF, 256>>>(h2, W1, b1, nullptr, ff1, MM, FF, DD, 1);

    // 7) FFN2 + bias + residual(x2) -> out
    gemm_kernel<<<gDD, 256>>>(ff1, W2, b2, x2, out, MM, DD, FF, 0);
}

// round 3
// speedup vs baseline: 2.0473x; 2.0473x over previous
#include <cuda_runtime.h>
#include <cuda_bf16.h>
#include <math.h>
#include <stdint.h>

// ---------------------------------------------------------------------------
// Problem constants
// ---------------------------------------------------------------------------
#define BB 4
#define TT 2048
#define DD 1024
#define HH 16
#define HD 64
#define FF 4096
#define MM (BB * TT)       // 8192 rows
#define EPS 1e-5f

// ---------------------------------------------------------------------------
// Scratch (allocation-free: __device__ globals)
// ---------------------------------------------------------------------------
__device__ float g_h   [(size_t)MM * DD];
__device__ float g_q   [(size_t)MM * DD];
__device__ float g_k   [(size_t)MM * DD];
__device__ float g_v   [(size_t)MM * DD];
__device__ float g_attn[(size_t)MM * DD];
__device__ float g_x2  [(size_t)MM * DD];
__device__ float g_h2  [(size_t)MM * DD];
__device__ float g_ff1 [(size_t)MM * FF];

// ---------------------------------------------------------------------------
// LayerNorm: one block (256 threads) per row of 1024
// ---------------------------------------------------------------------------
__global__ __launch_bounds__(256) void layernorm_kernel(
    const float* __restrict__ x, const float* __restrict__ gamma,
    const float* __restrict__ beta, float* __restrict__ out)
{
    __shared__ float shs[8], shss[8];
    __shared__ float s_mean, s_inv;
    const int row = blockIdx.x;
    const int tid = threadIdx.x;

    const float4 xv = *(const float4*)(x + (size_t)row * DD + tid * 4);
    float s  = xv.x + xv.y + xv.z + xv.w;
    float ss = xv.x * xv.x + xv.y * xv.y + xv.z * xv.z + xv.w * xv.w;
    #pragma unroll
    for (int o = 16; o > 0; o >>= 1) {
        s  += __shfl_down_sync(0xffffffffu, s, o);
        ss += __shfl_down_sync(0xffffffffu, ss, o);
    }
    if ((tid & 31) == 0) { shs[tid >> 5] = s; shss[tid >> 5] = ss; }
    __syncthreads();
    if (tid == 0) {
        float S = 0.f, SS = 0.f;
        #pragma unroll
        for (int i = 0; i < 8; i++) { S += shs[i]; SS += shss[i]; }
        float mean = S * (1.0f / DD);
        float var  = SS * (1.0f / DD) - mean * mean;
        s_mean = mean;
        s_inv  = rsqrtf(var + EPS);
    }
    __syncthreads();
    const float mean = s_mean, inv = s_inv;
    const float4 gv = *(const float4*)(gamma + tid * 4);
    const float4 bv = *(const float4*)(beta  + tid * 4);
    float4 o;
    o.x = gv.x * (xv.x - mean) * inv + bv.x;
    o.y = gv.y * (xv.y - mean) * inv + bv.y;
    o.z = gv.z * (xv.z - mean) * inv + bv.z;
    o.w = gv.w * (xv.w - mean) * inv + bv.w;
    *(float4*)(out + (size_t)row * DD + tid * 4) = o;
}

// ---------------------------------------------------------------------------
// GELU (tanh approximation, matches reference)
// ---------------------------------------------------------------------------
__device__ __forceinline__ float gelu_f(float x)
{
    const float c = 0.7978845608028654f;  // sqrt(2/pi)
    float inner = c * (x + 0.044715f * x * x * x);
    return 0.5f * x * (1.0f + tanhf(inner));
}

// ---------------------------------------------------------------------------
// tf32 helpers
// ---------------------------------------------------------------------------
__device__ __forceinline__ uint32_t tf32_cvt(float f) {
    uint32_t r;
    asm("cvt.rna.tf32.f32 %0, %1;" : "=r"(r) : "f"(f));
    return r;
}
__device__ __forceinline__ void mma_tf32(float c[4], const uint32_t a[4],
                                         const uint32_t b[2]) {
    asm volatile(
        "mma.sync.aligned.m16n8k8.row.col.f32.tf32.tf32.f32 "
        "{%0,%1,%2,%3}, {%4,%5,%6,%7}, {%8,%9}, {%0,%1,%2,%3};"
        : "+f"(c[0]), "+f"(c[1]), "+f"(c[2]), "+f"(c[3])
        : "r"(a[0]), "r"(a[1]), "r"(a[2]), "r"(a[3]), "r"(b[0]), "r"(b[1]));
}

// ---------------------------------------------------------------------------
// tf32 tensor-core GEMM:  C[M,N] = A[M,K] @ B[K,N]  (+bias)(+gelu)(+residual)
// 128x128x32 tile, 256 threads, 8 warps (2x4), m16n8k8 mma, double buffered.
// A smem stride 36 floats, B smem stride 136 floats (conflict-free).
// M,N % 128 == 0, K % 32 == 0. fp32 accumulation, tf32 (rna) inputs.
// ---------------------------------------------------------------------------
#define ASTR 36
#define BSTR 136
#define ASZ (128 * ASTR)          // 4608 floats
#define BSZ (32 * BSTR)           // 4352 floats
#define BUFSZ (ASZ + BSZ)         // 8960 floats
#define GEMM_SMEM (2 * BUFSZ * 4) // 71680 bytes

__global__ __launch_bounds__(256) void gemm_mma(
    const float* __restrict__ A, const float* __restrict__ B,
    const float* __restrict__ bias,   // may be null
    const float* __restrict__ resid,  // may be null
    float* __restrict__ C,
    int Mdim, int Ndim, int Kdim, int do_gelu)
{
    extern __shared__ __align__(16) float smg[];
    const int tid  = threadIdx.x;
    const int lane = tid & 31;
    const int warp = tid >> 5;
    const int wm   = warp >> 2;     // 0..1
    const int wn   = warp & 3;      // 0..3
    const int gid  = lane >> 2;     // 0..7
    const int tg   = lane & 3;      // 0..3
    const int m0 = blockIdx.y * 128;
    const int n0 = blockIdx.x * 128;

    // loader mapping
    const int lrA = tid >> 3;            // 0..31
    const int lcA = (tid & 7) * 4;       // 0..28
    const int lrB = tid >> 5;            // 0..7
    const int lcB = (tid & 31) * 4;      // 0..124

    float acc[4][4][4];
    #pragma unroll
    for (int mt = 0; mt < 4; mt++)
        #pragma unroll
        for (int nt = 0; nt < 4; nt++)
            #pragma unroll
            for (int r = 0; r < 4; r++) acc[mt][nt][r] = 0.f;

    const int nkb = Kdim / 32;

    auto load_g = [&](int kb, float4* av, float4* bv) {
        const float* Ap = A + (size_t)(m0 + lrA) * Kdim + kb * 32 + lcA;
        #pragma unroll
        for (int p = 0; p < 4; p++)
            av[p] = *(const float4*)(Ap + (size_t)p * 32 * Kdim);
        const float* Bp = B + (size_t)(kb * 32 + lrB) * Ndim + n0 + lcB;
        #pragma unroll
        for (int p = 0; p < 4; p++)
            bv[p] = *(const float4*)(Bp + (size_t)p * 8 * Ndim);
    };
    auto sts_buf = [&](int buf, const float4* av, const float4* bv) {
        uint32_t* As = (uint32_t*)(smg + buf * BUFSZ);
        uint32_t* Bs = As + ASZ;
        #pragma unroll
        for (int p = 0; p < 4; p++) {
            uint4 t;
            t.x = tf32_cvt(av[p].x); t.y = tf32_cvt(av[p].y);
            t.z = tf32_cvt(av[p].z); t.w = tf32_cvt(av[p].w);
            *(uint4*)&As[(lrA + 32 * p) * ASTR + lcA] = t;
        }
        #pragma unroll
        for (int p = 0; p < 4; p++) {
            uint4 t;
            t.x = tf32_cvt(bv[p].x); t.y = tf32_cvt(bv[p].y);
            t.z = tf32_cvt(bv[p].z); t.w = tf32_cvt(bv[p].w);
            *(uint4*)&Bs[(lrB + 8 * p) * BSTR + lcB] = t;
        }
    };
    auto compute = [&](int buf) {
        const uint32_t* As = (const uint32_t*)(smg + buf * BUFSZ);
        const uint32_t* Bs = As + ASZ;
        #pragma unroll
        for (int kk = 0; kk < 4; kk++) {
            uint32_t af[4][4], bf[4][2];
            #pragma unroll
            for (int mt = 0; mt < 4; mt++) {
                const uint32_t* ap =
                    As + (wm * 64 + mt * 16 + gid) * ASTR + kk * 8 + tg;
                af[mt][0] = ap[0];
                af[mt][1] = ap[8 * ASTR];
                af[mt][2] = ap[4];
                af[mt][3] = ap[8 * ASTR + 4];
            }
            #pragma unroll
            for (int nt = 0; nt < 4; nt++) {
                const uint32_t* bp =
                    Bs + (kk * 8 + tg) * BSTR + wn * 32 + nt * 8 + gid;
                bf[nt][0] = bp[0];
                bf[nt][1] = bp[4 * BSTR];
            }
            #pragma unroll
            for (int mt = 0; mt < 4; mt++)
                #pragma unroll
                for (int nt = 0; nt < 4; nt++)
                    mma_tf32(acc[mt][nt], af[mt], bf[nt]);
        }
    };

    // prologue
    float4 av[4], bv[4];
    load_g(0, av, bv);
    sts_buf(0, av, bv);
    __syncthreads();

    for (int kb = 0; kb < nkb; kb++) {
        const int cur = kb & 1;
        if (kb + 1 < nkb) load_g(kb + 1, av, bv);
        compute(cur);
        __syncthreads();
        if (kb + 1 < nkb) {
            sts_buf(cur ^ 1, av, bv);
            __syncthreads();
        }
    }

    // epilogue
    #pragma unroll
    for (int mt = 0; mt < 4; mt++) {
        #pragma unroll
        for (int half = 0; half < 2; half++) {
            const int row = m0 + wm * 64 + mt * 16 + gid + half * 8;
            float* Cr = C + (size_t)row * Ndim;
            const float* Rr = resid ? resid + (size_t)row * Ndim : nullptr;
            #pragma unroll
            for (int nt = 0; nt < 4; nt++) {
                const int col = n0 + wn * 32 + nt * 8 + 2 * tg;
                float v0 = acc[mt][nt][half * 2 + 0];
                float v1 = acc[mt][nt][half * 2 + 1];
                if (bias)    { v0 += bias[col]; v1 += bias[col + 1]; }
                if (do_gelu) { v0 = gelu_f(v0); v1 = gelu_f(v1); }
                if (Rr)      { v0 += Rr[col]; v1 += Rr[col + 1]; }
                float2 o; o.x = v0; o.y = v1;
                *(float2*)(Cr + col) = o;
            }
        }
    }
}

// ---------------------------------------------------------------------------
// Causal flash attention (fp32 SIMT). q,k,v,out are [M, D] laid out (b,t,h,hd).
// ---------------------------------------------------------------------------
#define ATILE 64
#define APD 65

__global__ __launch_bounds__(256) void attn_kernel(
    const float* __restrict__ q, const float* __restrict__ k,
    const float* __restrict__ v, float* __restrict__ out)
{
    extern __shared__ float sm[];
    float* Qs  = sm;
    float* Ks  = Qs + ATILE * APD;
    float* Vs  = Ks + ATILE * APD;
    float* Ss  = Vs + ATILE * APD;
    float* m_s = Ss + ATILE * APD;
    float* l_s = m_s + ATILE;
    float* al_s = l_s + ATILE;

    const int tid = threadIdx.x;
    const int tx = tid & 15;
    const int ty = tid >> 4;
    const int bh = blockIdx.y;
    const int b  = bh / HH;
    const int h  = bh % HH;
    const int qt = blockIdx.x;
    const int q0 = qt * ATILE;

    const size_t base = ((size_t)b * TT) * DD + (size_t)h * HD;

    #pragma unroll
    for (int i = 0; i < 16; i++) {
        int idx = tid + i * 256;
        int r = idx >> 6, c = idx & 63;
        Qs[r * APD + c] = q[base + (size_t)(q0 + r) * DD + c];
    }
    if (tid < ATILE) { m_s[tid] = -1e30f; l_s[tid] = 0.f; }

    float acc[4][4];
    #pragma unroll
    for (int i = 0; i < 4; i++)
        #pragma unroll
        for (int j = 0; j < 4; j++) acc[i][j] = 0.f;

    __syncthreads();

    for (int kt = 0; kt <= qt; kt++) {
        const int k0 = kt * ATILE;
        #pragma unroll
        for (int i = 0; i < 16; i++) {
            int idx = tid + i * 256;
            int r = idx >> 6, c = idx & 63;
            Ks[r * APD + c] = k[base + (size_t)(k0 + r) * DD + c];
            Vs[r * APD + c] = v[base + (size_t)(k0 + r) * DD + c];
        }
        __syncthreads();

        float s[4][4];
        #pragma unroll
        for (int i = 0; i < 4; i++)
            #pragma unroll
            for (int j = 0; j < 4; j++) s[i][j] = 0.f;
        #pragma unroll 8
        for (int d = 0; d < ATILE; d++) {
            float aq[4], bk[4];
            #pragma unroll
            for (int i = 0; i < 4; i++) aq[i] = Qs[(ty * 4 + i) * APD + d];
            #pragma unroll
            for (int j = 0; j < 4; j++) bk[j] = Ks[(tx * 4 + j) * APD + d];
            #pragma unroll
            for (int i = 0; i < 4; i++)
                #pragma unroll
                for (int j = 0; j < 4; j++)
                    s[i][j] += aq[i] * bk[j];
        }

        const float scale = 0.125f;
        const bool diag = (kt == qt);
        #pragma unroll
        for (int i = 0; i < 4; i++) {
            const int r = ty * 4 + i;
            #pragma unroll
            for (int j = 0; j < 4; j++) {
                const int c = tx * 4 + j;
                float val = s[i][j] * scale;
                if (diag && c > r) val = -1e30f;
                Ss[r * APD + c] = val;
            }
        }
        __syncthreads();

        if (tid < ATILE) {
            const int r = tid;
            float mp = m_s[r];
            float mm = mp;
            #pragma unroll 8
            for (int c = 0; c < ATILE; c++) mm = fmaxf(mm, Ss[r * APD + c]);
            float al = __expf(mp - mm);
            float sum = 0.f;
            #pragma unroll 8
            for (int c = 0; c < ATILE; c++) {
                float p = __expf(Ss[r * APD + c] - mm);
                Ss[r * APD + c] = p;
                sum += p;
            }
            l_s[r] = l_s[r] * al + sum;
            m_s[r] = mm;
            al_s[r] = al;
        }
        __syncthreads();

        #pragma unroll
        for (int i = 0; i < 4; i++) {
            float al = al_s[ty * 4 + i];
            #pragma unroll
            for (int j = 0; j < 4; j++) acc[i][j] *= al;
        }
        #pragma unroll 8
        for (int d = 0; d < ATILE; d++) {
            float p[4], vv[4];
            #pragma unroll
            for (int i = 0; i < 4; i++) p[i] = Ss[(ty * 4 + i) * APD + d];
            #pragma unroll
            for (int j = 0; j < 4; j++) vv[j] = Vs[d * APD + tx * 4 + j];
            #pragma unroll
            for (int i = 0; i < 4; i++)
                #pragma unroll
                for (int j = 0; j < 4; j++)
                    acc[i][j] += p[i] * vv[j];
        }
        __syncthreads();
    }

    #pragma unroll
    for (int i = 0; i < 4; i++) {
        const int r = ty * 4 + i;
        const float invl = 1.0f / l_s[r];
        #pragma unroll
        for (int j = 0; j < 4; j++) {
            const int c = tx * 4 + j;
            out[base + (size_t)(q0 + r) * DD + c] = acc[i][j] * invl;
        }
    }
}

// ---------------------------------------------------------------------------
// Host launch
// ---------------------------------------------------------------------------
extern "C" void kernel_launch(void* const* d_in, const int* in_sizes, int n_in,
                              void* d_out, int out_size)
{
    const float* x    = (const float*)d_in[0];
    const float* Wq   = (const float*)d_in[1];
    const float* Wk   = (const float*)d_in[2];
    const float* Wv   = (const float*)d_in[3];
    const float* Wo   = (const float*)d_in[4];
    const float* bo   = (const float*)d_in[5];
    const float* W1   = (const float*)d_in[6];
    const float* b1   = (const float*)d_in[7];
    const float* W2   = (const float*)d_in[8];
    const float* b2   = (const float*)d_in[9];
    const float* g1   = (const float*)d_in[10];
    const float* be1  = (const float*)d_in[11];
    const float* g2   = (const float*)d_in[12];
    const float* be2  = (const float*)d_in[13];
    float* out = (float*)d_out;

    float *h, *q, *k, *v, *attn, *x2, *h2, *ff1;
    cudaGetSymbolAddress((void**)&h,    g_h);
    cudaGetSymbolAddress((void**)&q,    g_q);
    cudaGetSymbolAddress((void**)&k,    g_k);
    cudaGetSymbolAddress((void**)&v,    g_v);
    cudaGetSymbolAddress((void**)&attn, g_attn);
    cudaGetSymbolAddress((void**)&x2,   g_x2);
    cudaGetSymbolAddress((void**)&h2,   g_h2);
    cudaGetSymbolAddress((void**)&ff1,  g_ff1);

    const int ATTN_SMEM = (4 * ATILE * APD + 3 * ATILE) * (int)sizeof(float);
    cudaFuncSetAttribute(attn_kernel,
                         cudaFuncAttributeMaxDynamicSharedMemorySize, ATTN_SMEM);
    cudaFuncSetAttribute(gemm_mma,
                         cudaFuncAttributeMaxDynamicSharedMemorySize, GEMM_SMEM);

    // 1) LN1
    layernorm_kernel<<<MM, 256>>>(x, g1, be1, h);

    // 2) QKV projections (tf32 tensor cores)
    dim3 gDD(DD / 128, MM / 128);
    gemm_mma<<<gDD, 256, GEMM_SMEM>>>(h, Wq, nullptr, nullptr, q, MM, DD, DD, 0);
    gemm_mma<<<gDD, 256, GEMM_SMEM>>>(h, Wk, nullptr, nullptr, k, MM, DD, DD, 0);
    gemm_mma<<<gDD, 256, GEMM_SMEM>>>(h, Wv, nullptr, nullptr, v, MM, DD, DD, 0);

    // 3) causal attention
    attn_kernel<<<dim3(TT / ATILE, BB * HH), 256, ATTN_SMEM>>>(q, k, v, attn);

    // 4) output projection + bias + residual(x)
    gemm_mma<<<gDD, 256, GEMM_SMEM>>>(attn, Wo, bo, x, x2, MM, DD, DD, 0);

    // 5) LN2
    layernorm_kernel<<<MM, 256>>>(x2, g2, be2, h2);

    // 6) FFN1 + bias + GELU
    dim3 gFF(FF / 128, MM / 128);
    gemm_mma<<<gFF, 256, GEMM_SMEM>>>(h2, W1, b1, nullptr, ff1, MM, FF, DD, 1);

    // 7) FFN2 + bias + residual(x2) -> out
    gemm_mma<<<gDD, 256, GEMM_SMEM>>>(ff1, W2, b2, x2, out, MM, DD, FF, 0);
}

// round 4
// speedup vs baseline: 2.2953x; 1.1211x over previous
#include <cuda_runtime.h>
#include <cuda_bf16.h>
#include <math.h>
#include <stdint.h>

// ---------------------------------------------------------------------------
// Problem constants
// ---------------------------------------------------------------------------
#define BB 4
#define TT 2048
#define DD 1024
#define HH 16
#define HD 64
#define FF 4096
#define MM (BB * TT)       // 8192 rows
#define EPS 1e-5f

// ---------------------------------------------------------------------------
// Scratch (allocation-free: __device__ globals)
// ---------------------------------------------------------------------------
__device__ float g_h   [(size_t)MM * DD];
__device__ float g_qkv [(size_t)MM * 3 * DD];
__device__ float g_attn[(size_t)MM * DD];
__device__ float g_x2  [(size_t)MM * DD];
__device__ float g_h2  [(size_t)MM * DD];
__device__ float g_ff1 [(size_t)MM * FF];
// tf32-rounded weights
__device__ float g_wqkv[(size_t)DD * 3 * DD];
__device__ float g_wo  [(size_t)DD * DD];
__device__ float g_w1  [(size_t)DD * FF];
__device__ float g_w2  [(size_t)FF * DD];

// ---------------------------------------------------------------------------
// tf32 helpers
// ---------------------------------------------------------------------------
__device__ __forceinline__ uint32_t tf32_cvt(float f) {
    uint32_t r;
    asm("cvt.rna.tf32.f32 %0, %1;" : "=r"(r) : "f"(f));
    return r;
}
__device__ __forceinline__ float tf32_round(float f) {
    return __uint_as_float(tf32_cvt(f));
}
__device__ __forceinline__ void mma_tf32(float c[4], const uint32_t a[4],
                                         const uint32_t b[2]) {
    asm volatile(
        "mma.sync.aligned.m16n8k8.row.col.f32.tf32.tf32.f32 "
        "{%0,%1,%2,%3}, {%4,%5,%6,%7}, {%8,%9}, {%0,%1,%2,%3};"
        : "+f"(c[0]), "+f"(c[1]), "+f"(c[2]), "+f"(c[3])
        : "r"(a[0]), "r"(a[1]), "r"(a[2]), "r"(a[3]), "r"(b[0]), "r"(b[1]));
}
__device__ __forceinline__ uint32_t smem_u32(const void* p) {
    uint32_t a;
    asm("{ .reg .u64 t; cvta.to.shared.u64 t, %1; cvt.u32.u64 %0, t; }"
        : "=r"(a) : "l"(p));
    return a;
}
__device__ __forceinline__ void cp_async16(uint32_t saddr, const void* gptr) {
    asm volatile("cp.async.cg.shared.global [%0], [%1], 16;"
                 :: "r"(saddr), "l"(gptr) : "memory");
}
__device__ __forceinline__ void cp_commit() {
    asm volatile("cp.async.commit_group;" ::: "memory");
}
template <int N>
__device__ __forceinline__ void cp_wait() {
    asm volatile("cp.async.wait_group %0;" :: "n"(N) : "memory");
}

// ---------------------------------------------------------------------------
// Weight preprocessing: tf32-round (and pack QKV)
// ---------------------------------------------------------------------------
__global__ __launch_bounds__(256) void cvt_tf32_kernel(
    const float* __restrict__ in, float* __restrict__ out)
{
    const size_t i = ((size_t)blockIdx.x * 256 + threadIdx.x) * 4;
    float4 v = *(const float4*)(in + i);
    v.x = tf32_round(v.x); v.y = tf32_round(v.y);
    v.z = tf32_round(v.z); v.w = tf32_round(v.w);
    *(float4*)(out + i) = v;
}

__global__ __launch_bounds__(256) void pack_qkv_kernel(
    const float* __restrict__ Wq, const float* __restrict__ Wk,
    const float* __restrict__ Wv, float* __restrict__ out)
{
    const int sel = blockIdx.y;
    const float* src = sel == 0 ? Wq : (sel == 1 ? Wk : Wv);
    const size_t i = ((size_t)blockIdx.x * 256 + threadIdx.x) * 4;
    const int r = (int)(i >> 10);          // /1024
    const int c = (int)(i & 1023);
    float4 v = *(const float4*)(src + i);
    v.x = tf32_round(v.x); v.y = tf32_round(v.y);
    v.z = tf32_round(v.z); v.w = tf32_round(v.w);
    *(float4*)(out + (size_t)r * (3 * DD) + sel * DD + c) = v;
}

// ---------------------------------------------------------------------------
// LayerNorm: one block (256 threads) per row of 1024; tf32-rounds the output
// (it always feeds a GEMM A operand).
// ---------------------------------------------------------------------------
__global__ __launch_bounds__(256) void layernorm_kernel(
    const float* __restrict__ x, const float* __restrict__ gamma,
    const float* __restrict__ beta, float* __restrict__ out)
{
    __shared__ float shs[8], shss[8];
    __shared__ float s_mean, s_inv;
    const int row = blockIdx.x;
    const int tid = threadIdx.x;

    const float4 xv = *(const float4*)(x + (size_t)row * DD + tid * 4);
    float s  = xv.x + xv.y + xv.z + xv.w;
    float ss = xv.x * xv.x + xv.y * xv.y + xv.z * xv.z + xv.w * xv.w;
    #pragma unroll
    for (int o = 16; o > 0; o >>= 1) {
        s  += __shfl_down_sync(0xffffffffu, s, o);
        ss += __shfl_down_sync(0xffffffffu, ss, o);
    }
    if ((tid & 31) == 0) { shs[tid >> 5] = s; shss[tid >> 5] = ss; }
    __syncthreads();
    if (tid == 0) {
        float S = 0.f, SS = 0.f;
        #pragma unroll
        for (int i = 0; i < 8; i++) { S += shs[i]; SS += shss[i]; }
        float mean = S * (1.0f / DD);
        float var  = SS * (1.0f / DD) - mean * mean;
        s_mean = mean;
        s_inv  = rsqrtf(var + EPS);
    }
    __syncthreads();
    const float mean = s_mean, inv = s_inv;
    const float4 gv = *(const float4*)(gamma + tid * 4);
    const float4 bv = *(const float4*)(beta  + tid * 4);
    float4 o;
    o.x = tf32_round(gv.x * (xv.x - mean) * inv + bv.x);
    o.y = tf32_round(gv.y * (xv.y - mean) * inv + bv.y);
    o.z = tf32_round(gv.z * (xv.z - mean) * inv + bv.z);
    o.w = tf32_round(gv.w * (xv.w - mean) * inv + bv.w);
    *(float4*)(out + (size_t)row * DD + tid * 4) = o;
}

// ---------------------------------------------------------------------------
// GELU (tanh approximation, matches reference)
// ---------------------------------------------------------------------------
__device__ __forceinline__ float gelu_f(float x)
{
    const float c = 0.7978845608028654f;  // sqrt(2/pi)
    float inner = c * (x + 0.044715f * x * x * x);
    return 0.5f * x * (1.0f + tanhf(inner));
}

// ---------------------------------------------------------------------------
// tf32 tensor-core GEMM:  C[M,N] = A[M,K] @ B[K,N]  (+bias)(+gelu)(+residual)
// Inputs pre-rounded to tf32. 128x128x32 tile, 256 threads, 8 warps (2x4),
// m16n8k8 mma, cp.async 4-stage pipeline.
// mode: 0 = plain, 1 = gelu + tf32-round output (FFN1), 2 = plain
// A smem stride 36 floats, B smem stride 136 floats (conflict-free LDS).
// ---------------------------------------------------------------------------
#define ASTR 36
#define BSTR 136
#define ASZ (128 * ASTR)          // 4608 floats
#define BSZ (32 * BSTR)           // 4352 floats
#define BUFSZ (ASZ + BSZ)         // 8960 floats
#define NS 4
#define STAGE_BYTES (BUFSZ * 4)   // 35840 bytes
#define GEMM_SMEM (NS * STAGE_BYTES)  // 143360 bytes

__global__ __launch_bounds__(256) void gemm_mma(
    const float* __restrict__ A, const float* __restrict__ B,
    const float* __restrict__ bias,   // may be null
    const float* __restrict__ resid,  // may be null
    float* __restrict__ C,
    int Ndim, int Kdim, int mode)
{
    extern __shared__ __align__(16) float smg[];
    const uint32_t sbase = smem_u32(smg);
    const int tid  = threadIdx.x;
    const int lane = tid & 31;
    const int warp = tid >> 5;
    const int wm   = warp >> 2;     // 0..1
    const int wn   = warp & 3;      // 0..3
    const int gid  = lane >> 2;     // 0..7
    const int tg   = lane & 3;      // 0..3
    const int m0 = blockIdx.y * 128;
    const int n0 = blockIdx.x * 128;

    // loader mapping
    const int rA = tid >> 3;             // 0..31
    const int cA = (tid & 7) * 4;        // 0..28
    const int rB = tid >> 5;             // 0..7
    const int cB = (tid & 31) * 4;       // 0..124

    const uint32_t sAoff = (uint32_t)(rA * ASTR + cA) * 4;
    const uint32_t sBoff = (uint32_t)(ASZ + rB * BSTR + cB) * 4;

    float acc[4][4][4];
    #pragma unroll
    for (int mt = 0; mt < 4; mt++)
        #pragma unroll
        for (int nt = 0; nt < 4; nt++)
            #pragma unroll
            for (int r = 0; r < 4; r++) acc[mt][nt][r] = 0.f;

    const int nkb = Kdim / 32;

    auto issue = [&](int kb, int slot) {
        const uint32_t sb = sbase + slot * STAGE_BYTES;
        const float* Ag = A + (size_t)(m0 + rA) * Kdim + kb * 32 + cA;
        #pragma unroll
        for (int p = 0; p < 4; p++)
            cp_async16(sb + sAoff + p * (32 * ASTR * 4), Ag + (size_t)p * 32 * Kdim);
        const float* Bg = B + (size_t)(kb * 32 + rB) * Ndim + n0 + cB;
        #pragma unroll
        for (int p = 0; p < 4; p++)
            cp_async16(sb + sBoff + p * (8 * BSTR * 4), Bg + (size_t)p * 8 * Ndim);
    };

    // prologue: stages 0..NS-2
    #pragma unroll
    for (int s = 0; s < NS - 1; s++) { issue(s, s); cp_commit(); }

    for (int kb = 0; kb < nkb; kb++) {
        cp_wait<NS - 2>();
        __syncthreads();
        if (kb + NS - 1 < nkb) issue(kb + NS - 1, (kb + NS - 1) & (NS - 1));
        cp_commit();

        const uint32_t* As = (const uint32_t*)(smg + (size_t)(kb & (NS - 1)) * BUFSZ);
        const uint32_t* Bs = As + ASZ;
        #pragma unroll
        for (int kk = 0; kk < 4; kk++) {
            uint32_t af[4][4], bf[4][2];
            #pragma unroll
            for (int mt = 0; mt < 4; mt++) {
                const uint32_t* ap =
                    As + (wm * 64 + mt * 16 + gid) * ASTR + kk * 8 + tg;
                af[mt][0] = ap[0];
                af[mt][1] = ap[8 * ASTR];
                af[mt][2] = ap[4];
                af[mt][3] = ap[8 * ASTR + 4];
            }
            #pragma unroll
            for (int nt = 0; nt < 4; nt++) {
                const uint32_t* bp =
                    Bs + (kk * 8 + tg) * BSTR + wn * 32 + nt * 8 + gid;
                bf[nt][0] = bp[0];
                bf[nt][1] = bp[4 * BSTR];
            }
            #pragma unroll
            for (int mt = 0; mt < 4; mt++)
                #pragma unroll
                for (int nt = 0; nt < 4; nt++)
                    mma_tf32(acc[mt][nt], af[mt], bf[nt]);
        }
    }

    // epilogue
    #pragma unroll
    for (int mt = 0; mt < 4; mt++) {
        #pragma unroll
        for (int half = 0; half < 2; half++) {
            const int row = m0 + wm * 64 + mt * 16 + gid + half * 8;
            float* Cr = C + (size_t)row * Ndim;
            const float* Rr = resid ? resid + (size_t)row * Ndim : nullptr;
            #pragma unroll
            for (int nt = 0; nt < 4; nt++) {
                const int col = n0 + wn * 32 + nt * 8 + 2 * tg;
                float v0 = acc[mt][nt][half * 2 + 0];
                float v1 = acc[mt][nt][half * 2 + 1];
                if (bias)      { v0 += bias[col]; v1 += bias[col + 1]; }
                if (mode == 1) {
                    v0 = tf32_round(gelu_f(v0));
                    v1 = tf32_round(gelu_f(v1));
                }
                if (Rr)        { v0 += Rr[col]; v1 += Rr[col + 1]; }
                float2 o; o.x = v0; o.y = v1;
                *(float2*)(Cr + col) = o;
            }
        }
    }
}

// ---------------------------------------------------------------------------
// Causal flash attention (fp32 SIMT). q,k,v come from the packed qkv buffer
// (row stride 3*DD); out is [M, D] (b,t,h,hd). Output tf32-rounded (feeds
// the Wo GEMM).
// ---------------------------------------------------------------------------
#define ATILE 64
#define APD 65
#define QSTR (3 * DD)

__global__ __launch_bounds__(256) void attn_kernel(
    const float* __restrict__ qkv, float* __restrict__ out)
{
    extern __shared__ float sm[];
    float* Qs  = sm;
    float* Ks  = Qs + ATILE * APD;
    float* Vs  = Ks + ATILE * APD;
    float* Ss  = Vs + ATILE * APD;
    float* m_s = Ss + ATILE * APD;
    float* l_s = m_s + ATILE;
    float* al_s = l_s + ATILE;

    const int tid = threadIdx.x;
    const int tx = tid & 15;
    const int ty = tid >> 4;
    const int bh = blockIdx.y;
    const int b  = bh / HH;
    const int h  = bh % HH;
    const int qt = blockIdx.x;
    const int q0 = qt * ATILE;

    const size_t qbase = ((size_t)b * TT) * QSTR + (size_t)h * HD;
    const size_t obase = ((size_t)b * TT) * DD + (size_t)h * HD;

    #pragma unroll
    for (int i = 0; i < 16; i++) {
        int idx = tid + i * 256;
        int r = idx >> 6, c = idx & 63;
        Qs[r * APD + c] = qkv[qbase + (size_t)(q0 + r) * QSTR + c];
    }
    if (tid < ATILE) { m_s[tid] = -1e30f; l_s[tid] = 0.f; }

    float acc[4][4];
    #pragma unroll
    for (int i = 0; i < 4; i++)
        #pragma unroll
        for (int j = 0; j < 4; j++) acc[i][j] = 0.f;

    __syncthreads();

    for (int kt = 0; kt <= qt; kt++) {
        const int k0 = kt * ATILE;
        #pragma unroll
        for (int i = 0; i < 16; i++) {
            int idx = tid + i * 256;
            int r = idx >> 6, c = idx & 63;
            Ks[r * APD + c] = qkv[qbase + DD     + (size_t)(k0 + r) * QSTR + c];
            Vs[r * APD + c] = qkv[qbase + 2 * DD + (size_t)(k0 + r) * QSTR + c];
        }
        __syncthreads();

        float s[4][4];
        #pragma unroll
        for (int i = 0; i < 4; i++)
            #pragma unroll
            for (int j = 0; j < 4; j++) s[i][j] = 0.f;
        #pragma unroll 8
        for (int d = 0; d < ATILE; d++) {
            float aq[4], bk[4];
            #pragma unroll
            for (int i = 0; i < 4; i++) aq[i] = Qs[(ty * 4 + i) * APD + d];
            #pragma unroll
            for (int j = 0; j < 4; j++) bk[j] = Ks[(tx * 4 + j) * APD + d];
            #pragma unroll
            for (int i = 0; i < 4; i++)
                #pragma unroll
                for (int j = 0; j < 4; j++)
                    s[i][j] += aq[i] * bk[j];
        }

        const float scale = 0.125f;
        const bool diag = (kt == qt);
        #pragma unroll
        for (int i = 0; i < 4; i++) {
            const int r = ty * 4 + i;
            #pragma unroll
            for (int j = 0; j < 4; j++) {
                const int c = tx * 4 + j;
                float val = s[i][j] * scale;
                if (diag && c > r) val = -1e30f;
                Ss[r * APD + c] = val;
            }
        }
        __syncthreads();

        if (tid < ATILE) {
            const int r = tid;
            float mp = m_s[r];
            float mm = mp;
            #pragma unroll 8
            for (int c = 0; c < ATILE; c++) mm = fmaxf(mm, Ss[r * APD + c]);
            float al = __expf(mp - mm);
            float sum = 0.f;
            #pragma unroll 8
            for (int c = 0; c < ATILE; c++) {
                float p = __expf(Ss[r * APD + c] - mm);
                Ss[r * APD + c] = p;
                sum += p;
            }
            l_s[r] = l_s[r] * al + sum;
            m_s[r] = mm;
            al_s[r] = al;
        }
        __syncthreads();

        #pragma unroll
        for (int i = 0; i < 4; i++) {
            float al = al_s[ty * 4 + i];
            #pragma unroll
            for (int j = 0; j < 4; j++) acc[i][j] *= al;
        }
        #pragma unroll 8
        for (int d = 0; d < ATILE; d++) {
            float p[4], vv[4];
            #pragma unroll
            for (int i = 0; i < 4; i++) p[i] = Ss[(ty * 4 + i) * APD + d];
            #pragma unroll
            for (int j = 0; j < 4; j++) vv[j] = Vs[d * APD + tx * 4 + j];
            #pragma unroll
            for (int i = 0; i < 4; i++)
                #pragma unroll
                for (int j = 0; j < 4; j++)
                    acc[i][j] += p[i] * vv[j];
        }
        __syncthreads();
    }

    #pragma unroll
    for (int i = 0; i < 4; i++) {
        const int r = ty * 4 + i;
        const float invl = 1.0f / l_s[r];
        #pragma unroll
        for (int j = 0; j < 4; j++) {
            const int c = tx * 4 + j;
            out[obase + (size_t)(q0 + r) * DD + c] = tf32_round(acc[i][j] * invl);
        }
    }
}

// ---------------------------------------------------------------------------
// Host launch
// ---------------------------------------------------------------------------
extern "C" void kernel_launch(void* const* d_in, const int* in_sizes, int n_in,
                              void* d_out, int out_size)
{
    const float* x    = (const float*)d_in[0];
    const float* Wq   = (const float*)d_in[1];
    const float* Wk   = (const float*)d_in[2];
    const float* Wv   = (const float*)d_in[3];
    const float* Wo   = (const float*)d_in[4];
    const float* bo   = (const float*)d_in[5];
    const float* W1   = (const float*)d_in[6];
    const float* b1   = (const float*)d_in[7];
    const float* W2   = (const float*)d_in[8];
    const float* b2   = (const float*)d_in[9];
    const float* g1   = (const float*)d_in[10];
    const float* be1  = (const float*)d_in[11];
    const float* g2   = (const float*)d_in[12];
    const float* be2  = (const float*)d_in[13];
    float* out = (float*)d_out;

    float *h, *qkv, *attn, *x2, *h2, *ff1;
    float *wqkv, *wo, *w1, *w2;
    cudaGetSymbolAddress((void**)&h,    g_h);
    cudaGetSymbolAddress((void**)&qkv,  g_qkv);
    cudaGetSymbolAddress((void**)&attn, g_attn);
    cudaGetSymbolAddress((void**)&x2,   g_x2);
    cudaGetSymbolAddress((void**)&h2,   g_h2);
    cudaGetSymbolAddress((void**)&ff1,  g_ff1);
    cudaGetSymbolAddress((void**)&wqkv, g_wqkv);
    cudaGetSymbolAddress((void**)&wo,   g_wo);
    cudaGetSymbolAddress((void**)&w1,   g_w1);
    cudaGetSymbolAddress((void**)&w2,   g_w2);

    const int ATTN_SMEM = (4 * ATILE * APD + 3 * ATILE) * (int)sizeof(float);
    cudaFuncSetAttribute(attn_kernel,
                         cudaFuncAttributeMaxDynamicSharedMemorySize, ATTN_SMEM);
    cudaFuncSetAttribute(gemm_mma,
                         cudaFuncAttributeMaxDynamicSharedMemorySize, GEMM_SMEM);

    // 0) weight preprocessing: tf32 rounding (+ QKV pack)
    pack_qkv_kernel<<<dim3(1024, 3), 256>>>(Wq, Wk, Wv, wqkv);
    cvt_tf32_kernel<<<1024, 256>>>(Wo, wo);
    cvt_tf32_kernel<<<4096, 256>>>(W1, w1);
    cvt_tf32_kernel<<<4096, 256>>>(W2, w2);

    // 1) LN1 (tf32-rounded output)
    layernorm_kernel<<<MM, 256>>>(x, g1, be1, h);

    // 2) fused QKV projection
    gemm_mma<<<dim3(3 * DD / 128, MM / 128), 256, GEMM_SMEM>>>(
        h, wqkv, nullptr, nullptr, qkv, 3 * DD, DD, 0);

    // 3) causal attention (tf32-rounded output)
    attn_kernel<<<dim3(TT / ATILE, BB * HH), 256, ATTN_SMEM>>>(qkv, attn);

    // 4) output projection + bias + residual(x)
    dim3 gDD(DD / 128, MM / 128);
    gemm_mma<<<gDD, 256, GEMM_SMEM>>>(attn, wo, bo, x, x2, DD, DD, 0);

    // 5) LN2 (tf32-rounded output)
    layernorm_kernel<<<MM, 256>>>(x2, g2, be2, h2);

    // 6) FFN1 + bias + GELU (tf32-rounded output)
    gemm_mma<<<dim3(FF / 128, MM / 128), 256, GEMM_SMEM>>>(
        h2, w1, b1, nullptr, ff1, FF, DD, 1);

    // 7) FFN2 + bias + residual(x2) -> out
    gemm_mma<<<gDD, 256, GEMM_SMEM>>>(ff1, w2, b2, x2, out, DD, FF, 2);
}

// round 5
// speedup vs baseline: 2.3028x; 1.0033x over previous
#include <cuda_runtime.h>
#include <cuda_bf16.h>
#include <math.h>
#include <stdint.h>

// ---------------------------------------------------------------------------
// Problem constants
// ---------------------------------------------------------------------------
#define BB 4
#define TT 2048
#define DD 1024
#define HH 16
#define HD 64
#define FF 4096
#define MM (BB * TT)       // 8192 rows
#define EPS 1e-5f

// ---------------------------------------------------------------------------
// Scratch (allocation-free: __device__ globals)
// ---------------------------------------------------------------------------
__device__ float g_h   [(size_t)MM * DD];
__device__ float g_qkv [(size_t)MM * 3 * DD];
__device__ float g_attn[(size_t)MM * DD];
__device__ float g_x2  [(size_t)MM * DD];
__device__ float g_h2  [(size_t)MM * DD];
__device__ float g_ff1 [(size_t)MM * FF];
// tf32-rounded weights
__device__ float g_wqkv[(size_t)DD * 3 * DD];
__device__ float g_wo  [(size_t)DD * DD];
__device__ float g_w1  [(size_t)DD * FF];
__device__ float g_w2  [(size_t)FF * DD];

// ---------------------------------------------------------------------------
// tf32 helpers
// ---------------------------------------------------------------------------
__device__ __forceinline__ uint32_t tf32_cvt(float f) {
    uint32_t r;
    asm("cvt.rna.tf32.f32 %0, %1;" : "=r"(r) : "f"(f));
    return r;
}
__device__ __forceinline__ float tf32_round(float f) {
    return __uint_as_float(tf32_cvt(f));
}
__device__ __forceinline__ void mma_tf32(float c[4], const uint32_t a[4],
                                         const uint32_t b[2]) {
    asm volatile(
        "mma.sync.aligned.m16n8k8.row.col.f32.tf32.tf32.f32 "
        "{%0,%1,%2,%3}, {%4,%5,%6,%7}, {%8,%9}, {%0,%1,%2,%3};"
        : "+f"(c[0]), "+f"(c[1]), "+f"(c[2]), "+f"(c[3])
        : "r"(a[0]), "r"(a[1]), "r"(a[2]), "r"(a[3]), "r"(b[0]), "r"(b[1]));
}
__device__ __forceinline__ uint32_t smem_u32(const void* p) {
    uint32_t a;
    asm("{ .reg .u64 t; cvta.to.shared.u64 t, %1; cvt.u32.u64 %0, t; }"
        : "=r"(a) : "l"(p));
    return a;
}
__device__ __forceinline__ void cp_async16(uint32_t saddr, const void* gptr) {
    asm volatile("cp.async.cg.shared.global [%0], [%1], 16;"
                 :: "r"(saddr), "l"(gptr) : "memory");
}
__device__ __forceinline__ void cp_commit() {
    asm volatile("cp.async.commit_group;" ::: "memory");
}
template <int N>
__device__ __forceinline__ void cp_wait() {
    asm volatile("cp.async.wait_group %0;" :: "n"(N) : "memory");
}

// ---------------------------------------------------------------------------
// Weight preprocessing: tf32-round (and pack QKV)
// ---------------------------------------------------------------------------
__global__ __launch_bounds__(256) void cvt_tf32_kernel(
    const float* __restrict__ in, float* __restrict__ out)
{
    const size_t i = ((size_t)blockIdx.x * 256 + threadIdx.x) * 4;
    float4 v = *(const float4*)(in + i);
    v.x = tf32_round(v.x); v.y = tf32_round(v.y);
    v.z = tf32_round(v.z); v.w = tf32_round(v.w);
    *(float4*)(out + i) = v;
}

__global__ __launch_bounds__(256) void pack_qkv_kernel(
    const float* __restrict__ Wq, const float* __restrict__ Wk,
    const float* __restrict__ Wv, float* __restrict__ out)
{
    const int sel = blockIdx.y;
    const float* src = sel == 0 ? Wq : (sel == 1 ? Wk : Wv);
    const size_t i = ((size_t)blockIdx.x * 256 + threadIdx.x) * 4;
    const int r = (int)(i >> 10);          // /1024
    const int c = (int)(i & 1023);
    float4 v = *(const float4*)(src + i);
    v.x = tf32_round(v.x); v.y = tf32_round(v.y);
    v.z = tf32_round(v.z); v.w = tf32_round(v.w);
    *(float4*)(out + (size_t)r * (3 * DD) + sel * DD + c) = v;
}

// ---------------------------------------------------------------------------
// LayerNorm: one block (256 threads) per row of 1024; tf32-rounds the output
// ---------------------------------------------------------------------------
__global__ __launch_bounds__(256) void layernorm_kernel(
    const float* __restrict__ x, const float* __restrict__ gamma,
    const float* __restrict__ beta, float* __restrict__ out)
{
    __shared__ float shs[8], shss[8];
    __shared__ float s_mean, s_inv;
    const int row = blockIdx.x;
    const int tid = threadIdx.x;

    const float4 xv = *(const float4*)(x + (size_t)row * DD + tid * 4);
    float s  = xv.x + xv.y + xv.z + xv.w;
    float ss = xv.x * xv.x + xv.y * xv.y + xv.z * xv.z + xv.w * xv.w;
    #pragma unroll
    for (int o = 16; o > 0; o >>= 1) {
        s  += __shfl_down_sync(0xffffffffu, s, o);
        ss += __shfl_down_sync(0xffffffffu, ss, o);
    }
    if ((tid & 31) == 0) { shs[tid >> 5] = s; shss[tid >> 5] = ss; }
    __syncthreads();
    if (tid == 0) {
        float S = 0.f, SS = 0.f;
        #pragma unroll
        for (int i = 0; i < 8; i++) { S += shs[i]; SS += shss[i]; }
        float mean = S * (1.0f / DD);
        float var  = SS * (1.0f / DD) - mean * mean;
        s_mean = mean;
        s_inv  = rsqrtf(var + EPS);
    }
    __syncthreads();
    const float mean = s_mean, inv = s_inv;
    const float4 gv = *(const float4*)(gamma + tid * 4);
    const float4 bv = *(const float4*)(beta  + tid * 4);
    float4 o;
    o.x = tf32_round(gv.x * (xv.x - mean) * inv + bv.x);
    o.y = tf32_round(gv.y * (xv.y - mean) * inv + bv.y);
    o.z = tf32_round(gv.z * (xv.z - mean) * inv + bv.z);
    o.w = tf32_round(gv.w * (xv.w - mean) * inv + bv.w);
    *(float4*)(out + (size_t)row * DD + tid * 4) = o;
}

// ---------------------------------------------------------------------------
// GELU (tanh approximation, matches reference)
// ---------------------------------------------------------------------------
__device__ __forceinline__ float gelu_f(float x)
{
    const float c = 0.7978845608028654f;  // sqrt(2/pi)
    float inner = c * (x + 0.044715f * x * x * x);
    return 0.5f * x * (1.0f + tanhf(inner));
}

// ---------------------------------------------------------------------------
// tf32 tensor-core GEMM:  C[M,N] = A[M,K] @ B[K,N]  (+bias)(+gelu)(+residual)
// Inputs pre-rounded to tf32. 128x128x32 tile, 256 threads, 8 warps (2x4),
// m16n8k8 mma, cp.async 4-stage pipeline, register double-buffered fragments.
// mode: 0 = plain, 1 = gelu + tf32-round output (FFN1)
// ---------------------------------------------------------------------------
#define ASTR 36
#define BSTR 136
#define ASZ (128 * ASTR)          // 4608 floats
#define BSZ (32 * BSTR)           // 4352 floats
#define BUFSZ (ASZ + BSZ)         // 8960 floats
#define NS 4
#define STAGE_BYTES (BUFSZ * 4)   // 35840 bytes
#define GEMM_SMEM (NS * STAGE_BYTES)  // 143360 bytes

__global__ __launch_bounds__(256) void gemm_mma(
    const float* __restrict__ A, const float* __restrict__ B,
    const float* __restrict__ bias,   // may be null
    const float* __restrict__ resid,  // may be null
    float* __restrict__ C,
    int Ndim, int Kdim, int mode)
{
    extern __shared__ __align__(16) float smg[];
    const uint32_t sbase = smem_u32(smg);
    const int tid  = threadIdx.x;
    const int lane = tid & 31;
    const int warp = tid >> 5;
    const int wm   = warp >> 2;     // 0..1
    const int wn   = warp & 3;      // 0..3
    const int gid  = lane >> 2;     // 0..7
    const int tg   = lane & 3;      // 0..3
    const int m0 = blockIdx.y * 128;
    const int n0 = blockIdx.x * 128;

    // loader mapping
    const int rA = tid >> 3;             // 0..31
    const int cA = (tid & 7) * 4;        // 0..28
    const int rB = tid >> 5;             // 0..7
    const int cB = (tid & 31) * 4;       // 0..124

    const uint32_t sAoff = (uint32_t)(rA * ASTR + cA) * 4;
    const uint32_t sBoff = (uint32_t)(ASZ + rB * BSTR + cB) * 4;

    float acc[4][4][4];
    #pragma unroll
    for (int mt = 0; mt < 4; mt++)
        #pragma unroll
        for (int nt = 0; nt < 4; nt++)
            #pragma unroll
            for (int r = 0; r < 4; r++) acc[mt][nt][r] = 0.f;

    const int nkb = Kdim / 32;

    auto issue = [&](int kb, int slot) {
        const uint32_t sb = sbase + slot * STAGE_BYTES;
        const float* Ag = A + (size_t)(m0 + rA) * Kdim + kb * 32 + cA;
        #pragma unroll
        for (int p = 0; p < 4; p++)
            cp_async16(sb + sAoff + p * (32 * ASTR * 4), Ag + (size_t)p * 32 * Kdim);
        const float* Bg = B + (size_t)(kb * 32 + rB) * Ndim + n0 + cB;
        #pragma unroll
        for (int p = 0; p < 4; p++)
            cp_async16(sb + sBoff + p * (8 * BSTR * 4), Bg + (size_t)p * 8 * Ndim);
    };

    // prologue: stages 0..NS-2
    #pragma unroll
    for (int s = 0; s < NS - 1; s++) { issue(s, s); cp_commit(); }

    // register fragment double buffer
    uint32_t af[2][4][4], bf[2][4][2];

    for (int kb = 0; kb < nkb; kb++) {
        cp_wait<NS - 2>();
        __syncthreads();
        if (kb + NS - 1 < nkb) issue(kb + NS - 1, (kb + NS - 1) & (NS - 1));
        cp_commit();

        const uint32_t* As = (const uint32_t*)(smg + (size_t)(kb & (NS - 1)) * BUFSZ);
        const uint32_t* Bs = As + ASZ;

        auto ldfrag = [&](int kk, uint32_t a[4][4], uint32_t b[4][2]) {
            #pragma unroll
            for (int mt = 0; mt < 4; mt++) {
                const uint32_t* ap =
                    As + (wm * 64 + mt * 16 + gid) * ASTR + kk * 8 + tg;
                a[mt][0] = ap[0];
                a[mt][1] = ap[8 * ASTR];
                a[mt][2] = ap[4];
                a[mt][3] = ap[8 * ASTR + 4];
            }
            #pragma unroll
            for (int nt = 0; nt < 4; nt++) {
                const uint32_t* bp =
                    Bs + (kk * 8 + tg) * BSTR + wn * 32 + nt * 8 + gid;
                b[nt][0] = bp[0];
                b[nt][1] = bp[4 * BSTR];
            }
        };

        ldfrag(0, af[0], bf[0]);
        #pragma unroll
        for (int kk = 0; kk < 4; kk++) {
            const int cur = kk & 1;
            if (kk < 3) ldfrag(kk + 1, af[cur ^ 1], bf[cur ^ 1]);
            #pragma unroll
            for (int mt = 0; mt < 4; mt++)
                #pragma unroll
                for (int nt = 0; nt < 4; nt++)
                    mma_tf32(acc[mt][nt], af[cur][mt], bf[cur][nt]);
        }
    }

    // epilogue
    #pragma unroll
    for (int mt = 0; mt < 4; mt++) {
        #pragma unroll
        for (int half = 0; half < 2; half++) {
            const int row = m0 + wm * 64 + mt * 16 + gid + half * 8;
            float* Cr = C + (size_t)row * Ndim;
            const float* Rr = resid ? resid + (size_t)row * Ndim : nullptr;
            #pragma unroll
            for (int nt = 0; nt < 4; nt++) {
                const int col = n0 + wn * 32 + nt * 8 + 2 * tg;
                float v0 = acc[mt][nt][half * 2 + 0];
                float v1 = acc[mt][nt][half * 2 + 1];
                if (bias)      { v0 += bias[col]; v1 += bias[col + 1]; }
                if (mode == 1) {
                    v0 = tf32_round(gelu_f(v0));
                    v1 = tf32_round(gelu_f(v1));
                }
                if (Rr)        { v0 += Rr[col]; v1 += Rr[col + 1]; }
                float2 o; o.x = v0; o.y = v1;
                *(float2*)(Cr + col) = o;
            }
        }
    }
}

// ---------------------------------------------------------------------------
// Causal flash attention (fp32 SIMT). q,k,v come from the packed qkv buffer
// (row stride 3*DD); out is [M, D] (b,t,h,hd). Output tf32-rounded.
// ---------------------------------------------------------------------------
#define ATILE 64
#define APD 65
#define QSTR (3 * DD)

__global__ __launch_bounds__(256) void attn_kernel(
    const float* __restrict__ qkv, float* __restrict__ out)
{
    extern __shared__ float sm[];
    float* Qs  = sm;
    float* Ks  = Qs + ATILE * APD;
    float* Vs  = Ks + ATILE * APD;
    float* Ss  = Vs + ATILE * APD;
    float* m_s = Ss + ATILE * APD;
    float* l_s = m_s + ATILE;
    float* al_s = l_s + ATILE;

    const int tid = threadIdx.x;
    const int tx = tid & 15;
    const int ty = tid >> 4;
    const int bh = blockIdx.y;
    const int b  = bh / HH;
    const int h  = bh % HH;
    const int qt = blockIdx.x;
    const int q0 = qt * ATILE;

    const size_t qbase = ((size_t)b * TT) * QSTR + (size_t)h * HD;
    const size_t obase = ((size_t)b * TT) * DD + (size_t)h * HD;

    #pragma unroll
    for (int i = 0; i < 16; i++) {
        int idx = tid + i * 256;
        int r = idx >> 6, c = idx & 63;
        Qs[r * APD + c] = qkv[qbase + (size_t)(q0 + r) * QSTR + c];
    }
    if (tid < ATILE) { m_s[tid] = -1e30f; l_s[tid] = 0.f; }

    float acc[4][4];
    #pragma unroll
    for (int i = 0; i < 4; i++)
        #pragma unroll
        for (int j = 0; j < 4; j++) acc[i][j] = 0.f;

    __syncthreads();

    for (int kt = 0; kt <= qt; kt++) {
        const int k0 = kt * ATILE;
        #pragma unroll
        for (int i = 0; i < 16; i++) {
            int idx = tid + i * 256;
            int r = idx >> 6, c = idx & 63;
            Ks[r * APD + c] = qkv[qbase + DD     + (size_t)(k0 + r) * QSTR + c];
            Vs[r * APD + c] = qkv[qbase + 2 * DD + (size_t)(k0 + r) * QSTR + c];
        }
        __syncthreads();

        float s[4][4];
        #pragma unroll
        for (int i = 0; i < 4; i++)
            #pragma unroll
            for (int j = 0; j < 4; j++) s[i][j] = 0.f;
        #pragma unroll 8
        for (int d = 0; d < ATILE; d++) {
            float aq[4], bk[4];
            #pragma unroll
            for (int i = 0; i < 4; i++) aq[i] = Qs[(ty * 4 + i) * APD + d];
            #pragma unroll
            for (int j = 0; j < 4; j++) bk[j] = Ks[(tx * 4 + j) * APD + d];
            #pragma unroll
            for (int i = 0; i < 4; i++)
                #pragma unroll
                for (int j = 0; j < 4; j++)
                    s[i][j] += aq[i] * bk[j];
        }

        const float scale = 0.125f;
        const bool diag = (kt == qt);
        #pragma unroll
        for (int i = 0; i < 4; i++) {
            const int r = ty * 4 + i;
            #pragma unroll
            for (int j = 0; j < 4; j++) {
                const int c = tx * 4 + j;
                float val = s[i][j] * scale;
                if (diag && c > r) val = -1e30f;
                Ss[r * APD + c] = val;
            }
        }
        __syncthreads();

        if (tid < ATILE) {
            const int r = tid;
            float mp = m_s[r];
            float mm = mp;
            #pragma unroll 8
            for (int c = 0; c < ATILE; c++) mm = fmaxf(mm, Ss[r * APD + c]);
            float al = __expf(mp - mm);
            float sum = 0.f;
            #pragma unroll 8
            for (int c = 0; c < ATILE; c++) {
                float p = __expf(Ss[r * APD + c] - mm);
                Ss[r * APD + c] = p;
                sum += p;
            }
            l_s[r] = l_s[r] * al + sum;
            m_s[r] = mm;
            al_s[r] = al;
        }
        __syncthreads();

        #pragma unroll
        for (int i = 0; i < 4; i++) {
            float al = al_s[ty * 4 + i];
            #pragma unroll
            for (int j = 0; j < 4; j++) acc[i][j] *= al;
        }
        #pragma unroll 8
        for (int d = 0; d < ATILE; d++) {
            float p[4], vv[4];
            #pragma unroll
            for (int i = 0; i < 4; i++) p[i] = Ss[(ty * 4 + i) * APD + d];
            #pragma unroll
            for (int j = 0; j < 4; j++) vv[j] = Vs[d * APD + tx * 4 + j];
            #pragma unroll
            for (int i = 0; i < 4; i++)
                #pragma unroll
                for (int j = 0; j < 4; j++)
                    acc[i][j] += p[i] * vv[j];
        }
        __syncthreads();
    }

    #pragma unroll
    for (int i = 0; i < 4; i++) {
        const int r = ty * 4 + i;
        const float invl = 1.0f / l_s[r];
        #pragma unroll
        for (int j = 0; j < 4; j++) {
            const int c = tx * 4 + j;
            out[obase + (size_t)(q0 + r) * DD + c] = tf32_round(acc[i][j] * invl);
        }
    }
}

// ---------------------------------------------------------------------------
// Host launch
// ---------------------------------------------------------------------------
extern "C" void kernel_launch(void* const* d_in, const int* in_sizes, int n_in,
                              void* d_out, int out_size)
{
    const float* x    = (const float*)d_in[0];
    const float* Wq   = (const float*)d_in[1];
    const float* Wk   = (const float*)d_in[2];
    const float* Wv   = (const float*)d_in[3];
    const float* Wo   = (const float*)d_in[4];
    const float* bo   = (const float*)d_in[5];
    const float* W1   = (const float*)d_in[6];
    const float* b1   = (const float*)d_in[7];
    const float* W2   = (const float*)d_in[8];
    const float* b2   = (const float*)d_in[9];
    const float* g1   = (const float*)d_in[10];
    const float* be1  = (const float*)d_in[11];
    const float* g2   = (const float*)d_in[12];
    const float* be2  = (const float*)d_in[13];
    float* out = (float*)d_out;

    float *h, *qkv, *attn, *x2, *h2, *ff1;
    float *wqkv, *wo, *w1, *w2;
    cudaGetSymbolAddress((void**)&h,    g_h);
    cudaGetSymbolAddress((void**)&qkv,  g_qkv);
    cudaGetSymbolAddress((void**)&attn, g_attn);
    cudaGetSymbolAddress((void**)&x2,   g_x2);
    cudaGetSymbolAddress((void**)&h2,   g_h2);
    cudaGetSymbolAddress((void**)&ff1,  g_ff1);
    cudaGetSymbolAddress((void**)&wqkv, g_wqkv);
    cudaGetSymbolAddress((void**)&wo,   g_wo);
    cudaGetSymbolAddress((void**)&w1,   g_w1);
    cudaGetSymbolAddress((void**)&w2,   g_w2);

    const int ATTN_SMEM = (4 * ATILE * APD + 3 * ATILE) * (int)sizeof(float);
    cudaFuncSetAttribute(attn_kernel,
                         cudaFuncAttributeMaxDynamicSharedMemorySize, ATTN_SMEM);
    cudaFuncSetAttribute(gemm_mma,
                         cudaFuncAttributeMaxDynamicSharedMemorySize, GEMM_SMEM);

    // 0) weight preprocessing: tf32 rounding (+ QKV pack)
    pack_qkv_kernel<<<dim3(1024, 3), 256>>>(Wq, Wk, Wv, wqkv);
    cvt_tf32_kernel<<<1024, 256>>>(Wo, wo);
    cvt_tf32_kernel<<<4096, 256>>>(W1, w1);
    cvt_tf32_kernel<<<4096, 256>>>(W2, w2);

    // 1) LN1 (tf32-rounded output)
    layernorm_kernel<<<MM, 256>>>(x, g1, be1, h);

    // 2) fused QKV projection
    gemm_mma<<<dim3(3 * DD / 128, MM / 128), 256, GEMM_SMEM>>>(
        h, wqkv, nullptr, nullptr, qkv, 3 * DD, DD, 0);

    // 3) causal attention (tf32-rounded output)
    attn_kernel<<<dim3(TT / ATILE, BB * HH), 256, ATTN_SMEM>>>(qkv, attn);

    // 4) output projection + bias + residual(x)
    dim3 gDD(DD / 128, MM / 128);
    gemm_mma<<<gDD, 256, GEMM_SMEM>>>(attn, wo, bo, x, x2, DD, DD, 0);

    // 5) LN2 (tf32-rounded output)
    layernorm_kernel<<<MM, 256>>>(x2, g2, be2, h2);

    // 6) FFN1 + bias + GELU (tf32-rounded output)
    gemm_mma<<<dim3(FF / 128, MM / 128), 256, GEMM_SMEM>>>(
        h2, w1, b1, nullptr, ff1, FF, DD, 1);

    // 7) FFN2 + bias + residual(x2) -> out
    gemm_mma<<<gDD, 256, GEMM_SMEM>>>(ff1, w2, b2, x2, out, DD, FF, 2);
}

// round 6
// speedup vs baseline: 2.5096x; 1.0898x over previous
#include <cuda_runtime.h>
#include <cuda_bf16.h>
#include <math.h>
#include <stdint.h>

// ---------------------------------------------------------------------------
// Problem constants
// ---------------------------------------------------------------------------
#define BB 4
#define TT 2048
#define DD 1024
#define HH 16
#define HD 64
#define FF 4096
#define MM (BB * TT)       // 8192 rows
#define EPS 1e-5f

// ---------------------------------------------------------------------------
// Scratch (allocation-free: __device__ globals)
// ---------------------------------------------------------------------------
__device__ float g_h   [(size_t)MM * DD];
__device__ float g_qkv [(size_t)MM * 3 * DD];
__device__ float g_attn[(size_t)MM * DD];
__device__ float g_x2  [(size_t)MM * DD];
__device__ float g_h2  [(size_t)MM * DD];
__device__ float g_ff1 [(size_t)MM * FF];
// tf32-rounded weights
__device__ float g_wqkv[(size_t)DD * 3 * DD];
__device__ float g_wo  [(size_t)DD * DD];
__device__ float g_w1  [(size_t)DD * FF];
__device__ float g_w2  [(size_t)FF * DD];

// ---------------------------------------------------------------------------
// tf32 helpers
// ---------------------------------------------------------------------------
__device__ __forceinline__ uint32_t tf32_cvt(float f) {
    uint32_t r;
    asm("cvt.rna.tf32.f32 %0, %1;" : "=r"(r) : "f"(f));
    return r;
}
__device__ __forceinline__ float tf32_round(float f) {
    return __uint_as_float(tf32_cvt(f));
}
__device__ __forceinline__ void mma_tf32(float c[4], const uint32_t a[4],
                                         const uint32_t b[2]) {
    asm volatile(
        "mma.sync.aligned.m16n8k8.row.col.f32.tf32.tf32.f32 "
        "{%0,%1,%2,%3}, {%4,%5,%6,%7}, {%8,%9}, {%0,%1,%2,%3};"
        : "+f"(c[0]), "+f"(c[1]), "+f"(c[2]), "+f"(c[3])
        : "r"(a[0]), "r"(a[1]), "r"(a[2]), "r"(a[3]), "r"(b[0]), "r"(b[1]));
}
__device__ __forceinline__ void cp_async16(uint32_t saddr, const void* gptr) {
    asm volatile("cp.async.cg.shared.global [%0], [%1], 16;"
                 :: "r"(saddr), "l"(gptr) : "memory");
}
__device__ __forceinline__ void cp_commit() {
    asm volatile("cp.async.commit_group;" ::: "memory");
}
template <int N>
__device__ __forceinline__ void cp_wait() {
    asm volatile("cp.async.wait_group %0;" :: "n"(N) : "memory");
}
__device__ __forceinline__ uint32_t smem_u32(const void* p) {
    uint32_t a;
    asm("{ .reg .u64 t; cvta.to.shared.u64 t, %1; cvt.u32.u64 %0, t; }"
        : "=r"(a) : "l"(p));
    return a;
}

// ---------------------------------------------------------------------------
// Weight preprocessing: tf32-round (and pack QKV)
// ---------------------------------------------------------------------------
__global__ __launch_bounds__(256) void cvt_tf32_kernel(
    const float* __restrict__ in, float* __restrict__ out)
{
    const size_t i = ((size_t)blockIdx.x * 256 + threadIdx.x) * 4;
    float4 v = *(const float4*)(in + i);
    v.x = tf32_round(v.x); v.y = tf32_round(v.y);
    v.z = tf32_round(v.z); v.w = tf32_round(v.w);
    *(float4*)(out + i) = v;
}

__global__ __launch_bounds__(256) void pack_qkv_kernel(
    const float* __restrict__ Wq, const float* __restrict__ Wk,
    const float* __restrict__ Wv, float* __restrict__ out)
{
    const int sel = blockIdx.y;
    const float* src = sel == 0 ? Wq : (sel == 1 ? Wk : Wv);
    const size_t i = ((size_t)blockIdx.x * 256 + threadIdx.x) * 4;
    const int r = (int)(i >> 10);          // /1024
    const int c = (int)(i & 1023);
    float4 v = *(const float4*)(src + i);
    v.x = tf32_round(v.x); v.y = tf32_round(v.y);
    v.z = tf32_round(v.z); v.w = tf32_round(v.w);
    *(float4*)(out + (size_t)r * (3 * DD) + sel * DD + c) = v;
}

// ---------------------------------------------------------------------------
// LayerNorm: one block (256 threads) per row of 1024; tf32-rounds the output
// ---------------------------------------------------------------------------
__global__ __launch_bounds__(256) void layernorm_kernel(
    const float* __restrict__ x, const float* __restrict__ gamma,
    const float* __restrict__ beta, float* __restrict__ out)
{
    __shared__ float shs[8], shss[8];
    __shared__ float s_mean, s_inv;
    const int row = blockIdx.x;
    const int tid = threadIdx.x;

    const float4 xv = *(const float4*)(x + (size_t)row * DD + tid * 4);
    float s  = xv.x + xv.y + xv.z + xv.w;
    float ss = xv.x * xv.x + xv.y * xv.y + xv.z * xv.z + xv.w * xv.w;
    #pragma unroll
    for (int o = 16; o > 0; o >>= 1) {
        s  += __shfl_down_sync(0xffffffffu, s, o);
        ss += __shfl_down_sync(0xffffffffu, ss, o);
    }
    if ((tid & 31) == 0) { shs[tid >> 5] = s; shss[tid >> 5] = ss; }
    __syncthreads();
    if (tid == 0) {
        float S = 0.f, SS = 0.f;
        #pragma unroll
        for (int i = 0; i < 8; i++) { S += shs[i]; SS += shss[i]; }
        float mean = S * (1.0f / DD);
        float var  = SS * (1.0f / DD) - mean * mean;
        s_mean = mean;
        s_inv  = rsqrtf(var + EPS);
    }
    __syncthreads();
    const float mean = s_mean, inv = s_inv;
    const float4 gv = *(const float4*)(gamma + tid * 4);
    const float4 bv = *(const float4*)(beta  + tid * 4);
    float4 o;
    o.x = tf32_round(gv.x * (xv.x - mean) * inv + bv.x);
    o.y = tf32_round(gv.y * (xv.y - mean) * inv + bv.y);
    o.z = tf32_round(gv.z * (xv.z - mean) * inv + bv.z);
    o.w = tf32_round(gv.w * (xv.w - mean) * inv + bv.w);
    *(float4*)(out + (size_t)row * DD + tid * 4) = o;
}

// ---------------------------------------------------------------------------
// GELU (tanh approximation, matches reference)
// ---------------------------------------------------------------------------
__device__ __forceinline__ float gelu_f(float x)
{
    const float c = 0.7978845608028654f;  // sqrt(2/pi)
    float inner = c * (x + 0.044715f * x * x * x);
    return 0.5f * x * (1.0f + tanhf(inner));
}

// ---------------------------------------------------------------------------
// tf32 tensor-core GEMM:  C[M,N] = A[M,K] @ B[K,N]  (+bias)(+gelu)(+residual)
// Inputs pre-rounded to tf32. CTA tile 128x256, BK=32, 256 threads, 8 warps
// (2x4), warp tile 64x64 (4 m-frags x 8 n-frags = 32 MMAs per kk-step).
// cp.async 3-stage pipeline. mode: 0 = plain, 1 = gelu + tf32-round (FFN1)
// A smem stride 36 floats, B smem stride 264 floats (conflict-free LDS).
// M % 128 == 0, N % 256 == 0, K % 32 == 0.
// ---------------------------------------------------------------------------
#define ASTR 36
#define BSTR 264
#define ASZ (128 * ASTR)            // 4608 floats
#define BSZ (32 * BSTR)             // 8448 floats
#define BUFSZ (ASZ + BSZ)           // 13056 floats
#define NS 3
#define STAGE_BYTES (BUFSZ * 4)     // 52224 bytes
#define GEMM_SMEM (NS * STAGE_BYTES)  // 156672 bytes

__global__ __launch_bounds__(256, 1) void gemm_mma(
    const float* __restrict__ A, const float* __restrict__ B,
    const float* __restrict__ bias,   // may be null
    const float* __restrict__ resid,  // may be null
    float* __restrict__ C,
    int Ndim, int Kdim, int mode)
{
    extern __shared__ __align__(16) float smg[];
    const uint32_t sbase = smem_u32(smg);
    const int tid  = threadIdx.x;
    const int lane = tid & 31;
    const int warp = tid >> 5;
    const int wm   = warp >> 2;     // 0..1  (64-row slab)
    const int wn   = warp & 3;      // 0..3  (64-col slab)
    const int gid  = lane >> 2;     // 0..7
    const int tg   = lane & 3;      // 0..3
    const int m0 = blockIdx.y * 128;
    const int n0 = blockIdx.x * 256;

    // A loader: 4 float4 per thread (rows tid>>3 + 32p, col (tid&7)*4)
    const int rA = tid >> 3;             // 0..31
    const int cA = (tid & 7) * 4;        // 0,4,..,28
    // B loader: 8 float4 per thread (idx = tid + 256p; row idx>>6, col (idx&63)*4)
    const int rB = tid >> 6;             // 0..3
    const int cB = (tid & 63) * 4;       // 0..252

    const uint32_t sAoff = (uint32_t)(rA * ASTR + cA) * 4;
    const uint32_t sBoff = (uint32_t)(ASZ + rB * BSTR + cB) * 4;

    float acc[4][8][4];
    #pragma unroll
    for (int mt = 0; mt < 4; mt++)
        #pragma unroll
        for (int nt = 0; nt < 8; nt++)
            #pragma unroll
            for (int r = 0; r < 4; r++) acc[mt][nt][r] = 0.f;

    const int nkb = Kdim / 32;

    auto issue = [&](int kb, int slot) {
        const uint32_t sb = sbase + slot * STAGE_BYTES;
        const float* Ag = A + (size_t)(m0 + rA) * Kdim + kb * 32 + cA;
        #pragma unroll
        for (int p = 0; p < 4; p++)
            cp_async16(sb + sAoff + p * (32 * ASTR * 4), Ag + (size_t)p * 32 * Kdim);
        const float* Bg = B + (size_t)(kb * 32 + rB) * Ndim + n0 + cB;
        #pragma unroll
        for (int p = 0; p < 8; p++)
            cp_async16(sb + sBoff + p * (4 * BSTR * 4), Bg + (size_t)p * 4 * Ndim);
    };

    // prologue: fill stages 0 and 1
    issue(0, 0); cp_commit();
    issue(1, 1); cp_commit();

    int s_cur = 0, s_nxt = 2;

    for (int kb = 0; kb < nkb; kb++) {
        cp_wait<1>();
        __syncthreads();
        if (kb + 2 < nkb) issue(kb + 2, s_nxt);
        cp_commit();

        const uint32_t* As = (const uint32_t*)(smg + (size_t)s_cur * BUFSZ);
        const uint32_t* Bs = As + ASZ;

        #pragma unroll
        for (int kk = 0; kk < 4; kk++) {
            uint32_t af[4][4], bf[8][2];
            #pragma unroll
            for (int mt = 0; mt < 4; mt++) {
                const uint32_t* ap =
                    As + (wm * 64 + mt * 16 + gid) * ASTR + kk * 8 + tg;
                af[mt][0] = ap[0];
                af[mt][1] = ap[8 * ASTR];
                af[mt][2] = ap[4];
                af[mt][3] = ap[8 * ASTR + 4];
            }
            #pragma unroll
            for (int nt = 0; nt < 8; nt++) {
                const uint32_t* bp =
                    Bs + (kk * 8 + tg) * BSTR + wn * 64 + nt * 8 + gid;
                bf[nt][0] = bp[0];
                bf[nt][1] = bp[4 * BSTR];
            }
            #pragma unroll
            for (int mt = 0; mt < 4; mt++)
                #pragma unroll
                for (int nt = 0; nt < 8; nt++)
                    mma_tf32(acc[mt][nt], af[mt], bf[nt]);
        }

        s_cur = s_cur + 1 == NS ? 0 : s_cur + 1;
        s_nxt = s_nxt + 1 == NS ? 0 : s_nxt + 1;
    }

    // epilogue
    #pragma unroll
    for (int mt = 0; mt < 4; mt++) {
        #pragma unroll
        for (int half = 0; half < 2; half++) {
            const int row = m0 + wm * 64 + mt * 16 + gid + half * 8;
            float* Cr = C + (size_t)row * Ndim;
            const float* Rr = resid ? resid + (size_t)row * Ndim : nullptr;
            #pragma unroll
            for (int nt = 0; nt < 8; nt++) {
                const int col = n0 + wn * 64 + nt * 8 + 2 * tg;
                float v0 = acc[mt][nt][half * 2 + 0];
                float v1 = acc[mt][nt][half * 2 + 1];
                if (bias)      { v0 += bias[col]; v1 += bias[col + 1]; }
                if (mode == 1) {
                    v0 = tf32_round(gelu_f(v0));
                    v1 = tf32_round(gelu_f(v1));
                }
                if (Rr)        { v0 += Rr[col]; v1 += Rr[col + 1]; }
                float2 o; o.x = v0; o.y = v1;
                *(float2*)(Cr + col) = o;
            }
        }
    }
}

// ---------------------------------------------------------------------------
// Causal flash attention (fp32 SIMT). q,k,v come from the packed qkv buffer
// (row stride 3*DD); out is [M, D] (b,t,h,hd). Output tf32-rounded.
// ---------------------------------------------------------------------------
#define ATILE 64
#define APD 65
#define QSTR (3 * DD)

__global__ __launch_bounds__(256) void attn_kernel(
    const float* __restrict__ qkv, float* __restrict__ out)
{
    extern __shared__ float sm[];
    float* Qs  = sm;
    float* Ks  = Qs + ATILE * APD;
    float* Vs  = Ks + ATILE * APD;
    float* Ss  = Vs + ATILE * APD;
    float* m_s = Ss + ATILE * APD;
    float* l_s = m_s + ATILE;
    float* al_s = l_s + ATILE;

    const int tid = threadIdx.x;
    const int tx = tid & 15;
    const int ty = tid >> 4;
    const int bh = blockIdx.y;
    const int b  = bh / HH;
    const int h  = bh % HH;
    const int qt = blockIdx.x;
    const int q0 = qt * ATILE;

    const size_t qbase = ((size_t)b * TT) * QSTR + (size_t)h * HD;
    const size_t obase = ((size_t)b * TT) * DD + (size_t)h * HD;

    #pragma unroll
    for (int i = 0; i < 16; i++) {
        int idx = tid + i * 256;
        int r = idx >> 6, c = idx & 63;
        Qs[r * APD + c] = qkv[qbase + (size_t)(q0 + r) * QSTR + c];
    }
    if (tid < ATILE) { m_s[tid] = -1e30f; l_s[tid] = 0.f; }

    float acc[4][4];
    #pragma unroll
    for (int i = 0; i < 4; i++)
        #pragma unroll
        for (int j = 0; j < 4; j++) acc[i][j] = 0.f;

    __syncthreads();

    for (int kt = 0; kt <= qt; kt++) {
        const int k0 = kt * ATILE;
        #pragma unroll
        for (int i = 0; i < 16; i++) {
            int idx = tid + i * 256;
            int r = idx >> 6, c = idx & 63;
            Ks[r * APD + c] = qkv[qbase + DD     + (size_t)(k0 + r) * QSTR + c];
            Vs[r * APD + c] = qkv[qbase + 2 * DD + (size_t)(k0 + r) * QSTR + c];
        }
        __syncthreads();

        float s[4][4];
        #pragma unroll
        for (int i = 0; i < 4; i++)
            #pragma unroll
            for (int j = 0; j < 4; j++) s[i][j] = 0.f;
        #pragma unroll 8
        for (int d = 0; d < ATILE; d++) {
            float aq[4], bk[4];
            #pragma unroll
            for (int i = 0; i < 4; i++) aq[i] = Qs[(ty * 4 + i) * APD + d];
            #pragma unroll
            for (int j = 0; j < 4; j++) bk[j] = Ks[(tx * 4 + j) * APD + d];
            #pragma unroll
            for (int i = 0; i < 4; i++)
                #pragma unroll
                for (int j = 0; j < 4; j++)
                    s[i][j] += aq[i] * bk[j];
        }

        const float scale = 0.125f;
        const bool diag = (kt == qt);
        #pragma unroll
        for (int i = 0; i < 4; i++) {
            const int r = ty * 4 + i;
            #pragma unroll
            for (int j = 0; j < 4; j++) {
                const int c = tx * 4 + j;
                float val = s[i][j] * scale;
                if (diag && c > r) val = -1e30f;
                Ss[r * APD + c] = val;
            }
        }
        __syncthreads();

        if (tid < ATILE) {
            const int r = tid;
            float mp = m_s[r];
            float mm = mp;
            #pragma unroll 8
            for (int c = 0; c < ATILE; c++) mm = fmaxf(mm, Ss[r * APD + c]);
            float al = __expf(mp - mm);
            float sum = 0.f;
            #pragma unroll 8
            for (int c = 0; c < ATILE; c++) {
                float p = __expf(Ss[r * APD + c] - mm);
                Ss[r * APD + c] = p;
                sum += p;
            }
            l_s[r] = l_s[r] * al + sum;
            m_s[r] = mm;
            al_s[r] = al;
        }
        __syncthreads();

        #pragma unroll
        for (int i = 0; i < 4; i++) {
            float al = al_s[ty * 4 + i];
            #pragma unroll
            for (int j = 0; j < 4; j++) acc[i][j] *= al;
        }
        #pragma unroll 8
        for (int d = 0; d < ATILE; d++) {
            float p[4], vv[4];
            #pragma unroll
            for (int i = 0; i < 4; i++) p[i] = Ss[(ty * 4 + i) * APD + d];
            #pragma unroll
            for (int j = 0; j < 4; j++) vv[j] = Vs[d * APD + tx * 4 + j];
            #pragma unroll
            for (int i = 0; i < 4; i++)
                #pragma unroll
                for (int j = 0; j < 4; j++)
                    acc[i][j] += p[i] * vv[j];
        }
        __syncthreads();
    }

    #pragma unroll
    for (int i = 0; i < 4; i++) {
        const int r = ty * 4 + i;
        const float invl = 1.0f / l_s[r];
        #pragma unroll
        for (int j = 0; j < 4; j++) {
            const int c = tx * 4 + j;
            out[obase + (size_t)(q0 + r) * DD + c] = tf32_round(acc[i][j] * invl);
        }
    }
}

// ---------------------------------------------------------------------------
// Host launch
// ---------------------------------------------------------------------------
extern "C" void kernel_launch(void* const* d_in, const int* in_sizes, int n_in,
                              void* d_out, int out_size)
{
    const float* x    = (const float*)d_in[0];
    const float* Wq   = (const float*)d_in[1];
    const float* Wk   = (const float*)d_in[2];
    const float* Wv   = (const float*)d_in[3];
    const float* Wo   = (const float*)d_in[4];
    const float* bo   = (const float*)d_in[5];
    const float* W1   = (const float*)d_in[6];
    const float* b1   = (const float*)d_in[7];
    const float* W2   = (const float*)d_in[8];
    const float* b2   = (const float*)d_in[9];
    const float* g1   = (const float*)d_in[10];
    const float* be1  = (const float*)d_in[11];
    const float* g2   = (const float*)d_in[12];
    const float* be2  = (const float*)d_in[13];
    float* out = (float*)d_out;

    float *h, *qkv, *attn, *x2, *h2, *ff1;
    float *wqkv, *wo, *w1, *w2;
    cudaGetSymbolAddress((void**)&h,    g_h);
    cudaGetSymbolAddress((void**)&qkv,  g_qkv);
    cudaGetSymbolAddress((void**)&attn, g_attn);
    cudaGetSymbolAddress((void**)&x2,   g_x2);
    cudaGetSymbolAddress((void**)&h2,   g_h2);
    cudaGetSymbolAddress((void**)&ff1,  g_ff1);
    cudaGetSymbolAddress((void**)&wqkv, g_wqkv);
    cudaGetSymbolAddress((void**)&wo,   g_wo);
    cudaGetSymbolAddress((void**)&w1,   g_w1);
    cudaGetSymbolAddress((void**)&w2,   g_w2);

    const int ATTN_SMEM = (4 * ATILE * APD + 3 * ATILE) * (int)sizeof(float);
    cudaFuncSetAttribute(attn_kernel,
                         cudaFuncAttributeMaxDynamicSharedMemorySize, ATTN_SMEM);
    cudaFuncSetAttribute(gemm_mma,
                         cudaFuncAttributeMaxDynamicSharedMemorySize, GEMM_SMEM);

    // 0) weight preprocessing: tf32 rounding (+ QKV pack)
    pack_qkv_kernel<<<dim3(1024, 3), 256>>>(Wq, Wk, Wv, wqkv);
    cvt_tf32_kernel<<<1024, 256>>>(Wo, wo);
    cvt_tf32_kernel<<<4096, 256>>>(W1, w1);
    cvt_tf32_kernel<<<4096, 256>>>(W2, w2);

    // 1) LN1 (tf32-rounded output)
    layernorm_kernel<<<MM, 256>>>(x, g1, be1, h);

    // 2) fused QKV projection
    gemm_mma<<<dim3(3 * DD / 256, MM / 128), 256, GEMM_SMEM>>>(
        h, wqkv, nullptr, nullptr, qkv, 3 * DD, DD, 0);

    // 3) causal attention (tf32-rounded output)
    attn_kernel<<<dim3(TT / ATILE, BB * HH), 256, ATTN_SMEM>>>(qkv, attn);

    // 4) output projection + bias + residual(x)
    dim3 gDD(DD / 256, MM / 128);
    gemm_mma<<<gDD, 256, GEMM_SMEM>>>(attn, wo, bo, x, x2, DD, DD, 0);

    // 5) LN2 (tf32-rounded output)
    layernorm_kernel<<<MM, 256>>>(x2, g2, be2, h2);

    // 6) FFN1 + bias + GELU (tf32-rounded output)
    gemm_mma<<<dim3(FF / 256, MM / 128), 256, GEMM_SMEM>>>(
        h2, w1, b1, nullptr, ff1, FF, DD, 1);

    // 7) FFN2 + bias + residual(x2) -> out
    gemm_mma<<<gDD, 256, GEMM_SMEM>>>(ff1, w2, b2, x2, out, DD, FF, 2);
}

// round 7
// speedup vs baseline: 3.6941x; 1.4720x over previous
#include <cuda_runtime.h>
#include <cuda_bf16.h>
#include <math.h>
#include <stdint.h>

// ---------------------------------------------------------------------------
// Problem constants
// ---------------------------------------------------------------------------
#define BB 4
#define TT 2048
#define DD 1024
#define HH 16
#define HD 64
#define FF 4096
#define MM (BB * TT)       // 8192 rows
#define EPS 1e-5f

// ---------------------------------------------------------------------------
// Scratch (allocation-free: __device__ globals)
// ---------------------------------------------------------------------------
__device__ float g_h   [(size_t)MM * DD];
__device__ float g_qkv [(size_t)MM * 3 * DD];
__device__ float g_attn[(size_t)MM * DD];
__device__ float g_x2  [(size_t)MM * DD];
__device__ float g_h2  [(size_t)MM * DD];
__device__ float g_ff1 [(size_t)MM * FF];
// tf32-rounded weights
__device__ float g_wqkv[(size_t)DD * 3 * DD];
__device__ float g_wo  [(size_t)DD * DD];
__device__ float g_w1  [(size_t)DD * FF];
__device__ float g_w2  [(size_t)FF * DD];

// ---------------------------------------------------------------------------
// tf32 helpers
// ---------------------------------------------------------------------------
__device__ __forceinline__ uint32_t tf32_cvt(float f) {
    uint32_t r;
    asm("cvt.rna.tf32.f32 %0, %1;" : "=r"(r) : "f"(f));
    return r;
}
__device__ __forceinline__ float tf32_round(float f) {
    return __uint_as_float(tf32_cvt(f));
}
__device__ __forceinline__ void mma_tf32(float c[4], const uint32_t a[4],
                                         const uint32_t b[2]) {
    asm volatile(
        "mma.sync.aligned.m16n8k8.row.col.f32.tf32.tf32.f32 "
        "{%0,%1,%2,%3}, {%4,%5,%6,%7}, {%8,%9}, {%0,%1,%2,%3};"
        : "+f"(c[0]), "+f"(c[1]), "+f"(c[2]), "+f"(c[3])
        : "r"(a[0]), "r"(a[1]), "r"(a[2]), "r"(a[3]), "r"(b[0]), "r"(b[1]));
}
__device__ __forceinline__ void cp_async16(uint32_t saddr, const void* gptr) {
    asm volatile("cp.async.cg.shared.global [%0], [%1], 16;"
                 :: "r"(saddr), "l"(gptr) : "memory");
}
__device__ __forceinline__ void cp_commit() {
    asm volatile("cp.async.commit_group;" ::: "memory");
}
template <int N>
__device__ __forceinline__ void cp_wait() {
    asm volatile("cp.async.wait_group %0;" :: "n"(N) : "memory");
}
__device__ __forceinline__ uint32_t smem_u32(const void* p) {
    uint32_t a;
    asm("{ .reg .u64 t; cvta.to.shared.u64 t, %1; cvt.u32.u64 %0, t; }"
        : "=r"(a) : "l"(p));
    return a;
}

// ---------------------------------------------------------------------------
// Weight preprocessing: tf32-round (and pack QKV)
// ---------------------------------------------------------------------------
__global__ __launch_bounds__(256) void cvt_tf32_kernel(
    const float* __restrict__ in, float* __restrict__ out)
{
    const size_t i = ((size_t)blockIdx.x * 256 + threadIdx.x) * 4;
    float4 v = *(const float4*)(in + i);
    v.x = tf32_round(v.x); v.y = tf32_round(v.y);
    v.z = tf32_round(v.z); v.w = tf32_round(v.w);
    *(float4*)(out + i) = v;
}

__global__ __launch_bounds__(256) void pack_qkv_kernel(
    const float* __restrict__ Wq, const float* __restrict__ Wk,
    const float* __restrict__ Wv, float* __restrict__ out)
{
    const int sel = blockIdx.y;
    const float* src = sel == 0 ? Wq : (sel == 1 ? Wk : Wv);
    const size_t i = ((size_t)blockIdx.x * 256 + threadIdx.x) * 4;
    const int r = (int)(i >> 10);          // /1024
    const int c = (int)(i & 1023);
    float4 v = *(const float4*)(src + i);
    v.x = tf32_round(v.x); v.y = tf32_round(v.y);
    v.z = tf32_round(v.z); v.w = tf32_round(v.w);
    *(float4*)(out + (size_t)r * (3 * DD) + sel * DD + c) = v;
}

// ---------------------------------------------------------------------------
// LayerNorm: one block (256 threads) per row of 1024; tf32-rounds the output
// ---------------------------------------------------------------------------
__global__ __launch_bounds__(256) void layernorm_kernel(
    const float* __restrict__ x, const float* __restrict__ gamma,
    const float* __restrict__ beta, float* __restrict__ out)
{
    __shared__ float shs[8], shss[8];
    __shared__ float s_mean, s_inv;
    const int row = blockIdx.x;
    const int tid = threadIdx.x;

    const float4 xv = *(const float4*)(x + (size_t)row * DD + tid * 4);
    float s  = xv.x + xv.y + xv.z + xv.w;
    float ss = xv.x * xv.x + xv.y * xv.y + xv.z * xv.z + xv.w * xv.w;
    #pragma unroll
    for (int o = 16; o > 0; o >>= 1) {
        s  += __shfl_down_sync(0xffffffffu, s, o);
        ss += __shfl_down_sync(0xffffffffu, ss, o);
    }
    if ((tid & 31) == 0) { shs[tid >> 5] = s; shss[tid >> 5] = ss; }
    __syncthreads();
    if (tid == 0) {
        float S = 0.f, SS = 0.f;
        #pragma unroll
        for (int i = 0; i < 8; i++) { S += shs[i]; SS += shss[i]; }
        float mean = S * (1.0f / DD);
        float var  = SS * (1.0f / DD) - mean * mean;
        s_mean = mean;
        s_inv  = rsqrtf(var + EPS);
    }
    __syncthreads();
    const float mean = s_mean, inv = s_inv;
    const float4 gv = *(const float4*)(gamma + tid * 4);
    const float4 bv = *(const float4*)(beta  + tid * 4);
    float4 o;
    o.x = tf32_round(gv.x * (xv.x - mean) * inv + bv.x);
    o.y = tf32_round(gv.y * (xv.y - mean) * inv + bv.y);
    o.z = tf32_round(gv.z * (xv.z - mean) * inv + bv.z);
    o.w = tf32_round(gv.w * (xv.w - mean) * inv + bv.w);
    *(float4*)(out + (size_t)row * DD + tid * 4) = o;
}

// ---------------------------------------------------------------------------
// GELU (tanh approximation, matches reference)
// ---------------------------------------------------------------------------
__device__ __forceinline__ float gelu_f(float x)
{
    const float c = 0.7978845608028654f;  // sqrt(2/pi)
    float inner = c * (x + 0.044715f * x * x * x);
    return 0.5f * x * (1.0f + tanhf(inner));
}

// ---------------------------------------------------------------------------
// tf32 tensor-core GEMM:  C[M,N] = A[M,K] @ B[K,N]  (+bias)(+gelu)(+residual)
// Inputs pre-rounded to tf32. CTA tile 128x256, BK=32, 256 threads, 8 warps
// (2x4), warp tile 64x64. cp.async 3-stage pipeline.
// mode: 0 = plain, 1 = gelu + tf32-round (FFN1)
// ---------------------------------------------------------------------------
#define ASTR 36
#define BSTR 264
#define ASZ (128 * ASTR)            // 4608 floats
#define BSZ (32 * BSTR)             // 8448 floats
#define BUFSZ (ASZ + BSZ)           // 13056 floats
#define NS 3
#define STAGE_BYTES (BUFSZ * 4)     // 52224 bytes
#define GEMM_SMEM (NS * STAGE_BYTES)  // 156672 bytes

__global__ __launch_bounds__(256, 1) void gemm_mma(
    const float* __restrict__ A, const float* __restrict__ B,
    const float* __restrict__ bias,   // may be null
    const float* __restrict__ resid,  // may be null
    float* __restrict__ C,
    int Ndim, int Kdim, int mode)
{
    extern __shared__ __align__(16) float smg[];
    const uint32_t sbase = smem_u32(smg);
    const int tid  = threadIdx.x;
    const int lane = tid & 31;
    const int warp = tid >> 5;
    const int wm   = warp >> 2;     // 0..1
    const int wn   = warp & 3;      // 0..3
    const int gid  = lane >> 2;     // 0..7
    const int tg   = lane & 3;      // 0..3
    const int m0 = blockIdx.y * 128;
    const int n0 = blockIdx.x * 256;

    const int rA = tid >> 3;             // 0..31
    const int cA = (tid & 7) * 4;        // 0,4,..,28
    const int rB = tid >> 6;             // 0..3
    const int cB = (tid & 63) * 4;       // 0..252

    const uint32_t sAoff = (uint32_t)(rA * ASTR + cA) * 4;
    const uint32_t sBoff = (uint32_t)(ASZ + rB * BSTR + cB) * 4;

    float acc[4][8][4];
    #pragma unroll
    for (int mt = 0; mt < 4; mt++)
        #pragma unroll
        for (int nt = 0; nt < 8; nt++)
            #pragma unroll
            for (int r = 0; r < 4; r++) acc[mt][nt][r] = 0.f;

    const int nkb = Kdim / 32;

    auto issue = [&](int kb, int slot) {
        const uint32_t sb = sbase + slot * STAGE_BYTES;
        const float* Ag = A + (size_t)(m0 + rA) * Kdim + kb * 32 + cA;
        #pragma unroll
        for (int p = 0; p < 4; p++)
            cp_async16(sb + sAoff + p * (32 * ASTR * 4), Ag + (size_t)p * 32 * Kdim);
        const float* Bg = B + (size_t)(kb * 32 + rB) * Ndim + n0 + cB;
        #pragma unroll
        for (int p = 0; p < 8; p++)
            cp_async16(sb + sBoff + p * (4 * BSTR * 4), Bg + (size_t)p * 4 * Ndim);
    };

    issue(0, 0); cp_commit();
    issue(1, 1); cp_commit();

    int s_cur = 0, s_nxt = 2;

    for (int kb = 0; kb < nkb; kb++) {
        cp_wait<1>();
        __syncthreads();
        if (kb + 2 < nkb) issue(kb + 2, s_nxt);
        cp_commit();

        const uint32_t* As = (const uint32_t*)(smg + (size_t)s_cur * BUFSZ);
        const uint32_t* Bs = As + ASZ;

        #pragma unroll
        for (int kk = 0; kk < 4; kk++) {
            uint32_t af[4][4], bf[8][2];
            #pragma unroll
            for (int mt = 0; mt < 4; mt++) {
                const uint32_t* ap =
                    As + (wm * 64 + mt * 16 + gid) * ASTR + kk * 8 + tg;
                af[mt][0] = ap[0];
                af[mt][1] = ap[8 * ASTR];
                af[mt][2] = ap[4];
                af[mt][3] = ap[8 * ASTR + 4];
            }
            #pragma unroll
            for (int nt = 0; nt < 8; nt++) {
                const uint32_t* bp =
                    Bs + (kk * 8 + tg) * BSTR + wn * 64 + nt * 8 + gid;
                bf[nt][0] = bp[0];
                bf[nt][1] = bp[4 * BSTR];
            }
            #pragma unroll
            for (int mt = 0; mt < 4; mt++)
                #pragma unroll
                for (int nt = 0; nt < 8; nt++)
                    mma_tf32(acc[mt][nt], af[mt], bf[nt]);
        }

        s_cur = s_cur + 1 == NS ? 0 : s_cur + 1;
        s_nxt = s_nxt + 1 == NS ? 0 : s_nxt + 1;
    }

    #pragma unroll
    for (int mt = 0; mt < 4; mt++) {
        #pragma unroll
        for (int half = 0; half < 2; half++) {
            const int row = m0 + wm * 64 + mt * 16 + gid + half * 8;
            float* Cr = C + (size_t)row * Ndim;
            const float* Rr = resid ? resid + (size_t)row * Ndim : nullptr;
            #pragma unroll
            for (int nt = 0; nt < 8; nt++) {
                const int col = n0 + wn * 64 + nt * 8 + 2 * tg;
                float v0 = acc[mt][nt][half * 2 + 0];
                float v1 = acc[mt][nt][half * 2 + 1];
                if (bias)      { v0 += bias[col]; v1 += bias[col + 1]; }
                if (mode == 1) {
                    v0 = tf32_round(gelu_f(v0));
                    v1 = tf32_round(gelu_f(v1));
                }
                if (Rr)        { v0 += Rr[col]; v1 += Rr[col + 1]; }
                float2 o; o.x = v0; o.y = v1;
                *(float2*)(Cr + col) = o;
            }
        }
    }
}

// ---------------------------------------------------------------------------
// Tensor-core causal flash attention (tf32 MMA, fp32 accum/softmax).
// q,k,v from packed qkv buffer (row stride 3*DD); out [M, D] (b,t,h,hd),
// tf32-rounded. 64x64 tiles, 128 threads / 4 warps; warp owns 16 q-rows.
// Online softmax in registers (rows live in 4 lanes -> shfl.bfly reduce).
// ---------------------------------------------------------------------------
#define QSTR (3 * DD)
#define AP2 68
#define ATTN_SMEM_MMA (4 * 64 * AP2 * 4)   // Qs,Ks,Vs,Ps = 69632 B

__global__ __launch_bounds__(128) void attn_mma(
    const float* __restrict__ qkv, float* __restrict__ out)
{
    extern __shared__ __align__(16) float sm[];
    float* Qs = sm;                 // 64 x 68
    float* Ks = Qs + 64 * AP2;
    float* Vs = Ks + 64 * AP2;
    float* Ps = Vs + 64 * AP2;

    const int tid  = threadIdx.x;
    const int lane = tid & 31;
    const int warp = tid >> 5;      // 0..3 -> q rows 16*warp..16*warp+15
    const int gid  = lane >> 2;     // 0..7
    const int tg   = lane & 3;      // 0..3
    const int bh = blockIdx.y;
    const int b  = bh / HH;
    const int h  = bh % HH;
    const int qt = blockIdx.x;
    const int q0 = qt * 64;

    const size_t qbase = ((size_t)b * TT) * QSTR + (size_t)h * HD;
    const size_t obase = ((size_t)b * TT) * DD + (size_t)h * HD;

    // load Q tile (64x64), tf32-rounded
    #pragma unroll
    for (int i = 0; i < 8; i++) {
        int j = tid + 128 * i;
        int r = j >> 4, c4 = (j & 15) * 4;
        float4 v = *(const float4*)(qkv + qbase + (size_t)(q0 + r) * QSTR + c4);
        v.x = tf32_round(v.x); v.y = tf32_round(v.y);
        v.z = tf32_round(v.z); v.w = tf32_round(v.w);
        *(float4*)(Qs + r * AP2 + c4) = v;
    }

    // online softmax state: two rows per thread (gid, gid+8 within warp tile)
    float mrow[2] = {-1e30f, -1e30f};
    float lrow[2] = {0.f, 0.f};
    float o[8][4];
    #pragma unroll
    for (int nf = 0; nf < 8; nf++)
        #pragma unroll
        for (int c = 0; c < 4; c++) o[nf][c] = 0.f;

    for (int kt = 0; kt <= qt; kt++) {
        const int k0 = kt * 64;
        // load K,V tiles to registers
        float4 kv[8], vv[8];
        #pragma unroll
        for (int i = 0; i < 8; i++) {
            int j = tid + 128 * i;
            int r = j >> 4, c4 = (j & 15) * 4;
            kv[i] = *(const float4*)(qkv + qbase + DD     + (size_t)(k0 + r) * QSTR + c4);
            vv[i] = *(const float4*)(qkv + qbase + 2 * DD + (size_t)(k0 + r) * QSTR + c4);
        }
        __syncthreads();   // everyone done with previous Ks/Vs/Ps
        #pragma unroll
        for (int i = 0; i < 8; i++) {
            int j = tid + 128 * i;
            int r = j >> 4, c4 = (j & 15) * 4;
            float4 a = kv[i];
            a.x = tf32_round(a.x); a.y = tf32_round(a.y);
            a.z = tf32_round(a.z); a.w = tf32_round(a.w);
            *(float4*)(Ks + r * AP2 + c4) = a;
            float4 bvv = vv[i];
            bvv.x = tf32_round(bvv.x); bvv.y = tf32_round(bvv.y);
            bvv.z = tf32_round(bvv.z); bvv.w = tf32_round(bvv.w);
            *(float4*)(Vs + r * AP2 + c4) = bvv;
        }
        __syncthreads();

        // S = Q K^T (warp: 16x64). s[nf][c]
        float s[8][4];
        #pragma unroll
        for (int nf = 0; nf < 8; nf++)
            #pragma unroll
            for (int c = 0; c < 4; c++) s[nf][c] = 0.f;
        #pragma unroll
        for (int ks = 0; ks < 8; ks++) {
            uint32_t af[4];
            const uint32_t* qp =
                (const uint32_t*)Qs + (warp * 16 + gid) * AP2 + ks * 8 + tg;
            af[0] = qp[0];
            af[1] = qp[8 * AP2];
            af[2] = qp[4];
            af[3] = qp[8 * AP2 + 4];
            #pragma unroll
            for (int nf = 0; nf < 8; nf++) {
                uint32_t bfk[2];
                const uint32_t* kp =
                    (const uint32_t*)Ks + (nf * 8 + gid) * AP2 + ks * 8 + tg;
                // b-frag (col-major B = K^T): b0 = K[n][k], b1 = K[n][k+4]
                bfk[0] = kp[0];
                bfk[1] = kp[4];
                mma_tf32(s[nf], af, bfk);
            }
        }

        // scale + causal mask
        const float scale = 0.125f;
        const bool diag = (kt == qt);
        #pragma unroll
        for (int nf = 0; nf < 8; nf++) {
            #pragma unroll
            for (int c = 0; c < 4; c++) {
                float val = s[nf][c] * scale;
                if (diag) {
                    int row = warp * 16 + gid + (c >= 2 ? 8 : 0);
                    int col = nf * 8 + 2 * tg + (c & 1);
                    if (col > row) val = -1e30f;
                }
                s[nf][c] = val;
            }
        }

        // row max (rows: [0]=gid, [1]=gid+8) via in-thread + shfl over tg lanes
        float mx0 = -1e30f, mx1 = -1e30f;
        #pragma unroll
        for (int nf = 0; nf < 8; nf++) {
            mx0 = fmaxf(mx0, fmaxf(s[nf][0], s[nf][1]));
            mx1 = fmaxf(mx1, fmaxf(s[nf][2], s[nf][3]));
        }
        #pragma unroll
        for (int w = 1; w <= 2; w <<= 1) {
            mx0 = fmaxf(mx0, __shfl_xor_sync(0xffffffffu, mx0, w));
            mx1 = fmaxf(mx1, __shfl_xor_sync(0xffffffffu, mx1, w));
        }
        float mn0 = fmaxf(mrow[0], mx0);
        float mn1 = fmaxf(mrow[1], mx1);
        float al0 = __expf(mrow[0] - mn0);
        float al1 = __expf(mrow[1] - mn1);

        // p = exp(s - m), row sums
        float sum0 = 0.f, sum1 = 0.f;
        #pragma unroll
        for (int nf = 0; nf < 8; nf++) {
            s[nf][0] = __expf(s[nf][0] - mn0);
            s[nf][1] = __expf(s[nf][1] - mn0);
            s[nf][2] = __expf(s[nf][2] - mn1);
            s[nf][3] = __expf(s[nf][3] - mn1);
            sum0 += s[nf][0] + s[nf][1];
            sum1 += s[nf][2] + s[nf][3];
        }
        #pragma unroll
        for (int w = 1; w <= 2; w <<= 1) {
            sum0 += __shfl_xor_sync(0xffffffffu, sum0, w);
            sum1 += __shfl_xor_sync(0xffffffffu, sum1, w);
        }
        lrow[0] = lrow[0] * al0 + sum0;
        lrow[1] = lrow[1] * al1 + sum1;
        mrow[0] = mn0;
        mrow[1] = mn1;

        // store P (tf32) to smem
        #pragma unroll
        for (int nf = 0; nf < 8; nf++) {
            float2 p0, p1;
            p0.x = tf32_round(s[nf][0]); p0.y = tf32_round(s[nf][1]);
            p1.x = tf32_round(s[nf][2]); p1.y = tf32_round(s[nf][3]);
            *(float2*)(Ps + (warp * 16 + gid)     * AP2 + nf * 8 + 2 * tg) = p0;
            *(float2*)(Ps + (warp * 16 + gid + 8) * AP2 + nf * 8 + 2 * tg) = p1;
        }
        // rescale accumulator
        #pragma unroll
        for (int nf = 0; nf < 8; nf++) {
            o[nf][0] *= al0; o[nf][1] *= al0;
            o[nf][2] *= al1; o[nf][3] *= al1;
        }
        __syncthreads();   // Ps visible

        // O += P V  (warp: 16x64; k-dim = key)
        #pragma unroll
        for (int ks = 0; ks < 8; ks++) {
            uint32_t af[4];
            const uint32_t* pp =
                (const uint32_t*)Ps + (warp * 16 + gid) * AP2 + ks * 8 + tg;
            af[0] = pp[0];
            af[1] = pp[8 * AP2];
            af[2] = pp[4];
            af[3] = pp[8 * AP2 + 4];
            #pragma unroll
            for (int nf = 0; nf < 8; nf++) {
                uint32_t bfv[2];
                const uint32_t* vp =
                    (const uint32_t*)Vs + (ks * 8 + tg) * AP2 + nf * 8 + gid;
                bfv[0] = vp[0];
                bfv[1] = vp[4 * AP2];
                mma_tf32(o[nf], af, bfv);
            }
        }
        // next iteration's __syncthreads (before K/V store) protects Vs/Ps
    }

    // write normalized output (tf32-rounded, feeds Wo GEMM)
    const float inv0 = 1.0f / lrow[0];
    const float inv1 = 1.0f / lrow[1];
    const int r0 = q0 + warp * 16 + gid;
    #pragma unroll
    for (int nf = 0; nf < 8; nf++) {
        const int col = nf * 8 + 2 * tg;
        float2 w0, w1;
        w0.x = tf32_round(o[nf][0] * inv0); w0.y = tf32_round(o[nf][1] * inv0);
        w1.x = tf32_round(o[nf][2] * inv1); w1.y = tf32_round(o[nf][3] * inv1);
        *(float2*)(out + obase + (size_t)r0 * DD + col)       = w0;
        *(float2*)(out + obase + (size_t)(r0 + 8) * DD + col) = w1;
    }
}

// ---------------------------------------------------------------------------
// Host launch
// ---------------------------------------------------------------------------
extern "C" void kernel_launch(void* const* d_in, const int* in_sizes, int n_in,
                              void* d_out, int out_size)
{
    const float* x    = (const float*)d_in[0];
    const float* Wq   = (const float*)d_in[1];
    const float* Wk   = (const float*)d_in[2];
    const float* Wv   = (const float*)d_in[3];
    const float* Wo   = (const float*)d_in[4];
    const float* bo   = (const float*)d_in[5];
    const float* W1   = (const float*)d_in[6];
    const float* b1   = (const float*)d_in[7];
    const float* W2   = (const float*)d_in[8];
    const float* b2   = (const float*)d_in[9];
    const float* g1   = (const float*)d_in[10];
    const float* be1  = (const float*)d_in[11];
    const float* g2   = (const float*)d_in[12];
    const float* be2  = (const float*)d_in[13];
    float* out = (float*)d_out;

    float *h, *qkv, *attn, *x2, *h2, *ff1;
    float *wqkv, *wo, *w1, *w2;
    cudaGetSymbolAddress((void**)&h,    g_h);
    cudaGetSymbolAddress((void**)&qkv,  g_qkv);
    cudaGetSymbolAddress((void**)&attn, g_attn);
    cudaGetSymbolAddress((void**)&x2,   g_x2);
    cudaGetSymbolAddress((void**)&h2,   g_h2);
    cudaGetSymbolAddress((void**)&ff1,  g_ff1);
    cudaGetSymbolAddress((void**)&wqkv, g_wqkv);
    cudaGetSymbolAddress((void**)&wo,   g_wo);
    cudaGetSymbolAddress((void**)&w1,   g_w1);
    cudaGetSymbolAddress((void**)&w2,   g_w2);

    cudaFuncSetAttribute(attn_mma,
                         cudaFuncAttributeMaxDynamicSharedMemorySize, ATTN_SMEM_MMA);
    cudaFuncSetAttribute(gemm_mma,
                         cudaFuncAttributeMaxDynamicSharedMemorySize, GEMM_SMEM);

    // 0) weight preprocessing: tf32 rounding (+ QKV pack)
    pack_qkv_kernel<<<dim3(1024, 3), 256>>>(Wq, Wk, Wv, wqkv);
    cvt_tf32_kernel<<<1024, 256>>>(Wo, wo);
    cvt_tf32_kernel<<<4096, 256>>>(W1, w1);
    cvt_tf32_kernel<<<4096, 256>>>(W2, w2);

    // 1) LN1 (tf32-rounded output)
    layernorm_kernel<<<MM, 256>>>(x, g1, be1, h);

    // 2) fused QKV projection
    gemm_mma<<<dim3(3 * DD / 256, MM / 128), 256, GEMM_SMEM>>>(
        h, wqkv, nullptr, nullptr, qkv, 3 * DD, DD, 0);

    // 3) causal attention (tensor cores, tf32-rounded output)
    attn_mma<<<dim3(TT / 64, BB * HH), 128, ATTN_SMEM_MMA>>>(qkv, attn);

    // 4) output projection + bias + residual(x)
    dim3 gDD(DD / 256, MM / 128);
    gemm_mma<<<gDD, 256, GEMM_SMEM>>>(attn, wo, bo, x, x2, DD, DD, 0);

    // 5) LN2 (tf32-rounded output)
    layernorm_kernel<<<MM, 256>>>(x2, g2, be2, h2);

    // 6) FFN1 + bias + GELU (tf32-rounded output)
    gemm_mma<<<dim3(FF / 256, MM / 128), 256, GEMM_SMEM>>>(
        h2, w1, b1, nullptr, ff1, FF, DD, 1);

    // 7) FFN2 + bias + residual(x2) -> out
    gemm_mma<<<gDD, 256, GEMM_SMEM>>>(ff1, w2, b2, x2, out, DD, FF, 2);
}

// round 8
// speedup vs baseline: 4.9078x; 1.3286x over previous
#include <cuda_runtime.h>
#include <cuda_fp16.h>
#include <math.h>
#include <stdint.h>

// ---------------------------------------------------------------------------
// Problem constants
// ---------------------------------------------------------------------------
#define BB 4
#define TT 2048
#define DD 1024
#define HH 16
#define HD 64
#define FF 4096
#define MM (BB * TT)       // 8192 rows
#define EPS 1e-5f

// ---------------------------------------------------------------------------
// Scratch (allocation-free: __device__ globals)
// ---------------------------------------------------------------------------
__device__ __half g_h   [(size_t)MM * DD];      // LN1 out (fp16)
__device__ float  g_qkv [(size_t)MM * 3 * DD];  // QKV out (fp32)
__device__ __half g_attn[(size_t)MM * DD];      // attention out (fp16)
__device__ float  g_x2  [(size_t)MM * DD];      // residual stream 2 (fp32)
__device__ __half g_h2  [(size_t)MM * DD];      // LN2 out (fp16)
__device__ __half g_ff1 [(size_t)MM * FF];      // FFN1 out (fp16)
// fp16 weights, transposed to [N][K]
__device__ __half g_wqkv[(size_t)(3 * DD) * DD];
__device__ __half g_wo  [(size_t)DD * DD];
__device__ __half g_w1  [(size_t)FF * DD];
__device__ __half g_w2  [(size_t)DD * FF];

// ---------------------------------------------------------------------------
// helpers
// ---------------------------------------------------------------------------
__device__ __forceinline__ uint32_t tf32_cvt(float f) {
    uint32_t r;
    asm("cvt.rna.tf32.f32 %0, %1;" : "=r"(r) : "f"(f));
    return r;
}
__device__ __forceinline__ float tf32_round(float f) {
    return __uint_as_float(tf32_cvt(f));
}
__device__ __forceinline__ void mma_tf32(float c[4], const uint32_t a[4],
                                         const uint32_t b[2]) {
    asm volatile(
        "mma.sync.aligned.m16n8k8.row.col.f32.tf32.tf32.f32 "
        "{%0,%1,%2,%3}, {%4,%5,%6,%7}, {%8,%9}, {%0,%1,%2,%3};"
        : "+f"(c[0]), "+f"(c[1]), "+f"(c[2]), "+f"(c[3])
        : "r"(a[0]), "r"(a[1]), "r"(a[2]), "r"(a[3]), "r"(b[0]), "r"(b[1]));
}
__device__ __forceinline__ void mma_f16(float c[4], const uint32_t a[4],
                                        const uint32_t b[2]) {
    asm volatile(
        "mma.sync.aligned.m16n8k16.row.col.f32.f16.f16.f32 "
        "{%0,%1,%2,%3}, {%4,%5,%6,%7}, {%8,%9}, {%0,%1,%2,%3};"
        : "+f"(c[0]), "+f"(c[1]), "+f"(c[2]), "+f"(c[3])
        : "r"(a[0]), "r"(a[1]), "r"(a[2]), "r"(a[3]), "r"(b[0]), "r"(b[1]));
}
__device__ __forceinline__ void cp_async16(uint32_t saddr, const void* gptr) {
    asm volatile("cp.async.cg.shared.global [%0], [%1], 16;"
                 :: "r"(saddr), "l"(gptr) : "memory");
}
__device__ __forceinline__ void cp_commit() {
    asm volatile("cp.async.commit_group;" ::: "memory");
}
template <int N>
__device__ __forceinline__ void cp_wait() {
    asm volatile("cp.async.wait_group %0;" :: "n"(N) : "memory");
}
__device__ __forceinline__ uint32_t smem_u32(const void* p) {
    uint32_t a;
    asm("{ .reg .u64 t; cvta.to.shared.u64 t, %1; cvt.u32.u64 %0, t; }"
        : "=r"(a) : "l"(p));
    return a;
}

// ---------------------------------------------------------------------------
// Weight preprocessing: transpose [R][C] fp32 -> [C][R] fp16
// ---------------------------------------------------------------------------
__global__ __launch_bounds__(256) void transpose_h_kernel(
    const float* __restrict__ in, __half* __restrict__ out, int R, int C)
{
    __shared__ float t[32][33];
    const int c0 = blockIdx.x * 32;
    const int r0 = blockIdx.y * 32;
    const int tx = threadIdx.x, ty = threadIdx.y;
    #pragma unroll
    for (int i = 0; i < 32; i += 8)
        t[ty + i][tx] = in[(size_t)(r0 + ty + i) * C + c0 + tx];
    __syncthreads();
    #pragma unroll
    for (int i = 0; i < 32; i += 8)
        out[(size_t)(c0 + ty + i) * R + r0 + tx] = __float2half_rn(t[tx][ty + i]);
}

// ---------------------------------------------------------------------------
// LayerNorm: one block (256 threads) per row of 1024; writes fp16
// ---------------------------------------------------------------------------
__global__ __launch_bounds__(256) void layernorm_kernel(
    const float* __restrict__ x, const float* __restrict__ gamma,
    const float* __restrict__ beta, __half* __restrict__ out)
{
    __shared__ float shs[8], shss[8];
    __shared__ float s_mean, s_inv;
    const int row = blockIdx.x;
    const int tid = threadIdx.x;

    const float4 xv = *(const float4*)(x + (size_t)row * DD + tid * 4);
    float s  = xv.x + xv.y + xv.z + xv.w;
    float ss = xv.x * xv.x + xv.y * xv.y + xv.z * xv.z + xv.w * xv.w;
    #pragma unroll
    for (int o = 16; o > 0; o >>= 1) {
        s  += __shfl_down_sync(0xffffffffu, s, o);
        ss += __shfl_down_sync(0xffffffffu, ss, o);
    }
    if ((tid & 31) == 0) { shs[tid >> 5] = s; shss[tid >> 5] = ss; }
    __syncthreads();
    if (tid == 0) {
        float S = 0.f, SS = 0.f;
        #pragma unroll
        for (int i = 0; i < 8; i++) { S += shs[i]; SS += shss[i]; }
        float mean = S * (1.0f / DD);
        float var  = SS * (1.0f / DD) - mean * mean;
        s_mean = mean;
        s_inv  = rsqrtf(var + EPS);
    }
    __syncthreads();
    const float mean = s_mean, inv = s_inv;
    const float4 gv = *(const float4*)(gamma + tid * 4);
    const float4 bv = *(const float4*)(beta  + tid * 4);
    __half2 o01 = __floats2half2_rn(gv.x * (xv.x - mean) * inv + bv.x,
                                    gv.y * (xv.y - mean) * inv + bv.y);
    __half2 o23 = __floats2half2_rn(gv.z * (xv.z - mean) * inv + bv.z,
                                    gv.w * (xv.w - mean) * inv + bv.w);
    *(__half2*)(out + (size_t)row * DD + tid * 4)     = o01;
    *(__half2*)(out + (size_t)row * DD + tid * 4 + 2) = o23;
}

// ---------------------------------------------------------------------------
// GELU (tanh approximation, matches reference)
// ---------------------------------------------------------------------------
__device__ __forceinline__ float gelu_f(float x)
{
    const float c = 0.7978845608028654f;  // sqrt(2/pi)
    float inner = c * (x + 0.044715f * x * x * x);
    return 0.5f * x * (1.0f + tanhf(inner));
}

// ---------------------------------------------------------------------------
// fp16 tensor-core GEMM:  C[M,N] = A[M,K] @ Bt[N,K]^T  (+bias)(+gelu)(+resid)
// A, Bt fp16; fp32 accumulate. CTA tile 128x256, BK=32, 256 threads, 8 warps
// (2x4), warp tile 64x64, m16n8k16. cp.async 4-stage pipeline.
// smem rows padded to 40 halves (20 words; conflict-free fragment LDS).
// mode: 0 = fp32 out plain, 1 = fp16 out bias+gelu, 2 = fp32 out bias+resid
// ---------------------------------------------------------------------------
#define PADW 20                     // 32-bit words per smem row
#define A_BYTES (128 * 80)          // 10240
#define B_BYTES (256 * 80)          // 20480
#define STG (A_BYTES + B_BYTES)     // 30720
#define NSF 4
#define GEMM_SMEM (NSF * STG)       // 122880

__global__ __launch_bounds__(256, 1) void gemm_h(
    const __half* __restrict__ A, const __half* __restrict__ Bt,
    const float* __restrict__ bias,   // may be null
    const float* __restrict__ resid,  // may be null
    void* __restrict__ Cout,
    int Ndim, int Kdim, int mode)
{
    extern __shared__ __align__(16) char smg[];
    const uint32_t sbase = smem_u32(smg);
    const int tid  = threadIdx.x;
    const int lane = tid & 31;
    const int warp = tid >> 5;
    const int wm   = warp >> 2;     // 0..1
    const int wn   = warp & 3;      // 0..3
    const int gid  = lane >> 2;     // 0..7
    const int tg   = lane & 3;      // 0..3
    const int m0 = blockIdx.y * 128;
    const int n0 = blockIdx.x * 256;

    float acc[4][8][4];
    #pragma unroll
    for (int mt = 0; mt < 4; mt++)
        #pragma unroll
        for (int nt = 0; nt < 8; nt++)
            #pragma unroll
            for (int r = 0; r < 4; r++) acc[mt][nt][r] = 0.f;

    const int nkb = Kdim / 32;

    auto issue = [&](int kb, int slot) {
        const uint32_t sb = sbase + slot * STG;
        #pragma unroll
        for (int p = 0; p < 2; p++) {
            const int id = tid + 256 * p;
            const int row = id >> 2, cc = id & 3;
            cp_async16(sb + row * 80 + cc * 16,
                       A + (size_t)(m0 + row) * Kdim + kb * 32 + cc * 8);
        }
        #pragma unroll
        for (int p = 0; p < 4; p++) {
            const int id = tid + 256 * p;
            const int row = id >> 2, cc = id & 3;
            cp_async16(sb + A_BYTES + row * 80 + cc * 16,
                       Bt + (size_t)(n0 + row) * Kdim + kb * 32 + cc * 8);
        }
    };

    // prologue: fill stages 0..2
    issue(0, 0); cp_commit();
    issue(1, 1); cp_commit();
    issue(2, 2); cp_commit();

    int s_cur = 0, s_nxt = 3;

    for (int kb = 0; kb < nkb; kb++) {
        cp_wait<2>();
        __syncthreads();
        if (kb + 3 < nkb) issue(kb + 3, s_nxt);
        cp_commit();

        const uint32_t* As = (const uint32_t*)(smg + (size_t)s_cur * STG);
        const uint32_t* Bs = As + A_BYTES / 4;

        #pragma unroll
        for (int ks = 0; ks < 2; ks++) {
            uint32_t af[4][4], bf[8][2];
            #pragma unroll
            for (int mt = 0; mt < 4; mt++) {
                const uint32_t* ap =
                    As + (wm * 64 + mt * 16 + gid) * PADW + ks * 8 + tg;
                af[mt][0] = ap[0];
                af[mt][1] = ap[8 * PADW];
                af[mt][2] = ap[4];
                af[mt][3] = ap[8 * PADW + 4];
            }
            #pragma unroll
            for (int nt = 0; nt < 8; nt++) {
                const uint32_t* bp =
                    Bs + (wn * 64 + nt * 8 + gid) * PADW + ks * 8 + tg;
                bf[nt][0] = bp[0];
                bf[nt][1] = bp[4];
            }
            #pragma unroll
            for (int mt = 0; mt < 4; mt++)
                #pragma unroll
                for (int nt = 0; nt < 8; nt++)
                    mma_f16(acc[mt][nt], af[mt], bf[nt]);
        }

        s_cur = s_cur + 1 == NSF ? 0 : s_cur + 1;
        s_nxt = s_nxt + 1 == NSF ? 0 : s_nxt + 1;
    }

    // epilogue
    #pragma unroll
    for (int mt = 0; mt < 4; mt++) {
        #pragma unroll
        for (int half = 0; half < 2; half++) {
            const int row = m0 + wm * 64 + mt * 16 + gid + half * 8;
            #pragma unroll
            for (int nt = 0; nt < 8; nt++) {
                const int col = n0 + wn * 64 + nt * 8 + 2 * tg;
                float v0 = acc[mt][nt][half * 2 + 0];
                float v1 = acc[mt][nt][half * 2 + 1];
                if (bias) { v0 += bias[col]; v1 += bias[col + 1]; }
                if (mode == 1) {
                    // fp16 out, gelu
                    __half2 h2 = __floats2half2_rn(gelu_f(v0), gelu_f(v1));
                    *(__half2*)((__half*)Cout + (size_t)row * Ndim + col) = h2;
                } else {
                    if (resid) {
                        const float* Rr = resid + (size_t)row * Ndim;
                        v0 += Rr[col]; v1 += Rr[col + 1];
                    }
                    float2 o; o.x = v0; o.y = v1;
                    *(float2*)((float*)Cout + (size_t)row * Ndim + col) = o;
                }
            }
        }
    }
}

// ---------------------------------------------------------------------------
// Tensor-core causal flash attention (tf32 MMA, fp32 accum/softmax).
// qkv fp32 (row stride 3*DD); out fp16 [M, D] (b,t,h,hd).
// 64x64 tiles, 128 threads / 4 warps; warp owns 16 q-rows.
// ---------------------------------------------------------------------------
#define QSTR (3 * DD)
#define AP2 68
#define ATTN_SMEM_MMA (4 * 64 * AP2 * 4)   // Qs,Ks,Vs,Ps = 69632 B

__global__ __launch_bounds__(128) void attn_mma(
    const float* __restrict__ qkv, __half* __restrict__ out)
{
    extern __shared__ __align__(16) float sm[];
    float* Qs = sm;                 // 64 x 68
    float* Ks = Qs + 64 * AP2;
    float* Vs = Ks + 64 * AP2;
    float* Ps = Vs + 64 * AP2;

    const int tid  = threadIdx.x;
    const int lane = tid & 31;
    const int warp = tid >> 5;
    const int gid  = lane >> 2;
    const int tg   = lane & 3;
    const int bh = blockIdx.y;
    const int b  = bh / HH;
    const int h  = bh % HH;
    const int qt = blockIdx.x;
    const int q0 = qt * 64;

    const size_t qbase = ((size_t)b * TT) * QSTR + (size_t)h * HD;
    const size_t obase = ((size_t)b * TT) * DD + (size_t)h * HD;

    #pragma unroll
    for (int i = 0; i < 8; i++) {
        int j = tid + 128 * i;
        int r = j >> 4, c4 = (j & 15) * 4;
        float4 v = *(const float4*)(qkv + qbase + (size_t)(q0 + r) * QSTR + c4);
        v.x = tf32_round(v.x); v.y = tf32_round(v.y);
        v.z = tf32_round(v.z); v.w = tf32_round(v.w);
        *(float4*)(Qs + r * AP2 + c4) = v;
    }

    float mrow[2] = {-1e30f, -1e30f};
    float lrow[2] = {0.f, 0.f};
    float o[8][4];
    #pragma unroll
    for (int nf = 0; nf < 8; nf++)
        #pragma unroll
        for (int c = 0; c < 4; c++) o[nf][c] = 0.f;

    for (int kt = 0; kt <= qt; kt++) {
        const int k0 = kt * 64;
        float4 kv[8], vv[8];
        #pragma unroll
        for (int i = 0; i < 8; i++) {
            int j = tid + 128 * i;
            int r = j >> 4, c4 = (j & 15) * 4;
            kv[i] = *(const float4*)(qkv + qbase + DD     + (size_t)(k0 + r) * QSTR + c4);
            vv[i] = *(const float4*)(qkv + qbase + 2 * DD + (size_t)(k0 + r) * QSTR + c4);
        }
        __syncthreads();
        #pragma unroll
        for (int i = 0; i < 8; i++) {
            int j = tid + 128 * i;
            int r = j >> 4, c4 = (j & 15) * 4;
            float4 a = kv[i];
            a.x = tf32_round(a.x); a.y = tf32_round(a.y);
            a.z = tf32_round(a.z); a.w = tf32_round(a.w);
            *(float4*)(Ks + r * AP2 + c4) = a;
            float4 bvv = vv[i];
            bvv.x = tf32_round(bvv.x); bvv.y = tf32_round(bvv.y);
            bvv.z = tf32_round(bvv.z); bvv.w = tf32_round(bvv.w);
            *(float4*)(Vs + r * AP2 + c4) = bvv;
        }
        __syncthreads();

        float s[8][4];
        #pragma unroll
        for (int nf = 0; nf < 8; nf++)
            #pragma unroll
            for (int c = 0; c < 4; c++) s[nf][c] = 0.f;
        #pragma unroll
        for (int ks = 0; ks < 8; ks++) {
            uint32_t af[4];
            const uint32_t* qp =
                (const uint32_t*)Qs + (warp * 16 + gid) * AP2 + ks * 8 + tg;
            af[0] = qp[0];
            af[1] = qp[8 * AP2];
            af[2] = qp[4];
            af[3] = qp[8 * AP2 + 4];
            #pragma unroll
            for (int nf = 0; nf < 8; nf++) {
                uint32_t bfk[2];
                const uint32_t* kp =
                    (const uint32_t*)Ks + (nf * 8 + gid) * AP2 + ks * 8 + tg;
                bfk[0] = kp[0];
                bfk[1] = kp[4];
                mma_tf32(s[nf], af, bfk);
            }
        }

        const float scale = 0.125f;
        const bool diag = (kt == qt);
        #pragma unroll
        for (int nf = 0; nf < 8; nf++) {
            #pragma unroll
            for (int c = 0; c < 4; c++) {
                float val = s[nf][c] * scale;
                if (diag) {
                    int row = warp * 16 + gid + (c >= 2 ? 8 : 0);
                    int col = nf * 8 + 2 * tg + (c & 1);
                    if (col > row) val = -1e30f;
                }
                s[nf][c] = val;
            }
        }

        float mx0 = -1e30f, mx1 = -1e30f;
        #pragma unroll
        for (int nf = 0; nf < 8; nf++) {
            mx0 = fmaxf(mx0, fmaxf(s[nf][0], s[nf][1]));
            mx1 = fmaxf(mx1, fmaxf(s[nf][2], s[nf][3]));
        }
        #pragma unroll
        for (int w = 1; w <= 2; w <<= 1) {
            mx0 = fmaxf(mx0, __shfl_xor_sync(0xffffffffu, mx0, w));
            mx1 = fmaxf(mx1, __shfl_xor_sync(0xffffffffu, mx1, w));
        }
        float mn0 = fmaxf(mrow[0], mx0);
        float mn1 = fmaxf(mrow[1], mx1);
        float al0 = __expf(mrow[0] - mn0);
        float al1 = __expf(mrow[1] - mn1);

        float sum0 = 0.f, sum1 = 0.f;
        #pragma unroll
        for (int nf = 0; nf < 8; nf++) {
            s[nf][0] = __expf(s[nf][0] - mn0);
            s[nf][1] = __expf(s[nf][1] - mn0);
            s[nf][2] = __expf(s[nf][2] - mn1);
            s[nf][3] = __expf(s[nf][3] - mn1);
            sum0 += s[nf][0] + s[nf][1];
            sum1 += s[nf][2] + s[nf][3];
        }
        #pragma unroll
        for (int w = 1; w <= 2; w <<= 1) {
            sum0 += __shfl_xor_sync(0xffffffffu, sum0, w);
            sum1 += __shfl_xor_sync(0xffffffffu, sum1, w);
        }
        lrow[0] = lrow[0] * al0 + sum0;
        lrow[1] = lrow[1] * al1 + sum1;
        mrow[0] = mn0;
        mrow[1] = mn1;

        #pragma unroll
        for (int nf = 0; nf < 8; nf++) {
            float2 p0, p1;
            p0.x = tf32_round(s[nf][0]); p0.y = tf32_round(s[nf][1]);
            p1.x = tf32_round(s[nf][2]); p1.y = tf32_round(s[nf][3]);
            *(float2*)(Ps + (warp * 16 + gid)     * AP2 + nf * 8 + 2 * tg) = p0;
            *(float2*)(Ps + (warp * 16 + gid + 8) * AP2 + nf * 8 + 2 * tg) = p1;
        }
        #pragma unroll
        for (int nf = 0; nf < 8; nf++) {
            o[nf][0] *= al0; o[nf][1] *= al0;
            o[nf][2] *= al1; o[nf][3] *= al1;
        }
        __syncthreads();

        #pragma unroll
        for (int ks = 0; ks < 8; ks++) {
            uint32_t af[4];
            const uint32_t* pp =
                (const uint32_t*)Ps + (warp * 16 + gid) * AP2 + ks * 8 + tg;
            af[0] = pp[0];
            af[1] = pp[8 * AP2];
            af[2] = pp[4];
            af[3] = pp[8 * AP2 + 4];
            #pragma unroll
            for (int nf = 0; nf < 8; nf++) {
                uint32_t bfv[2];
                const uint32_t* vp =
                    (const uint32_t*)Vs + (ks * 8 + tg) * AP2 + nf * 8 + gid;
                bfv[0] = vp[0];
                bfv[1] = vp[4 * AP2];
                mma_tf32(o[nf], af, bfv);
            }
        }
    }

    const float inv0 = 1.0f / lrow[0];
    const float inv1 = 1.0f / lrow[1];
    const int r0 = q0 + warp * 16 + gid;
    #pragma unroll
    for (int nf = 0; nf < 8; nf++) {
        const int col = nf * 8 + 2 * tg;
        __half2 w0 = __floats2half2_rn(o[nf][0] * inv0, o[nf][1] * inv0);
        __half2 w1 = __floats2half2_rn(o[nf][2] * inv1, o[nf][3] * inv1);
        *(__half2*)(out + obase + (size_t)r0 * DD + col)       = w0;
        *(__half2*)(out + obase + (size_t)(r0 + 8) * DD + col) = w1;
    }
}

// ---------------------------------------------------------------------------
// Host launch
// ---------------------------------------------------------------------------
extern "C" void kernel_launch(void* const* d_in, const int* in_sizes, int n_in,
                              void* d_out, int out_size)
{
    const float* x    = (const float*)d_in[0];
    const float* Wq   = (const float*)d_in[1];
    const float* Wk   = (const float*)d_in[2];
    const float* Wv   = (const float*)d_in[3];
    const float* Wo   = (const float*)d_in[4];
    const float* bo   = (const float*)d_in[5];
    const float* W1   = (const float*)d_in[6];
    const float* b1   = (const float*)d_in[7];
    const float* W2   = (const float*)d_in[8];
    const float* b2   = (const float*)d_in[9];
    const float* g1   = (const float*)d_in[10];
    const float* be1  = (const float*)d_in[11];
    const float* g2   = (const float*)d_in[12];
    const float* be2  = (const float*)d_in[13];
    float* out = (float*)d_out;

    __half *h, *attn, *h2, *ff1, *wqkv, *wo, *w1, *w2;
    float *qkv, *x2;
    cudaGetSymbolAddress((void**)&h,    g_h);
    cudaGetSymbolAddress((void**)&qkv,  g_qkv);
    cudaGetSymbolAddress((void**)&attn, g_attn);
    cudaGetSymbolAddress((void**)&x2,   g_x2);
    cudaGetSymbolAddress((void**)&h2,   g_h2);
    cudaGetSymbolAddress((void**)&ff1,  g_ff1);
    cudaGetSymbolAddress((void**)&wqkv, g_wqkv);
    cudaGetSymbolAddress((void**)&wo,   g_wo);
    cudaGetSymbolAddress((void**)&w1,   g_w1);
    cudaGetSymbolAddress((void**)&w2,   g_w2);

    cudaFuncSetAttribute(attn_mma,
                         cudaFuncAttributeMaxDynamicSharedMemorySize, ATTN_SMEM_MMA);
    cudaFuncSetAttribute(gemm_h,
                         cudaFuncAttributeMaxDynamicSharedMemorySize, GEMM_SMEM);

    // 0) weight preprocessing: transpose to [N][K] fp16
    dim3 tb(32, 8);
    transpose_h_kernel<<<dim3(32, 32),  tb>>>(Wq, wqkv,                 DD, DD);
    transpose_h_kernel<<<dim3(32, 32),  tb>>>(Wk, wqkv + (size_t)DD * DD,  DD, DD);
    transpose_h_kernel<<<dim3(32, 32),  tb>>>(Wv, wqkv + (size_t)2 * DD * DD, DD, DD);
    transpose_h_kernel<<<dim3(32, 32),  tb>>>(Wo, wo, DD, DD);
    transpose_h_kernel<<<dim3(128, 32), tb>>>(W1, w1, DD, FF);
    transpose_h_kernel<<<dim3(32, 128), tb>>>(W2, w2, FF, DD);

    // 1) LN1 -> fp16
    layernorm_kernel<<<MM, 256>>>(x, g1, be1, h);

    // 2) fused QKV projection (fp16 in, fp32 out)
    gemm_h<<<dim3(3 * DD / 256, MM / 128), 256, GEMM_SMEM>>>(
        h, wqkv, nullptr, nullptr, qkv, 3 * DD, DD, 0);

    // 3) causal attention (tensor cores, fp16 out)
    attn_mma<<<dim3(TT / 64, BB * HH), 128, ATTN_SMEM_MMA>>>(qkv, attn);

    // 4) output projection + bias + residual(x) -> fp32
    dim3 gDD(DD / 256, MM / 128);
    gemm_h<<<gDD, 256, GEMM_SMEM>>>(attn, wo, bo, x, x2, DD, DD, 2);

    // 5) LN2 -> fp16
    layernorm_kernel<<<MM, 256>>>(x2, g2, be2, h2);

    // 6) FFN1 + bias + GELU -> fp16
    gemm_h<<<dim3(FF / 256, MM / 128), 256, GEMM_SMEM>>>(
        h2, w1, b1, nullptr, ff1, FF, DD, 1);

    // 7) FFN2 + bias + residual(x2) -> out (fp32)
    gemm_h<<<gDD, 256, GEMM_SMEM>>>(ff1, w2, b2, x2, out, DD, FF, 2);
}

// round 10
// speedup vs baseline: 6.2810x; 1.2798x over previous
#include <cuda_runtime.h>
#include <cuda_fp16.h>
#include <math.h>
#include <stdint.h>

// ---------------------------------------------------------------------------
// Problem constants
// ---------------------------------------------------------------------------
#define BB 4
#define TT 2048
#define DD 1024
#define HH 16
#define HD 64
#define FF 4096
#define MM (BB * TT)       // 8192 rows
#define EPS 1e-5f

// ---------------------------------------------------------------------------
// Scratch (allocation-free: __device__ globals)
// ---------------------------------------------------------------------------
__device__ __half g_h   [(size_t)MM * DD];      // LN1 out (fp16)
__device__ __half g_qkv [(size_t)MM * 3 * DD];  // QKV out (fp16)
__device__ __half g_attn[(size_t)MM * DD];      // attention out (fp16)
__device__ float  g_x2  [(size_t)MM * DD];      // residual stream 2 (fp32)
__device__ __half g_h2  [(size_t)MM * DD];      // LN2 out (fp16)
__device__ __half g_ff1 [(size_t)MM * FF];      // FFN1 out (fp16)
// fp16 weights, transposed to [N][K]
__device__ __half g_wqkv[(size_t)(3 * DD) * DD];
__device__ __half g_wo  [(size_t)DD * DD];
__device__ __half g_w1  [(size_t)FF * DD];
__device__ __half g_w2  [(size_t)DD * FF];

// ---------------------------------------------------------------------------
// helpers
// ---------------------------------------------------------------------------
__device__ __forceinline__ void mma_f16(float c[4], const uint32_t a[4],
                                        const uint32_t b[2]) {
    asm volatile(
        "mma.sync.aligned.m16n8k16.row.col.f32.f16.f16.f32 "
        "{%0,%1,%2,%3}, {%4,%5,%6,%7}, {%8,%9}, {%0,%1,%2,%3};"
        : "+f"(c[0]), "+f"(c[1]), "+f"(c[2]), "+f"(c[3])
        : "r"(a[0]), "r"(a[1]), "r"(a[2]), "r"(a[3]), "r"(b[0]), "r"(b[1]));
}
__device__ __forceinline__ void ldsm_x4(uint32_t r[4], uint32_t saddr) {
    asm volatile("ldmatrix.sync.aligned.m8n8.x4.shared.b16 {%0,%1,%2,%3}, [%4];"
        : "=r"(r[0]), "=r"(r[1]), "=r"(r[2]), "=r"(r[3]) : "r"(saddr));
}
__device__ __forceinline__ void ldsm_x4_t(uint32_t r[4], uint32_t saddr) {
    asm volatile("ldmatrix.sync.aligned.m8n8.x4.trans.shared.b16 {%0,%1,%2,%3}, [%4];"
        : "=r"(r[0]), "=r"(r[1]), "=r"(r[2]), "=r"(r[3]) : "r"(saddr));
}
__device__ __forceinline__ void cp_async16(uint32_t saddr, const void* gptr) {
    asm volatile("cp.async.cg.shared.global [%0], [%1], 16;"
                 :: "r"(saddr), "l"(gptr) : "memory");
}
__device__ __forceinline__ void cp_commit() {
    asm volatile("cp.async.commit_group;" ::: "memory");
}
template <int N>
__device__ __forceinline__ void cp_wait() {
    asm volatile("cp.async.wait_group %0;" :: "n"(N) : "memory");
}
__device__ __forceinline__ uint32_t smem_u32(const void* p) {
    uint32_t a;
    asm("{ .reg .u64 t; cvta.to.shared.u64 t, %1; cvt.u32.u64 %0, t; }"
        : "=r"(a) : "l"(p));
    return a;
}

// ---------------------------------------------------------------------------
// Weight preprocessing: transpose [R][C] fp32 -> [C][R] fp16
// ---------------------------------------------------------------------------
__global__ __launch_bounds__(256) void transpose_h_kernel(
    const float* __restrict__ in, __half* __restrict__ out, int R, int C)
{
    __shared__ float t[32][33];
    const int c0 = blockIdx.x * 32;
    const int r0 = blockIdx.y * 32;
    const int tx = threadIdx.x, ty = threadIdx.y;
    #pragma unroll
    for (int i = 0; i < 32; i += 8)
        t[ty + i][tx] = in[(size_t)(r0 + ty + i) * C + c0 + tx];
    __syncthreads();
    #pragma unroll
    for (int i = 0; i < 32; i += 8)
        out[(size_t)(c0 + ty + i) * R + r0 + tx] = __float2half_rn(t[tx][ty + i]);
}

// ---------------------------------------------------------------------------
// LayerNorm: one block (256 threads) per row of 1024; writes fp16
// ---------------------------------------------------------------------------
__global__ __launch_bounds__(256) void layernorm_kernel(
    const float* __restrict__ x, const float* __restrict__ gamma,
    const float* __restrict__ beta, __half* __restrict__ out)
{
    __shared__ float shs[8], shss[8];
    __shared__ float s_mean, s_inv;
    const int row = blockIdx.x;
    const int tid = threadIdx.x;

    const float4 xv = *(const float4*)(x + (size_t)row * DD + tid * 4);
    float s  = xv.x + xv.y + xv.z + xv.w;
    float ss = xv.x * xv.x + xv.y * xv.y + xv.z * xv.z + xv.w * xv.w;
    #pragma unroll
    for (int o = 16; o > 0; o >>= 1) {
        s  += __shfl_down_sync(0xffffffffu, s, o);
        ss += __shfl_down_sync(0xffffffffu, ss, o);
    }
    if ((tid & 31) == 0) { shs[tid >> 5] = s; shss[tid >> 5] = ss; }
    __syncthreads();
    if (tid == 0) {
        float S = 0.f, SS = 0.f;
        #pragma unroll
        for (int i = 0; i < 8; i++) { S += shs[i]; SS += shss[i]; }
        float mean = S * (1.0f / DD);
        float var  = SS * (1.0f / DD) - mean * mean;
        s_mean = mean;
        s_inv  = rsqrtf(var + EPS);
    }
    __syncthreads();
    const float mean = s_mean, inv = s_inv;
    const float4 gv = *(const float4*)(gamma + tid * 4);
    const float4 bv = *(const float4*)(beta  + tid * 4);
    __half2 o01 = __floats2half2_rn(gv.x * (xv.x - mean) * inv + bv.x,
                                    gv.y * (xv.y - mean) * inv + bv.y);
    __half2 o23 = __floats2half2_rn(gv.z * (xv.z - mean) * inv + bv.z,
                                    gv.w * (xv.w - mean) * inv + bv.w);
    *(__half2*)(out + (size_t)row * DD + tid * 4)     = o01;
    *(__half2*)(out + (size_t)row * DD + tid * 4 + 2) = o23;
}

// ---------------------------------------------------------------------------
// GELU (tanh approximation, matches reference)
// ---------------------------------------------------------------------------
__device__ __forceinline__ float gelu_f(float x)
{
    const float c = 0.7978845608028654f;  // sqrt(2/pi)
    float inner = c * (x + 0.044715f * x * x * x);
    return 0.5f * x * (1.0f + tanhf(inner));
}

// ---------------------------------------------------------------------------
// fp16 tensor-core GEMM:  C[M,N] = A[M,K] @ Bt[N,K]^T  (+bias)(+gelu)(+resid)
// A, Bt fp16; fp32 accumulate. CTA tile 128x256, BK=32, 256 threads, 8 warps
// (2x4), warp tile 64x64, m16n8k16, ldmatrix operand fetch.
// cp.async 4-stage pipeline. smem rows (32 halves data) padded to 80 B.
// mode: 0 = fp32 out plain, 1 = fp16 out bias+gelu, 2 = fp32 out bias+resid,
//       3 = fp16 out plain
// ---------------------------------------------------------------------------
#define A_BYTES (128 * 80)          // 10240
#define B_BYTES (256 * 80)          // 20480
#define STG (A_BYTES + B_BYTES)     // 30720
#define NSF 4
#define GEMM_SMEM (NSF * STG)       // 122880

__global__ __launch_bounds__(256, 1) void gemm_h(
    const __half* __restrict__ A, const __half* __restrict__ Bt,
    const float* __restrict__ bias,   // may be null
    const float* __restrict__ resid,  // may be null
    void* __restrict__ Cout,
    int Ndim, int Kdim, int mode)
{
    extern __shared__ __align__(16) char smg[];
    const uint32_t sbase = smem_u32(smg);
    const int tid  = threadIdx.x;
    const int lane = tid & 31;
    const int warp = tid >> 5;
    const int wm   = warp >> 2;     // 0..1
    const int wn   = warp & 3;      // 0..3
    const int gid  = lane >> 2;     // 0..7
    const int tg   = lane & 3;      // 0..3
    const int m0 = blockIdx.y * 128;
    const int n0 = blockIdx.x * 256;

    // ldmatrix per-lane offsets (within a stage)
    const uint32_t aoff = (uint32_t)(wm * 64 + (lane & 15)) * 80 + (lane >> 4) * 16;
    const uint32_t boff = A_BYTES +
        (uint32_t)(wn * 64 + (lane & 7) + (lane >> 4) * 8) * 80 +
        ((lane >> 3) & 1) * 16;

    float acc[4][8][4];
    #pragma unroll
    for (int mt = 0; mt < 4; mt++)
        #pragma unroll
        for (int nt = 0; nt < 8; nt++)
            #pragma unroll
            for (int r = 0; r < 4; r++) acc[mt][nt][r] = 0.f;

    const int nkb = Kdim / 32;

    auto issue = [&](int kb, int slot) {
        const uint32_t sb = sbase + slot * STG;
        #pragma unroll
        for (int p = 0; p < 2; p++) {
            const int id = tid + 256 * p;
            const int row = id >> 2, cc = id & 3;
            cp_async16(sb + row * 80 + cc * 16,
                       A + (size_t)(m0 + row) * Kdim + kb * 32 + cc * 8);
        }
        #pragma unroll
        for (int p = 0; p < 4; p++) {
            const int id = tid + 256 * p;
            const int row = id >> 2, cc = id & 3;
            cp_async16(sb + A_BYTES + row * 80 + cc * 16,
                       Bt + (size_t)(n0 + row) * Kdim + kb * 32 + cc * 8);
        }
    };

    issue(0, 0); cp_commit();
    issue(1, 1); cp_commit();
    issue(2, 2); cp_commit();

    int s_cur = 0, s_nxt = 3;

    for (int kb = 0; kb < nkb; kb++) {
        cp_wait<2>();
        __syncthreads();
        if (kb + 3 < nkb) issue(kb + 3, s_nxt);
        cp_commit();

        const uint32_t sA = sbase + s_cur * STG + aoff;
        const uint32_t sB = sbase + s_cur * STG + boff;

        #pragma unroll
        for (int ks = 0; ks < 2; ks++) {
            uint32_t af[4][4], bf[8][2];
            #pragma unroll
            for (int mt = 0; mt < 4; mt++)
                ldsm_x4(af[mt], sA + mt * 1280 + ks * 32);
            #pragma unroll
            for (int ntp = 0; ntp < 4; ntp++) {
                uint32_t t[4];
                ldsm_x4(t, sB + ntp * 1280 + ks * 32);
                bf[2 * ntp][0] = t[0]; bf[2 * ntp][1] = t[1];
                bf[2 * ntp + 1][0] = t[2]; bf[2 * ntp + 1][1] = t[3];
            }
            #pragma unroll
            for (int mt = 0; mt < 4; mt++)
                #pragma unroll
                for (int nt = 0; nt < 8; nt++)
                    mma_f16(acc[mt][nt], af[mt], bf[nt]);
        }

        s_cur = s_cur + 1 == NSF ? 0 : s_cur + 1;
        s_nxt = s_nxt + 1 == NSF ? 0 : s_nxt + 1;
    }

    // epilogue
    #pragma unroll
    for (int mt = 0; mt < 4; mt++) {
        #pragma unroll
        for (int half = 0; half < 2; half++) {
            const int row = m0 + wm * 64 + mt * 16 + gid + half * 8;
            #pragma unroll
            for (int nt = 0; nt < 8; nt++) {
                const int col = n0 + wn * 64 + nt * 8 + 2 * tg;
                float v0 = acc[mt][nt][half * 2 + 0];
                float v1 = acc[mt][nt][half * 2 + 1];
                if (bias) { v0 += bias[col]; v1 += bias[col + 1]; }
                if (mode == 1) {
                    __half2 h2 = __floats2half2_rn(gelu_f(v0), gelu_f(v1));
                    *(__half2*)((__half*)Cout + (size_t)row * Ndim + col) = h2;
                } else if (mode == 3) {
                    __half2 h2 = __floats2half2_rn(v0, v1);
                    *(__half2*)((__half*)Cout + (size_t)row * Ndim + col) = h2;
                } else {
                    if (resid) {
                        const float* Rr = resid + (size_t)row * Ndim;
                        v0 += Rr[col]; v1 += Rr[col + 1];
                    }
                    float2 o; o.x = v0; o.y = v1;
                    *(float2*)((float*)Cout + (size_t)row * Ndim + col) = o;
                }
            }
        }
    }
}

// ---------------------------------------------------------------------------
// fp16 tensor-core causal flash attention (m16n8k16, fp32 accum/softmax).
// qkv fp16 packed (row stride 3*DD halves); out fp16 [M, D] (b,t,h,hd).
// 64x64 tiles, 128 threads / 4 warps; warp owns 16 q-rows.
// smem tiles: 64 rows x 64 halves (128 B data) padded to 144-B stride
// (36 words mod 32 = 4 -> 8 consecutive rows hit distinct 16B banks).
// Q,K,V,P tiles = 4 x 9216 B = 36 KB.
// ---------------------------------------------------------------------------
#define AQSTR (3 * DD)
#define ARSTR 144                   // bytes per smem row
#define ATILE_B (64 * ARSTR)        // 9216
#define ATTN_SMEM (4 * ATILE_B)     // 36864

__global__ __launch_bounds__(128) void attn_h(
    const __half* __restrict__ qkv, __half* __restrict__ out)
{
    extern __shared__ __align__(16) char sma[];
    const uint32_t sb = smem_u32(sma);
    const uint32_t Qb = sb;
    const uint32_t Kb = sb + ATILE_B;
    const uint32_t Vb = sb + 2 * ATILE_B;
    const uint32_t Pb = sb + 3 * ATILE_B;
    __half* Ps = (__half*)(sma + 3 * ATILE_B);

    const int tid  = threadIdx.x;
    const int lane = tid & 31;
    const int warp = tid >> 5;
    const int gid  = lane >> 2;
    const int tg   = lane & 3;
    const int bh = blockIdx.y;
    const int b  = bh / HH;
    const int h  = bh % HH;
    const int qt = blockIdx.x;
    const int q0 = qt * 64;

    const size_t qbase = ((size_t)b * TT) * AQSTR + (size_t)h * HD;
    const size_t obase = ((size_t)b * TT) * DD + (size_t)h * HD;

    // load Q tile (64 rows x 128 B)
    {
        const __half* src = qkv + qbase + (size_t)q0 * AQSTR;
        #pragma unroll
        for (int p = 0; p < 4; p++) {
            const int id = tid + 128 * p;
            const int r = id >> 3, c = id & 7;
            cp_async16(Qb + r * ARSTR + c * 16, src + (size_t)r * AQSTR + c * 8);
        }
        cp_commit();
    }

    float mrow[2] = {-1e30f, -1e30f};
    float lrow[2] = {0.f, 0.f};
    float o[8][4];
    #pragma unroll
    for (int nf = 0; nf < 8; nf++)
        #pragma unroll
        for (int c = 0; c < 4; c++) o[nf][c] = 0.f;

    // ldmatrix per-lane offsets
    const uint32_t qp_off = (uint32_t)(warp * 16 + (lane & 15)) * ARSTR +
                            (lane >> 4) * 16;
    const uint32_t kp_off = (uint32_t)((lane & 7) + (lane >> 4) * 8) * ARSTR +
                            ((lane >> 3) & 1) * 16;
    const uint32_t vp_off = (uint32_t)((lane & 7) + ((lane >> 3) & 1) * 8) * ARSTR +
                            (lane >> 4) * 16;

    for (int kt = 0; kt <= qt; kt++) {
        const int k0 = kt * 64;
        __syncthreads();   // prior iteration's K/V/P readers done
        {
            const __half* ksrc = qkv + qbase + DD     + (size_t)k0 * AQSTR;
            const __half* vsrc = qkv + qbase + 2 * DD + (size_t)k0 * AQSTR;
            #pragma unroll
            for (int p = 0; p < 4; p++) {
                const int id = tid + 128 * p;
                const int r = id >> 3, c = id & 7;
                cp_async16(Kb + r * ARSTR + c * 16,
                           ksrc + (size_t)r * AQSTR + c * 8);
            }
            #pragma unroll
            for (int p = 0; p < 4; p++) {
                const int id = tid + 128 * p;
                const int r = id >> 3, c = id & 7;
                cp_async16(Vb + r * ARSTR + c * 16,
                           vsrc + (size_t)r * AQSTR + c * 8);
            }
            cp_commit();
        }
        cp_wait<0>();
        __syncthreads();

        // S = Q K^T  (warp: 16 x 64)
        float s[8][4];
        #pragma unroll
        for (int nf = 0; nf < 8; nf++)
            #pragma unroll
            for (int c = 0; c < 4; c++) s[nf][c] = 0.f;
        #pragma unroll
        for (int ks = 0; ks < 4; ks++) {
            uint32_t aq[4];
            ldsm_x4(aq, Qb + qp_off + ks * 32);
            #pragma unroll
            for (int ntp = 0; ntp < 4; ntp++) {
                uint32_t t[4];
                ldsm_x4(t, Kb + kp_off + ntp * 16 * ARSTR + ks * 32);
                uint32_t b0[2] = {t[0], t[1]};
                uint32_t b1[2] = {t[2], t[3]};
                mma_f16(s[2 * ntp],     aq, b0);
                mma_f16(s[2 * ntp + 1], aq, b1);
            }
        }

        // scale + causal mask
        const float scale = 0.125f;
        const bool diag = (kt == qt);
        #pragma unroll
        for (int nf = 0; nf < 8; nf++) {
            #pragma unroll
            for (int c = 0; c < 4; c++) {
                float val = s[nf][c] * scale;
                if (diag) {
                    int row = warp * 16 + gid + (c >= 2 ? 8 : 0);
                    int col = nf * 8 + 2 * tg + (c & 1);
                    if (col > row) val = -1e30f;
                }
                s[nf][c] = val;
            }
        }

        // online softmax (rows gid / gid+8; reduce over tg lanes)
        float mx0 = -1e30f, mx1 = -1e30f;
        #pragma unroll
        for (int nf = 0; nf < 8; nf++) {
            mx0 = fmaxf(mx0, fmaxf(s[nf][0], s[nf][1]));
            mx1 = fmaxf(mx1, fmaxf(s[nf][2], s[nf][3]));
        }
        #pragma unroll
        for (int w = 1; w <= 2; w <<= 1) {
            mx0 = fmaxf(mx0, __shfl_xor_sync(0xffffffffu, mx0, w));
            mx1 = fmaxf(mx1, __shfl_xor_sync(0xffffffffu, mx1, w));
        }
        float mn0 = fmaxf(mrow[0], mx0);
        float mn1 = fmaxf(mrow[1], mx1);
        float al0 = __expf(mrow[0] - mn0);
        float al1 = __expf(mrow[1] - mn1);

        float sum0 = 0.f, sum1 = 0.f;
        #pragma unroll
        for (int nf = 0; nf < 8; nf++) {
            s[nf][0] = __expf(s[nf][0] - mn0);
            s[nf][1] = __expf(s[nf][1] - mn0);
            s[nf][2] = __expf(s[nf][2] - mn1);
            s[nf][3] = __expf(s[nf][3] - mn1);
            sum0 += s[nf][0] + s[nf][1];
            sum1 += s[nf][2] + s[nf][3];
        }
        #pragma unroll
        for (int w = 1; w <= 2; w <<= 1) {
            sum0 += __shfl_xor_sync(0xffffffffu, sum0, w);
            sum1 += __shfl_xor_sync(0xffffffffu, sum1, w);
        }
        lrow[0] = lrow[0] * al0 + sum0;
        lrow[1] = lrow[1] * al1 + sum1;
        mrow[0] = mn0;
        mrow[1] = mn1;

        // store P (fp16; warp-private rows; 72-half row stride)
        #pragma unroll
        for (int nf = 0; nf < 8; nf++) {
            *(__half2*)(Ps + (warp * 16 + gid) * 72 + nf * 8 + 2 * tg) =
                __floats2half2_rn(s[nf][0], s[nf][1]);
            *(__half2*)(Ps + (warp * 16 + gid + 8) * 72 + nf * 8 + 2 * tg) =
                __floats2half2_rn(s[nf][2], s[nf][3]);
        }
        // rescale accumulator
        #pragma unroll
        for (int nf = 0; nf < 8; nf++) {
            o[nf][0] *= al0; o[nf][1] *= al0;
            o[nf][2] *= al1; o[nf][3] *= al1;
        }
        __syncwarp();

        // O += P V  (V consumed via ldmatrix.trans)
        #pragma unroll
        for (int ks = 0; ks < 4; ks++) {
            uint32_t ap[4];
            ldsm_x4(ap, Pb + qp_off + ks * 32);
            #pragma unroll
            for (int ntp = 0; ntp < 4; ntp++) {
                uint32_t t[4];
                ldsm_x4_t(t, Vb + vp_off + ks * 16 * ARSTR + ntp * 32);
                uint32_t b0[2] = {t[0], t[1]};
                uint32_t b1[2] = {t[2], t[3]};
                mma_f16(o[2 * ntp],     ap, b0);
                mma_f16(o[2 * ntp + 1], ap, b1);
            }
        }
    }

    const float inv0 = 1.0f / lrow[0];
    const float inv1 = 1.0f / lrow[1];
    const int r0 = q0 + warp * 16 + gid;
    #pragma unroll
    for (int nf = 0; nf < 8; nf++) {
        const int col = nf * 8 + 2 * tg;
        __half2 w0 = __floats2half2_rn(o[nf][0] * inv0, o[nf][1] * inv0);
        __half2 w1 = __floats2half2_rn(o[nf][2] * inv1, o[nf][3] * inv1);
        *(__half2*)(out + obase + (size_t)r0 * DD + col)       = w0;
        *(__half2*)(out + obase + (size_t)(r0 + 8) * DD + col) = w1;
    }
}

// ---------------------------------------------------------------------------
// Host launch
// ---------------------------------------------------------------------------
extern "C" void kernel_launch(void* const* d_in, const int* in_sizes, int n_in,
                              void* d_out, int out_size)
{
    const float* x    = (const float*)d_in[0];
    const float* Wq   = (const float*)d_in[1];
    const float* Wk   = (const float*)d_in[2];
    const float* Wv   = (const float*)d_in[3];
    const float* Wo   = (const float*)d_in[4];
    const float* bo   = (const float*)d_in[5];
    const float* W1   = (const float*)d_in[6];
    const float* b1   = (const float*)d_in[7];
    const float* W2   = (const float*)d_in[8];
    const float* b2   = (const float*)d_in[9];
    const float* g1   = (const float*)d_in[10];
    const float* be1  = (const float*)d_in[11];
    const float* g2   = (const float*)d_in[12];
    const float* be2  = (const float*)d_in[13];
    float* out = (float*)d_out;

    __half *h, *qkv, *attn, *h2, *ff1, *wqkv, *wo, *w1, *w2;
    float *x2;
    cudaGetSymbolAddress((void**)&h,    g_h);
    cudaGetSymbolAddress((void**)&qkv,  g_qkv);
    cudaGetSymbolAddress((void**)&attn, g_attn);
    cudaGetSymbolAddress((void**)&x2,   g_x2);
    cudaGetSymbolAddress((void**)&h2,   g_h2);
    cudaGetSymbolAddress((void**)&ff1,  g_ff1);
    cudaGetSymbolAddress((void**)&wqkv, g_wqkv);
    cudaGetSymbolAddress((void**)&wo,   g_wo);
    cudaGetSymbolAddress((void**)&w1,   g_w1);
    cudaGetSymbolAddress((void**)&w2,   g_w2);

    cudaFuncSetAttribute(attn_h,
                         cudaFuncAttributeMaxDynamicSharedMemorySize, ATTN_SMEM);
    cudaFuncSetAttribute(gemm_h,
                         cudaFuncAttributeMaxDynamicSharedMemorySize, GEMM_SMEM);

    // 0) weight preprocessing: transpose to [N][K] fp16
    dim3 tb(32, 8);
    transpose_h_kernel<<<dim3(32, 32),  tb>>>(Wq, wqkv,                    DD, DD);
    transpose_h_kernel<<<dim3(32, 32),  tb>>>(Wk, wqkv + (size_t)DD * DD,  DD, DD);
    transpose_h_kernel<<<dim3(32, 32),  tb>>>(Wv, wqkv + (size_t)2 * DD * DD, DD, DD);
    transpose_h_kernel<<<dim3(32, 32),  tb>>>(Wo, wo, DD, DD);
    transpose_h_kernel<<<dim3(128, 32), tb>>>(W1, w1, DD, FF);
    transpose_h_kernel<<<dim3(32, 128), tb>>>(W2, w2, FF, DD);

    // 1) LN1 -> fp16
    layernorm_kernel<<<MM, 256>>>(x, g1, be1, h);

    // 2) fused QKV projection -> fp16
    gemm_h<<<dim3(3 * DD / 256, MM / 128), 256, GEMM_SMEM>>>(
        h, wqkv, nullptr, nullptr, qkv, 3 * DD, DD, 3);

    // 3) causal attention (fp16 tensor cores)
    attn_h<<<dim3(TT / 64, BB * HH), 128, ATTN_SMEM>>>(qkv, attn);

    // 4) output projection + bias + residual(x) -> fp32
    dim3 gDD(DD / 256, MM / 128);
    gemm_h<<<gDD, 256, GEMM_SMEM>>>(attn, wo, bo, x, x2, DD, DD, 2);

    // 5) LN2 -> fp16
    layernorm_kernel<<<MM, 256>>>(x2, g2, be2, h2);

    // 6) FFN1 + bias + GELU -> fp16
    gemm_h<<<dim3(FF / 256, MM / 128), 256, GEMM_SMEM>>>(
        h2, w1, b1, nullptr, ff1, FF, DD, 1);

    // 7) FFN2 + bias + residual(x2) -> out (fp32)
    gemm_h<<<gDD, 256, GEMM_SMEM>>>(ff1, w2, b2, x2, out, DD, FF, 2);
}

// round 11
// speedup vs baseline: 6.3126x; 1.0050x over previous
#include <cuda_runtime.h>
#include <cuda_fp16.h>
#include <math.h>
#include <stdint.h>

// ---------------------------------------------------------------------------
// Problem constants
// ---------------------------------------------------------------------------
#define BB 4
#define TT 2048
#define DD 1024
#define HH 16
#define HD 64
#define FF 4096
#define MM (BB * TT)       // 8192 rows
#define EPS 1e-5f

// ---------------------------------------------------------------------------
// Scratch (allocation-free: __device__ globals)
// ---------------------------------------------------------------------------
__device__ __half g_h   [(size_t)MM * DD];      // LN1 out (fp16)
__device__ __half g_qkv [(size_t)MM * 3 * DD];  // QKV out (fp16)
__device__ __half g_attn[(size_t)MM * DD];      // attention out (fp16)
__device__ float  g_x2  [(size_t)MM * DD];      // residual stream 2 (fp32)
__device__ __half g_h2  [(size_t)MM * DD];      // LN2 out (fp16)
__device__ __half g_ff1 [(size_t)MM * FF];      // FFN1 out (fp16)
// fp16 weights, transposed to [N][K]
__device__ __half g_wqkv[(size_t)(3 * DD) * DD];
__device__ __half g_wo  [(size_t)DD * DD];
__device__ __half g_w1  [(size_t)FF * DD];
__device__ __half g_w2  [(size_t)DD * FF];

// ---------------------------------------------------------------------------
// helpers
// ---------------------------------------------------------------------------
__device__ __forceinline__ void mma_f16(float c[4], const uint32_t a[4],
                                        const uint32_t b[2]) {
    asm volatile(
        "mma.sync.aligned.m16n8k16.row.col.f32.f16.f16.f32 "
        "{%0,%1,%2,%3}, {%4,%5,%6,%7}, {%8,%9}, {%0,%1,%2,%3};"
        : "+f"(c[0]), "+f"(c[1]), "+f"(c[2]), "+f"(c[3])
        : "r"(a[0]), "r"(a[1]), "r"(a[2]), "r"(a[3]), "r"(b[0]), "r"(b[1]));
}
__device__ __forceinline__ void ldsm_x4(uint32_t r[4], uint32_t saddr) {
    asm volatile("ldmatrix.sync.aligned.m8n8.x4.shared.b16 {%0,%1,%2,%3}, [%4];"
        : "=r"(r[0]), "=r"(r[1]), "=r"(r[2]), "=r"(r[3]) : "r"(saddr));
}
__device__ __forceinline__ void ldsm_x4_t(uint32_t r[4], uint32_t saddr) {
    asm volatile("ldmatrix.sync.aligned.m8n8.x4.trans.shared.b16 {%0,%1,%2,%3}, [%4];"
        : "=r"(r[0]), "=r"(r[1]), "=r"(r[2]), "=r"(r[3]) : "r"(saddr));
}
__device__ __forceinline__ void cp_async16(uint32_t saddr, const void* gptr) {
    asm volatile("cp.async.cg.shared.global [%0], [%1], 16;"
                 :: "r"(saddr), "l"(gptr) : "memory");
}
__device__ __forceinline__ void cp_commit() {
    asm volatile("cp.async.commit_group;" ::: "memory");
}
template <int N>
__device__ __forceinline__ void cp_wait() {
    asm volatile("cp.async.wait_group %0;" :: "n"(N) : "memory");
}
__device__ __forceinline__ uint32_t smem_u32(const void* p) {
    uint32_t a;
    asm("{ .reg .u64 t; cvta.to.shared.u64 t, %1; cvt.u32.u64 %0, t; }"
        : "=r"(a) : "l"(p));
    return a;
}

// ---------------------------------------------------------------------------
// Weight preprocessing: all 6 transposes ([R][C] fp32 -> [C][R] fp16) fused
// into one launch. 1-D grid of 12288 blocks:
//   [0, 4096):   four DD x DD transposes (Wq, Wk, Wv -> wqkv slices, Wo -> wo)
//   [4096, 8192): W1 (DD x FF), grid 128 x 32
//   [8192,12288): W2 (FF x DD), grid 32 x 128
// ---------------------------------------------------------------------------
__global__ __launch_bounds__(256) void transpose_all_kernel(
    const float* __restrict__ Wq, const float* __restrict__ Wk,
    const float* __restrict__ Wv, const float* __restrict__ Wo,
    const float* __restrict__ W1, const float* __restrict__ W2,
    __half* __restrict__ wqkv, __half* __restrict__ wo,
    __half* __restrict__ w1, __half* __restrict__ w2)
{
    const int id = blockIdx.x;
    const float* in;
    __half* out;
    int R, C, bx, by;
    if (id < 4096) {
        const int w = id >> 10, t = id & 1023;
        bx = t & 31; by = t >> 5;
        R = DD; C = DD;
        if (w == 0)      { in = Wq; out = wqkv; }
        else if (w == 1) { in = Wk; out = wqkv + (size_t)DD * DD; }
        else if (w == 2) { in = Wv; out = wqkv + (size_t)2 * DD * DD; }
        else             { in = Wo; out = wo; }
    } else if (id < 8192) {
        const int t = id - 4096;
        bx = t & 127; by = t >> 7;
        in = W1; out = w1; R = DD; C = FF;
    } else {
        const int t = id - 8192;
        bx = t & 31; by = t >> 5;
        in = W2; out = w2; R = FF; C = DD;
    }

    __shared__ float tl[32][33];
    const int c0 = bx * 32;
    const int r0 = by * 32;
    const int tx = threadIdx.x & 31, ty = threadIdx.x >> 5;
    #pragma unroll
    for (int i = 0; i < 32; i += 8)
        tl[ty + i][tx] = in[(size_t)(r0 + ty + i) * C + c0 + tx];
    __syncthreads();
    #pragma unroll
    for (int i = 0; i < 32; i += 8)
        out[(size_t)(c0 + ty + i) * R + r0 + tx] = __float2half_rn(tl[tx][ty + i]);
}

// ---------------------------------------------------------------------------
// LayerNorm: one block (256 threads) per row of 1024; writes fp16
// ---------------------------------------------------------------------------
__global__ __launch_bounds__(256) void layernorm_kernel(
    const float* __restrict__ x, const float* __restrict__ gamma,
    const float* __restrict__ beta, __half* __restrict__ out)
{
    __shared__ float shs[8], shss[8];
    __shared__ float s_mean, s_inv;
    const int row = blockIdx.x;
    const int tid = threadIdx.x;

    const float4 xv = *(const float4*)(x + (size_t)row * DD + tid * 4);
    float s  = xv.x + xv.y + xv.z + xv.w;
    float ss = xv.x * xv.x + xv.y * xv.y + xv.z * xv.z + xv.w * xv.w;
    #pragma unroll
    for (int o = 16; o > 0; o >>= 1) {
        s  += __shfl_down_sync(0xffffffffu, s, o);
        ss += __shfl_down_sync(0xffffffffu, ss, o);
    }
    if ((tid & 31) == 0) { shs[tid >> 5] = s; shss[tid >> 5] = ss; }
    __syncthreads();
    if (tid == 0) {
        float S = 0.f, SS = 0.f;
        #pragma unroll
        for (int i = 0; i < 8; i++) { S += shs[i]; SS += shss[i]; }
        float mean = S * (1.0f / DD);
        float var  = SS * (1.0f / DD) - mean * mean;
        s_mean = mean;
        s_inv  = rsqrtf(var + EPS);
    }
    __syncthreads();
    const float mean = s_mean, inv = s_inv;
    const float4 gv = *(const float4*)(gamma + tid * 4);
    const float4 bv = *(const float4*)(beta  + tid * 4);
    __half2 o01 = __floats2half2_rn(gv.x * (xv.x - mean) * inv + bv.x,
                                    gv.y * (xv.y - mean) * inv + bv.y);
    __half2 o23 = __floats2half2_rn(gv.z * (xv.z - mean) * inv + bv.z,
                                    gv.w * (xv.w - mean) * inv + bv.w);
    *(__half2*)(out + (size_t)row * DD + tid * 4)     = o01;
    *(__half2*)(out + (size_t)row * DD + tid * 4 + 2) = o23;
}

// ---------------------------------------------------------------------------
// GELU (tanh approximation, matches reference)
// ---------------------------------------------------------------------------
__device__ __forceinline__ float gelu_f(float x)
{
    const float c = 0.7978845608028654f;  // sqrt(2/pi)
    float inner = c * (x + 0.044715f * x * x * x);
    return 0.5f * x * (1.0f + tanhf(inner));
}

// ---------------------------------------------------------------------------
// fp16 tensor-core GEMM:  C[M,N] = A[M,K] @ Bt[N,K]^T  (+bias)(+gelu)(+resid)
// A, Bt fp16; fp32 accumulate. CTA tile 128x256, BK=32, 256 threads, 8 warps
// (2x4), warp tile 64x64, m16n8k16, ldmatrix operand fetch.
// cp.async 4-stage pipeline. smem rows (32 halves data) padded to 80 B.
// mode: 0 = fp32 out plain, 1 = fp16 out bias+gelu, 2 = fp32 out bias+resid,
//       3 = fp16 out plain
// ---------------------------------------------------------------------------
#define A_BYTES (128 * 80)          // 10240
#define B_BYTES (256 * 80)          // 20480
#define STG (A_BYTES + B_BYTES)     // 30720
#define NSF 4
#define GEMM_SMEM (NSF * STG)       // 122880

__global__ __launch_bounds__(256, 1) void gemm_h(
    const __half* __restrict__ A, const __half* __restrict__ Bt,
    const float* __restrict__ bias,   // may be null
    const float* __restrict__ resid,  // may be null
    void* __restrict__ Cout,
    int Ndim, int Kdim, int mode)
{
    extern __shared__ __align__(16) char smg[];
    const uint32_t sbase = smem_u32(smg);
    const int tid  = threadIdx.x;
    const int lane = tid & 31;
    const int warp = tid >> 5;
    const int wm   = warp >> 2;     // 0..1
    const int wn   = warp & 3;      // 0..3
    const int gid  = lane >> 2;     // 0..7
    const int tg   = lane & 3;      // 0..3
    const int m0 = blockIdx.y * 128;
    const int n0 = blockIdx.x * 256;

    // ldmatrix per-lane offsets (within a stage)
    const uint32_t aoff = (uint32_t)(wm * 64 + (lane & 15)) * 80 + (lane >> 4) * 16;
    const uint32_t boff = A_BYTES +
        (uint32_t)(wn * 64 + (lane & 7) + (lane >> 4) * 8) * 80 +
        ((lane >> 3) & 1) * 16;

    float acc[4][8][4];
    #pragma unroll
    for (int mt = 0; mt < 4; mt++)
        #pragma unroll
        for (int nt = 0; nt < 8; nt++)
            #pragma unroll
            for (int r = 0; r < 4; r++) acc[mt][nt][r] = 0.f;

    const int nkb = Kdim / 32;

    auto issue = [&](int kb, int slot) {
        const uint32_t sb = sbase + slot * STG;
        #pragma unroll
        for (int p = 0; p < 2; p++) {
            const int id = tid + 256 * p;
            const int row = id >> 2, cc = id & 3;
            cp_async16(sb + row * 80 + cc * 16,
                       A + (size_t)(m0 + row) * Kdim + kb * 32 + cc * 8);
        }
        #pragma unroll
        for (int p = 0; p < 4; p++) {
            const int id = tid + 256 * p;
            const int row = id >> 2, cc = id & 3;
            cp_async16(sb + A_BYTES + row * 80 + cc * 16,
                       Bt + (size_t)(n0 + row) * Kdim + kb * 32 + cc * 8);
        }
    };

    issue(0, 0); cp_commit();
    issue(1, 1); cp_commit();
    issue(2, 2); cp_commit();

    int s_cur = 0, s_nxt = 3;

    for (int kb = 0; kb < nkb; kb++) {
        cp_wait<2>();
        __syncthreads();
        if (kb + 3 < nkb) issue(kb + 3, s_nxt);
        cp_commit();

        const uint32_t sA = sbase + s_cur * STG + aoff;
        const uint32_t sB = sbase + s_cur * STG + boff;

        #pragma unroll
        for (int ks = 0; ks < 2; ks++) {
            uint32_t af[4][4], bf[8][2];
            #pragma unroll
            for (int mt = 0; mt < 4; mt++)
                ldsm_x4(af[mt], sA + mt * 1280 + ks * 32);
            #pragma unroll
            for (int ntp = 0; ntp < 4; ntp++) {
                uint32_t t[4];
                ldsm_x4(t, sB + ntp * 1280 + ks * 32);
                bf[2 * ntp][0] = t[0]; bf[2 * ntp][1] = t[1];
                bf[2 * ntp + 1][0] = t[2]; bf[2 * ntp + 1][1] = t[3];
            }
            #pragma unroll
            for (int mt = 0; mt < 4; mt++)
                #pragma unroll
                for (int nt = 0; nt < 8; nt++)
                    mma_f16(acc[mt][nt], af[mt], bf[nt]);
        }

        s_cur = s_cur + 1 == NSF ? 0 : s_cur + 1;
        s_nxt = s_nxt + 1 == NSF ? 0 : s_nxt + 1;
    }

    // epilogue
    #pragma unroll
    for (int mt = 0; mt < 4; mt++) {
        #pragma unroll
        for (int half = 0; half < 2; half++) {
            const int row = m0 + wm * 64 + mt * 16 + gid + half * 8;
            #pragma unroll
            for (int nt = 0; nt < 8; nt++) {
                const int col = n0 + wn * 64 + nt * 8 + 2 * tg;
                float v0 = acc[mt][nt][half * 2 + 0];
                float v1 = acc[mt][nt][half * 2 + 1];
                if (bias) { v0 += bias[col]; v1 += bias[col + 1]; }
                if (mode == 1) {
                    __half2 h2 = __floats2half2_rn(gelu_f(v0), gelu_f(v1));
                    *(__half2*)((__half*)Cout + (size_t)row * Ndim + col) = h2;
                } else if (mode == 3) {
                    __half2 h2 = __floats2half2_rn(v0, v1);
                    *(__half2*)((__half*)Cout + (size_t)row * Ndim + col) = h2;
                } else {
                    if (resid) {
                        const float* Rr = resid + (size_t)row * Ndim;
                        v0 += Rr[col]; v1 += Rr[col + 1];
                    }
                    float2 o; o.x = v0; o.y = v1;
                    *(float2*)((float*)Cout + (size_t)row * Ndim + col) = o;
                }
            }
        }
    }
}

// ---------------------------------------------------------------------------
// fp16 tensor-core causal flash attention (m16n8k16, fp32 accum/softmax).
// qkv fp16 packed (row stride 3*DD halves); out fp16 [M, D] (b,t,h,hd).
// 64x64 tiles, 128 threads / 4 warps; warp owns 16 q-rows.
// K/V tiles DOUBLE BUFFERED via cp.async: tile kt+1 streams during kt compute.
// smem tiles: 64 rows x 128 B data, 144-B row stride (conflict-free ldmatrix).
// Layout: Q, K0, V0, K1, V1, P = 6 x 9216 B = 54 KB.
// ---------------------------------------------------------------------------
#define AQSTR (3 * DD)
#define ARSTR 144                   // bytes per smem row
#define ATILE_B (64 * ARSTR)        // 9216
#define ATTN_SMEM (6 * ATILE_B)     // 55296

__global__ __launch_bounds__(128) void attn_h(
    const __half* __restrict__ qkv, __half* __restrict__ out)
{
    extern __shared__ __align__(16) char sma[];
    const uint32_t sb = smem_u32(sma);
    const uint32_t Qb = sb;
    // K(i) at 1 + 2i tiles, V(i) at 2 + 2i tiles
    const uint32_t Pb = sb + 5 * ATILE_B;
    __half* Ps = (__half*)(sma + 5 * ATILE_B);

    const int tid  = threadIdx.x;
    const int lane = tid & 31;
    const int warp = tid >> 5;
    const int gid  = lane >> 2;
    const int tg   = lane & 3;
    const int bh = blockIdx.y;
    const int b  = bh / HH;
    const int h  = bh % HH;
    const int qt = blockIdx.x;
    const int q0 = qt * 64;

    const size_t qbase = ((size_t)b * TT) * AQSTR + (size_t)h * HD;
    const size_t obase = ((size_t)b * TT) * DD + (size_t)h * HD;

    auto issue_kv = [&](int kt_i, int buf) {
        const int k0i = kt_i * 64;
        const uint32_t Kb = sb + (1 + 2 * buf) * ATILE_B;
        const uint32_t Vb = sb + (2 + 2 * buf) * ATILE_B;
        const __half* ksrc = qkv + qbase + DD     + (size_t)k0i * AQSTR;
        const __half* vsrc = qkv + qbase + 2 * DD + (size_t)k0i * AQSTR;
        #pragma unroll
        for (int p = 0; p < 4; p++) {
            const int id = tid + 128 * p;
            const int r = id >> 3, c = id & 7;
            cp_async16(Kb + r * ARSTR + c * 16, ksrc + (size_t)r * AQSTR + c * 8);
        }
        #pragma unroll
        for (int p = 0; p < 4; p++) {
            const int id = tid + 128 * p;
            const int r = id >> 3, c = id & 7;
            cp_async16(Vb + r * ARSTR + c * 16, vsrc + (size_t)r * AQSTR + c * 8);
        }
    };

    // prologue: Q tile + KV(0)
    {
        const __half* src = qkv + qbase + (size_t)q0 * AQSTR;
        #pragma unroll
        for (int p = 0; p < 4; p++) {
            const int id = tid + 128 * p;
            const int r = id >> 3, c = id & 7;
            cp_async16(Qb + r * ARSTR + c * 16, src + (size_t)r * AQSTR + c * 8);
        }
        cp_commit();
    }
    issue_kv(0, 0);
    cp_commit();

    float mrow[2] = {-1e30f, -1e30f};
    float lrow[2] = {0.f, 0.f};
    float o[8][4];
    #pragma unroll
    for (int nf = 0; nf < 8; nf++)
        #pragma unroll
        for (int c = 0; c < 4; c++) o[nf][c] = 0.f;

    // ldmatrix per-lane offsets
    const uint32_t qp_off = (uint32_t)(warp * 16 + (lane & 15)) * ARSTR +
                            (lane >> 4) * 16;
    const uint32_t kp_off = (uint32_t)((lane & 7) + (lane >> 4) * 8) * ARSTR +
                            ((lane >> 3) & 1) * 16;
    const uint32_t vp_off = (uint32_t)((lane & 7) + ((lane >> 3) & 1) * 8) * ARSTR +
                            (lane >> 4) * 16;

    for (int kt = 0; kt <= qt; kt++) {
        const int cur = kt & 1;
        __syncthreads();   // all warps done reading buf cur^1 (iteration kt-1)
        if (kt < qt) {
            issue_kv(kt + 1, cur ^ 1);
            cp_commit();
            cp_wait<1>();  // current tile (and Q) landed; next still in flight
        } else {
            cp_wait<0>();
        }
        __syncthreads();

        const uint32_t Kc = sb + (1 + 2 * cur) * ATILE_B;
        const uint32_t Vc = sb + (2 + 2 * cur) * ATILE_B;

        // S = Q K^T  (warp: 16 x 64)
        float s[8][4];
        #pragma unroll
        for (int nf = 0; nf < 8; nf++)
            #pragma unroll
            for (int c = 0; c < 4; c++) s[nf][c] = 0.f;
        #pragma unroll
        for (int ks = 0; ks < 4; ks++) {
            uint32_t aq[4];
            ldsm_x4(aq, Qb + qp_off + ks * 32);
            #pragma unroll
            for (int ntp = 0; ntp < 4; ntp++) {
                uint32_t t[4];
                ldsm_x4(t, Kc + kp_off + ntp * 16 * ARSTR + ks * 32);
                uint32_t b0[2] = {t[0], t[1]};
                uint32_t b1[2] = {t[2], t[3]};
                mma_f16(s[2 * ntp],     aq, b0);
                mma_f16(s[2 * ntp + 1], aq, b1);
            }
        }

        // scale + causal mask
        const float scale = 0.125f;
        const bool diag = (kt == qt);
        #pragma unroll
        for (int nf = 0; nf < 8; nf++) {
            #pragma unroll
            for (int c = 0; c < 4; c++) {
                float val = s[nf][c] * scale;
                if (diag) {
                    int row = warp * 16 + gid + (c >= 2 ? 8 : 0);
                    int col = nf * 8 + 2 * tg + (c & 1);
                    if (col > row) val = -1e30f;
                }
                s[nf][c] = val;
            }
        }

        // online softmax (rows gid / gid+8; reduce over tg lanes)
        float mx0 = -1e30f, mx1 = -1e30f;
        #pragma unroll
        for (int nf = 0; nf < 8; nf++) {
            mx0 = fmaxf(mx0, fmaxf(s[nf][0], s[nf][1]));
            mx1 = fmaxf(mx1, fmaxf(s[nf][2], s[nf][3]));
        }
        #pragma unroll
        for (int w = 1; w <= 2; w <<= 1) {
            mx0 = fmaxf(mx0, __shfl_xor_sync(0xffffffffu, mx0, w));
            mx1 = fmaxf(mx1, __shfl_xor_sync(0xffffffffu, mx1, w));
        }
        float mn0 = fmaxf(mrow[0], mx0);
        float mn1 = fmaxf(mrow[1], mx1);
        float al0 = __expf(mrow[0] - mn0);
        float al1 = __expf(mrow[1] - mn1);

        float sum0 = 0.f, sum1 = 0.f;
        #pragma unroll
        for (int nf = 0; nf < 8; nf++) {
            s[nf][0] = __expf(s[nf][0] - mn0);
            s[nf][1] = __expf(s[nf][1] - mn0);
            s[nf][2] = __expf(s[nf][2] - mn1);
            s[nf][3] = __expf(s[nf][3] - mn1);
            sum0 += s[nf][0] + s[nf][1];
            sum1 += s[nf][2] + s[nf][3];
        }
        #pragma unroll
        for (int w = 1; w <= 2; w <<= 1) {
            sum0 += __shfl_xor_sync(0xffffffffu, sum0, w);
            sum1 += __shfl_xor_sync(0xffffffffu, sum1, w);
        }
        lrow[0] = lrow[0] * al0 + sum0;
        lrow[1] = lrow[1] * al1 + sum1;
        mrow[0] = mn0;
        mrow[1] = mn1;

        // store P (fp16; warp-private rows; 72-half row stride)
        #pragma unroll
        for (int nf = 0; nf < 8; nf++) {
            *(__half2*)(Ps + (warp * 16 + gid) * 72 + nf * 8 + 2 * tg) =
                __floats2half2_rn(s[nf][0], s[nf][1]);
            *(__half2*)(Ps + (warp * 16 + gid + 8) * 72 + nf * 8 + 2 * tg) =
                __floats2half2_rn(s[nf][2], s[nf][3]);
        }
        // rescale accumulator
        #pragma unroll
        for (int nf = 0; nf < 8; nf++) {
            o[nf][0] *= al0; o[nf][1] *= al0;
            o[nf][2] *= al1; o[nf][3] *= al1;
        }
        __syncwarp();

        // O += P V  (V consumed via ldmatrix.trans)
        #pragma unroll
        for (int ks = 0; ks < 4; ks++) {
            uint32_t ap[4];
            ldsm_x4(ap, Pb + qp_off + ks * 32);
            #pragma unroll
            for (int ntp = 0; ntp < 4; ntp++) {
                uint32_t t[4];
                ldsm_x4_t(t, Vc + vp_off + ks * 16 * ARSTR + ntp * 32);
                uint32_t b0[2] = {t[0], t[1]};
                uint32_t b1[2] = {t[2], t[3]};
                mma_f16(o[2 * ntp],     ap, b0);
                mma_f16(o[2 * ntp + 1], ap, b1);
            }
        }
    }

    const float inv0 = 1.0f / lrow[0];
    const float inv1 = 1.0f / lrow[1];
    const int r0 = q0 + warp * 16 + gid;
    #pragma unroll
    for (int nf = 0; nf < 8; nf++) {
        const int col = nf * 8 + 2 * tg;
        __half2 w0 = __floats2half2_rn(o[nf][0] * inv0, o[nf][1] * inv0);
        __half2 w1 = __floats2half2_rn(o[nf][2] * inv1, o[nf][3] * inv1);
        *(__half2*)(out + obase + (size_t)r0 * DD + col)       = w0;
        *(__half2*)(out + obase + (size_t)(r0 + 8) * DD + col) = w1;
    }
}

// ---------------------------------------------------------------------------
// Host launch
// ---------------------------------------------------------------------------
extern "C" void kernel_launch(void* const* d_in, const int* in_sizes, int n_in,
                              void* d_out, int out_size)
{
    const float* x    = (const float*)d_in[0];
    const float* Wq   = (const float*)d_in[1];
    const float* Wk   = (const float*)d_in[2];
    const float* Wv   = (const float*)d_in[3];
    const float* Wo   = (const float*)d_in[4];
    const float* bo   = (const float*)d_in[5];
    const float* W1   = (const float*)d_in[6];
    const float* b1   = (const float*)d_in[7];
    const float* W2   = (const float*)d_in[8];
    const float* b2   = (const float*)d_in[9];
    const float* g1   = (const float*)d_in[10];
    const float* be1  = (const float*)d_in[11];
    const float* g2   = (const float*)d_in[12];
    const float* be2  = (const float*)d_in[13];
    float* out = (float*)d_out;

    __half *h, *qkv, *attn, *h2, *ff1, *wqkv, *wo, *w1, *w2;
    float *x2;
    cudaGetSymbolAddress((void**)&h,    g_h);
    cudaGetSymbolAddress((void**)&qkv,  g_qkv);
    cudaGetSymbolAddress((void**)&attn, g_attn);
    cudaGetSymbolAddress((void**)&x2,   g_x2);
    cudaGetSymbolAddress((void**)&h2,   g_h2);
    cudaGetSymbolAddress((void**)&ff1,  g_ff1);
    cudaGetSymbolAddress((void**)&wqkv, g_wqkv);
    cudaGetSymbolAddress((void**)&wo,   g_wo);
    cudaGetSymbolAddress((void**)&w1,   g_w1);
    cudaGetSymbolAddress((void**)&w2,   g_w2);

    cudaFuncSetAttribute(attn_h,
                         cudaFuncAttributeMaxDynamicSharedMemorySize, ATTN_SMEM);
    cudaFuncSetAttribute(gemm_h,
                         cudaFuncAttributeMaxDynamicSharedMemorySize, GEMM_SMEM);

    // 0) weight preprocessing: all transposes in one launch
    transpose_all_kernel<<<12288, 256>>>(Wq, Wk, Wv, Wo, W1, W2,
                                         wqkv, wo, w1, w2);

    // 1) LN1 -> fp16
    layernorm_kernel<<<MM, 256>>>(x, g1, be1, h);

    // 2) fused QKV projection -> fp16
    gemm_h<<<dim3(3 * DD / 256, MM / 128), 256, GEMM_SMEM>>>(
        h, wqkv, nullptr, nullptr, qkv, 3 * DD, DD, 3);

    // 3) causal attention (fp16 tensor cores, double-buffered K/V)
    attn_h<<<dim3(TT / 64, BB * HH), 128, ATTN_SMEM>>>(qkv, attn);

    // 4) output projection + bias + residual(x) -> fp32
    dim3 gDD(DD / 256, MM / 128);
    gemm_h<<<gDD, 256, GEMM_SMEM>>>(attn, wo, bo, x, x2, DD, DD, 2);

    // 5) LN2 -> fp16
    layernorm_kernel<<<MM, 256>>>(x2, g2, be2, h2);

    // 6) FFN1 + bias + GELU -> fp16
    gemm_h<<<dim3(FF / 256, MM / 128), 256, GEMM_SMEM>>>(
        h2, w1, b1, nullptr, ff1, FF, DD, 1);

    // 7) FFN2 + bias + residual(x2) -> out (fp32)
    gemm_h<<<gDD, 256, GEMM_SMEM>>>(ff1, w2, b2, x2, out, DD, FF, 2);
}

// round 12
// speedup vs baseline: 6.4113x; 1.0156x over previous
#include <cuda_runtime.h>
#include <cuda_fp16.h>
#include <math.h>
#include <stdint.h>

// ---------------------------------------------------------------------------
// Problem constants
// ---------------------------------------------------------------------------
#define BB 4
#define TT 2048
#define DD 1024
#define HH 16
#define HD 64
#define FF 4096
#define MM (BB * TT)       // 8192 rows
#define EPS 1e-5f

// ---------------------------------------------------------------------------
// Scratch (allocation-free: __device__ globals)
// ---------------------------------------------------------------------------
__device__ __half g_h   [(size_t)MM * DD];      // LN1 out (fp16)
__device__ __half g_qkv [(size_t)MM * 3 * DD];  // QKV out (fp16)
__device__ __half g_attn[(size_t)MM * DD];      // attention out (fp16)
__device__ float  g_x2  [(size_t)MM * DD];      // residual stream 2 (fp32)
__device__ __half g_h2  [(size_t)MM * DD];      // LN2 out (fp16)
__device__ __half g_ff1 [(size_t)MM * FF];      // FFN1 out (fp16)
// fp16 weights, transposed to [N][K]
__device__ __half g_wqkv[(size_t)(3 * DD) * DD];
__device__ __half g_wo  [(size_t)DD * DD];
__device__ __half g_w1  [(size_t)FF * DD];
__device__ __half g_w2  [(size_t)DD * FF];

// ---------------------------------------------------------------------------
// helpers
// ---------------------------------------------------------------------------
__device__ __forceinline__ void mma_f16(float c[4], const uint32_t a[4],
                                        const uint32_t b[2]) {
    asm volatile(
        "mma.sync.aligned.m16n8k16.row.col.f32.f16.f16.f32 "
        "{%0,%1,%2,%3}, {%4,%5,%6,%7}, {%8,%9}, {%0,%1,%2,%3};"
        : "+f"(c[0]), "+f"(c[1]), "+f"(c[2]), "+f"(c[3])
        : "r"(a[0]), "r"(a[1]), "r"(a[2]), "r"(a[3]), "r"(b[0]), "r"(b[1]));
}
__device__ __forceinline__ void ldsm_x4(uint32_t r[4], uint32_t saddr) {
    asm volatile("ldmatrix.sync.aligned.m8n8.x4.shared.b16 {%0,%1,%2,%3}, [%4];"
        : "=r"(r[0]), "=r"(r[1]), "=r"(r[2]), "=r"(r[3]) : "r"(saddr));
}
__device__ __forceinline__ void ldsm_x4_t(uint32_t r[4], uint32_t saddr) {
    asm volatile("ldmatrix.sync.aligned.m8n8.x4.trans.shared.b16 {%0,%1,%2,%3}, [%4];"
        : "=r"(r[0]), "=r"(r[1]), "=r"(r[2]), "=r"(r[3]) : "r"(saddr));
}
__device__ __forceinline__ void cp_async16(uint32_t saddr, const void* gptr) {
    asm volatile("cp.async.cg.shared.global [%0], [%1], 16;"
                 :: "r"(saddr), "l"(gptr) : "memory");
}
__device__ __forceinline__ void cp_commit() {
    asm volatile("cp.async.commit_group;" ::: "memory");
}
template <int N>
__device__ __forceinline__ void cp_wait() {
    asm volatile("cp.async.wait_group %0;" :: "n"(N) : "memory");
}
__device__ __forceinline__ uint32_t smem_u32(const void* p) {
    uint32_t a;
    asm("{ .reg .u64 t; cvta.to.shared.u64 t, %1; cvt.u32.u64 %0, t; }"
        : "=r"(a) : "l"(p));
    return a;
}
__device__ __forceinline__ uint32_t pack_h2(float a, float b) {
    __half2 h = __floats2half2_rn(a, b);
    return *(uint32_t*)&h;
}

// ---------------------------------------------------------------------------
// Weight preprocessing: all 6 transposes ([R][C] fp32 -> [C][R] fp16) fused
// into one launch.
// ---------------------------------------------------------------------------
__global__ __launch_bounds__(256) void transpose_all_kernel(
    const float* __restrict__ Wq, const float* __restrict__ Wk,
    const float* __restrict__ Wv, const float* __restrict__ Wo,
    const float* __restrict__ W1, const float* __restrict__ W2,
    __half* __restrict__ wqkv, __half* __restrict__ wo,
    __half* __restrict__ w1, __half* __restrict__ w2)
{
    const int id = blockIdx.x;
    const float* in;
    __half* out;
    int R, C, bx, by;
    if (id < 4096) {
        const int w = id >> 10, t = id & 1023;
        bx = t & 31; by = t >> 5;
        R = DD; C = DD;
        if (w == 0)      { in = Wq; out = wqkv; }
        else if (w == 1) { in = Wk; out = wqkv + (size_t)DD * DD; }
        else if (w == 2) { in = Wv; out = wqkv + (size_t)2 * DD * DD; }
        else             { in = Wo; out = wo; }
    } else if (id < 8192) {
        const int t = id - 4096;
        bx = t & 127; by = t >> 7;
        in = W1; out = w1; R = DD; C = FF;
    } else {
        const int t = id - 8192;
        bx = t & 31; by = t >> 5;
        in = W2; out = w2; R = FF; C = DD;
    }

    __shared__ float tl[32][33];
    const int c0 = bx * 32;
    const int r0 = by * 32;
    const int tx = threadIdx.x & 31, ty = threadIdx.x >> 5;
    #pragma unroll
    for (int i = 0; i < 32; i += 8)
        tl[ty + i][tx] = in[(size_t)(r0 + ty + i) * C + c0 + tx];
    __syncthreads();
    #pragma unroll
    for (int i = 0; i < 32; i += 8)
        out[(size_t)(c0 + ty + i) * R + r0 + tx] = __float2half_rn(tl[tx][ty + i]);
}

// ---------------------------------------------------------------------------
// LayerNorm: one block (256 threads) per row of 1024; writes fp16
// ---------------------------------------------------------------------------
__global__ __launch_bounds__(256) void layernorm_kernel(
    const float* __restrict__ x, const float* __restrict__ gamma,
    const float* __restrict__ beta, __half* __restrict__ out)
{
    __shared__ float shs[8], shss[8];
    __shared__ float s_mean, s_inv;
    const int row = blockIdx.x;
    const int tid = threadIdx.x;

    const float4 xv = *(const float4*)(x + (size_t)row * DD + tid * 4);
    float s  = xv.x + xv.y + xv.z + xv.w;
    float ss = xv.x * xv.x + xv.y * xv.y + xv.z * xv.z + xv.w * xv.w;
    #pragma unroll
    for (int o = 16; o > 0; o >>= 1) {
        s  += __shfl_down_sync(0xffffffffu, s, o);
        ss += __shfl_down_sync(0xffffffffu, ss, o);
    }
    if ((tid & 31) == 0) { shs[tid >> 5] = s; shss[tid >> 5] = ss; }
    __syncthreads();
    if (tid == 0) {
        float S = 0.f, SS = 0.f;
        #pragma unroll
        for (int i = 0; i < 8; i++) { S += shs[i]; SS += shss[i]; }
        float mean = S * (1.0f / DD);
        float var  = SS * (1.0f / DD) - mean * mean;
        s_mean = mean;
        s_inv  = rsqrtf(var + EPS);
    }
    __syncthreads();
    const float mean = s_mean, inv = s_inv;
    const float4 gv = *(const float4*)(gamma + tid * 4);
    const float4 bv = *(const float4*)(beta  + tid * 4);
    __half2 o01 = __floats2half2_rn(gv.x * (xv.x - mean) * inv + bv.x,
                                    gv.y * (xv.y - mean) * inv + bv.y);
    __half2 o23 = __floats2half2_rn(gv.z * (xv.z - mean) * inv + bv.z,
                                    gv.w * (xv.w - mean) * inv + bv.w);
    *(__half2*)(out + (size_t)row * DD + tid * 4)     = o01;
    *(__half2*)(out + (size_t)row * DD + tid * 4 + 2) = o23;
}

// ---------------------------------------------------------------------------
// GELU (tanh approximation, matches reference)
// ---------------------------------------------------------------------------
__device__ __forceinline__ float gelu_f(float x)
{
    const float c = 0.7978845608028654f;  // sqrt(2/pi)
    float inner = c * (x + 0.044715f * x * x * x);
    return 0.5f * x * (1.0f + tanhf(inner));
}

// ---------------------------------------------------------------------------
// fp16 tensor-core GEMM:  C[M,N] = A[M,K] @ Bt[N,K]^T  (+bias)(+gelu)(+resid)
// (unchanged from R10 — near HMMA pipe ceiling)
// ---------------------------------------------------------------------------
#define A_BYTES (128 * 80)          // 10240
#define B_BYTES (256 * 80)          // 20480
#define STG (A_BYTES + B_BYTES)     // 30720
#define NSF 4
#define GEMM_SMEM (NSF * STG)       // 122880

__global__ __launch_bounds__(256, 1) void gemm_h(
    const __half* __restrict__ A, const __half* __restrict__ Bt,
    const float* __restrict__ bias,   // may be null
    const float* __restrict__ resid,  // may be null
    void* __restrict__ Cout,
    int Ndim, int Kdim, int mode)
{
    extern __shared__ __align__(16) char smg[];
    const uint32_t sbase = smem_u32(smg);
    const int tid  = threadIdx.x;
    const int lane = tid & 31;
    const int warp = tid >> 5;
    const int wm   = warp >> 2;     // 0..1
    const int wn   = warp & 3;      // 0..3
    const int gid  = lane >> 2;     // 0..7
    const int tg   = lane & 3;      // 0..3
    const int m0 = blockIdx.y * 128;
    const int n0 = blockIdx.x * 256;

    const uint32_t aoff = (uint32_t)(wm * 64 + (lane & 15)) * 80 + (lane >> 4) * 16;
    const uint32_t boff = A_BYTES +
        (uint32_t)(wn * 64 + (lane & 7) + (lane >> 4) * 8) * 80 +
        ((lane >> 3) & 1) * 16;

    float acc[4][8][4];
    #pragma unroll
    for (int mt = 0; mt < 4; mt++)
        #pragma unroll
        for (int nt = 0; nt < 8; nt++)
            #pragma unroll
            for (int r = 0; r < 4; r++) acc[mt][nt][r] = 0.f;

    const int nkb = Kdim / 32;

    auto issue = [&](int kb, int slot) {
        const uint32_t sb = sbase + slot * STG;
        #pragma unroll
        for (int p = 0; p < 2; p++) {
            const int id = tid + 256 * p;
            const int row = id >> 2, cc = id & 3;
            cp_async16(sb + row * 80 + cc * 16,
                       A + (size_t)(m0 + row) * Kdim + kb * 32 + cc * 8);
        }
        #pragma unroll
        for (int p = 0; p < 4; p++) {
            const int id = tid + 256 * p;
            const int row = id >> 2, cc = id & 3;
            cp_async16(sb + A_BYTES + row * 80 + cc * 16,
                       Bt + (size_t)(n0 + row) * Kdim + kb * 32 + cc * 8);
        }
    };

    issue(0, 0); cp_commit();
    issue(1, 1); cp_commit();
    issue(2, 2); cp_commit();

    int s_cur = 0, s_nxt = 3;

    for (int kb = 0; kb < nkb; kb++) {
        cp_wait<2>();
        __syncthreads();
        if (kb + 3 < nkb) issue(kb + 3, s_nxt);
        cp_commit();

        const uint32_t sA = sbase + s_cur * STG + aoff;
        const uint32_t sB = sbase + s_cur * STG + boff;

        #pragma unroll
        for (int ks = 0; ks < 2; ks++) {
            uint32_t af[4][4], bf[8][2];
            #pragma unroll
            for (int mt = 0; mt < 4; mt++)
                ldsm_x4(af[mt], sA + mt * 1280 + ks * 32);
            #pragma unroll
            for (int ntp = 0; ntp < 4; ntp++) {
                uint32_t t[4];
                ldsm_x4(t, sB + ntp * 1280 + ks * 32);
                bf[2 * ntp][0] = t[0]; bf[2 * ntp][1] = t[1];
                bf[2 * ntp + 1][0] = t[2]; bf[2 * ntp + 1][1] = t[3];
            }
            #pragma unroll
            for (int mt = 0; mt < 4; mt++)
                #pragma unroll
                for (int nt = 0; nt < 8; nt++)
                    mma_f16(acc[mt][nt], af[mt], bf[nt]);
        }

        s_cur = s_cur + 1 == NSF ? 0 : s_cur + 1;
        s_nxt = s_nxt + 1 == NSF ? 0 : s_nxt + 1;
    }

    #pragma unroll
    for (int mt = 0; mt < 4; mt++) {
        #pragma unroll
        for (int half = 0; half < 2; half++) {
            const int row = m0 + wm * 64 + mt * 16 + gid + half * 8;
            #pragma unroll
            for (int nt = 0; nt < 8; nt++) {
                const int col = n0 + wn * 64 + nt * 8 + 2 * tg;
                float v0 = acc[mt][nt][half * 2 + 0];
                float v1 = acc[mt][nt][half * 2 + 1];
                if (bias) { v0 += bias[col]; v1 += bias[col + 1]; }
                if (mode == 1) {
                    __half2 h2 = __floats2half2_rn(gelu_f(v0), gelu_f(v1));
                    *(__half2*)((__half*)Cout + (size_t)row * Ndim + col) = h2;
                } else if (mode == 3) {
                    __half2 h2 = __floats2half2_rn(v0, v1);
                    *(__half2*)((__half*)Cout + (size_t)row * Ndim + col) = h2;
                } else {
                    if (resid) {
                        const float* Rr = resid + (size_t)row * Ndim;
                        v0 += Rr[col]; v1 += Rr[col + 1];
                    }
                    float2 o; o.x = v0; o.y = v1;
                    *(float2*)((float*)Cout + (size_t)row * Ndim + col) = o;
                }
            }
        }
    }
}

// ---------------------------------------------------------------------------
// fp16 tensor-core causal flash attention (m16n8k16, fp32 accum/softmax).
// P stays in registers: the QK C-fragment layout IS the PV A-fragment layout.
// exp2-domain softmax (scale*log2e folded into masking multiply).
// K/V double buffered; smem: Q, K0, V0, K1, V1 = 5 x 9216 = 45 KB.
// __launch_bounds__(128, 4): cap regs at 128 -> 4 CTAs/SM.
// Heavy qt CTAs launch first (reversed mapping) to shrink the grid tail.
// ---------------------------------------------------------------------------
#define AQSTR (3 * DD)
#define ARSTR 144                   // bytes per smem row
#define ATILE_B (64 * ARSTR)        // 9216
#define ATTN_SMEM (5 * ATILE_B)     // 46080

__global__ __launch_bounds__(128, 4) void attn_h(
    const __half* __restrict__ qkv, __half* __restrict__ out)
{
    extern __shared__ __align__(16) char sma[];
    const uint32_t sb = smem_u32(sma);
    const uint32_t Qb = sb;
    // K(i) at tile 1 + 2i, V(i) at tile 2 + 2i

    const int tid  = threadIdx.x;
    const int lane = tid & 31;
    const int warp = tid >> 5;
    const int gid  = lane >> 2;
    const int tg   = lane & 3;
    const int bh = blockIdx.y;
    const int b  = bh / HH;
    const int h  = bh % HH;
    const int qt = gridDim.x - 1 - blockIdx.x;   // heavy tiles first
    const int q0 = qt * 64;

    const size_t qbase = ((size_t)b * TT) * AQSTR + (size_t)h * HD;
    const size_t obase = ((size_t)b * TT) * DD + (size_t)h * HD;

    auto issue_kv = [&](int kt_i, int buf) {
        const int k0i = kt_i * 64;
        const uint32_t Kb = sb + (1 + 2 * buf) * ATILE_B;
        const uint32_t Vb = sb + (2 + 2 * buf) * ATILE_B;
        const __half* ksrc = qkv + qbase + DD     + (size_t)k0i * AQSTR;
        const __half* vsrc = qkv + qbase + 2 * DD + (size_t)k0i * AQSTR;
        #pragma unroll
        for (int p = 0; p < 4; p++) {
            const int id = tid + 128 * p;
            const int r = id >> 3, c = id & 7;
            cp_async16(Kb + r * ARSTR + c * 16, ksrc + (size_t)r * AQSTR + c * 8);
        }
        #pragma unroll
        for (int p = 0; p < 4; p++) {
            const int id = tid + 128 * p;
            const int r = id >> 3, c = id & 7;
            cp_async16(Vb + r * ARSTR + c * 16, vsrc + (size_t)r * AQSTR + c * 8);
        }
    };

    // prologue: Q tile + KV(0)
    {
        const __half* src = qkv + qbase + (size_t)q0 * AQSTR;
        #pragma unroll
        for (int p = 0; p < 4; p++) {
            const int id = tid + 128 * p;
            const int r = id >> 3, c = id & 7;
            cp_async16(Qb + r * ARSTR + c * 16, src + (size_t)r * AQSTR + c * 8);
        }
        cp_commit();
    }
    issue_kv(0, 0);
    cp_commit();

    float mrow[2] = {-1e30f, -1e30f};   // log2-domain running max
    float lrow[2] = {0.f, 0.f};
    float o[8][4];
    #pragma unroll
    for (int nf = 0; nf < 8; nf++)
        #pragma unroll
        for (int c = 0; c < 4; c++) o[nf][c] = 0.f;

    const uint32_t qp_off = (uint32_t)(warp * 16 + (lane & 15)) * ARSTR +
                            (lane >> 4) * 16;
    const uint32_t kp_off = (uint32_t)((lane & 7) + (lane >> 4) * 8) * ARSTR +
                            ((lane >> 3) & 1) * 16;
    const uint32_t vp_off = (uint32_t)((lane & 7) + ((lane >> 3) & 1) * 8) * ARSTR +
                            (lane >> 4) * 16;

    // scale * log2(e): softmax done in exp2 domain
    const float SC2 = 0.125f * 1.4426950408889634f;

    for (int kt = 0; kt <= qt; kt++) {
        const int cur = kt & 1;
        __syncthreads();
        if (kt < qt) {
            issue_kv(kt + 1, cur ^ 1);
            cp_commit();
            cp_wait<1>();
        } else {
            cp_wait<0>();
        }
        __syncthreads();

        const uint32_t Kc = sb + (1 + 2 * cur) * ATILE_B;
        const uint32_t Vc = sb + (2 + 2 * cur) * ATILE_B;

        // S = Q K^T  (warp: 16 x 64)
        float s[8][4];
        #pragma unroll
        for (int nf = 0; nf < 8; nf++)
            #pragma unroll
            for (int c = 0; c < 4; c++) s[nf][c] = 0.f;
        #pragma unroll
        for (int ks = 0; ks < 4; ks++) {
            uint32_t aq[4];
            ldsm_x4(aq, Qb + qp_off + ks * 32);
            #pragma unroll
            for (int ntp = 0; ntp < 4; ntp++) {
                uint32_t t[4];
                ldsm_x4(t, Kc + kp_off + ntp * 16 * ARSTR + ks * 32);
                uint32_t b0[2] = {t[0], t[1]};
                uint32_t b1[2] = {t[2], t[3]};
                mma_f16(s[2 * ntp],     aq, b0);
                mma_f16(s[2 * ntp + 1], aq, b1);
            }
        }

        // scale into exp2 domain + causal mask
        const bool diag = (kt == qt);
        #pragma unroll
        for (int nf = 0; nf < 8; nf++) {
            #pragma unroll
            for (int c = 0; c < 4; c++) {
                float val = s[nf][c] * SC2;
                if (diag) {
                    int row = warp * 16 + gid + (c >= 2 ? 8 : 0);
                    int col = nf * 8 + 2 * tg + (c & 1);
                    if (col > row) val = -1e30f;
                }
                s[nf][c] = val;
            }
        }

        // online softmax (rows gid / gid+8; reduce over tg lanes)
        float mx0 = -1e30f, mx1 = -1e30f;
        #pragma unroll
        for (int nf = 0; nf < 8; nf++) {
            mx0 = fmaxf(mx0, fmaxf(s[nf][0], s[nf][1]));
            mx1 = fmaxf(mx1, fmaxf(s[nf][2], s[nf][3]));
        }
        #pragma unroll
        for (int w = 1; w <= 2; w <<= 1) {
            mx0 = fmaxf(mx0, __shfl_xor_sync(0xffffffffu, mx0, w));
            mx1 = fmaxf(mx1, __shfl_xor_sync(0xffffffffu, mx1, w));
        }
        float mn0 = fmaxf(mrow[0], mx0);
        float mn1 = fmaxf(mrow[1], mx1);
        float al0 = exp2f(mrow[0] - mn0);
        float al1 = exp2f(mrow[1] - mn1);

        float sum0 = 0.f, sum1 = 0.f;
        #pragma unroll
        for (int nf = 0; nf < 8; nf++) {
            s[nf][0] = exp2f(s[nf][0] - mn0);
            s[nf][1] = exp2f(s[nf][1] - mn0);
            s[nf][2] = exp2f(s[nf][2] - mn1);
            s[nf][3] = exp2f(s[nf][3] - mn1);
            sum0 += s[nf][0] + s[nf][1];
            sum1 += s[nf][2] + s[nf][3];
        }
        #pragma unroll
        for (int w = 1; w <= 2; w <<= 1) {
            sum0 += __shfl_xor_sync(0xffffffffu, sum0, w);
            sum1 += __shfl_xor_sync(0xffffffffu, sum1, w);
        }
        lrow[0] = lrow[0] * al0 + sum0;
        lrow[1] = lrow[1] * al1 + sum1;
        mrow[0] = mn0;
        mrow[1] = mn1;

        // rescale accumulator
        #pragma unroll
        for (int nf = 0; nf < 8; nf++) {
            o[nf][0] *= al0; o[nf][1] *= al0;
            o[nf][2] *= al1; o[nf][3] *= al1;
        }

        // O += P V — P taken straight from the S registers:
        // A-frag(k-block ks) = {h2(s[2ks][0],s[2ks][1]), h2(s[2ks][2],s[2ks][3]),
        //                       h2(s[2ks+1][0],s[2ks+1][1]), h2(s[2ks+1][2],s[2ks+1][3])}
        #pragma unroll
        for (int ks = 0; ks < 4; ks++) {
            uint32_t ap[4];
            ap[0] = pack_h2(s[2 * ks][0],     s[2 * ks][1]);
            ap[1] = pack_h2(s[2 * ks][2],     s[2 * ks][3]);
            ap[2] = pack_h2(s[2 * ks + 1][0], s[2 * ks + 1][1]);
            ap[3] = pack_h2(s[2 * ks + 1][2], s[2 * ks + 1][3]);
            #pragma unroll
            for (int ntp = 0; ntp < 4; ntp++) {
                uint32_t t[4];
                ldsm_x4_t(t, Vc + vp_off + ks * 16 * ARSTR + ntp * 32);
                uint32_t b0[2] = {t[0], t[1]};
                uint32_t b1[2] = {t[2], t[3]};
                mma_f16(o[2 * ntp],     ap, b0);
                mma_f16(o[2 * ntp + 1], ap, b1);
            }
        }
    }

    const float inv0 = 1.0f / lrow[0];
    const float inv1 = 1.0f / lrow[1];
    const int r0 = q0 + warp * 16 + gid;
    #pragma unroll
    for (int nf = 0; nf < 8; nf++) {
        const int col = nf * 8 + 2 * tg;
        __half2 w0 = __floats2half2_rn(o[nf][0] * inv0, o[nf][1] * inv0);
        __half2 w1 = __floats2half2_rn(o[nf][2] * inv1, o[nf][3] * inv1);
        *(__half2*)(out + obase + (size_t)r0 * DD + col)       = w0;
        *(__half2*)(out + obase + (size_t)(r0 + 8) * DD + col) = w1;
    }
}

// ---------------------------------------------------------------------------
// Host launch
// ---------------------------------------------------------------------------
extern "C" void kernel_launch(void* const* d_in, const int* in_sizes, int n_in,
                              void* d_out, int out_size)
{
    const float* x    = (const float*)d_in[0];
    const float* Wq   = (const float*)d_in[1];
    const float* Wk   = (const float*)d_in[2];
    const float* Wv   = (const float*)d_in[3];
    const float* Wo   = (const float*)d_in[4];
    const float* bo   = (const float*)d_in[5];
    const float* W1   = (const float*)d_in[6];
    const float* b1   = (const float*)d_in[7];
    const float* W2   = (const float*)d_in[8];
    const float* b2   = (const float*)d_in[9];
    const float* g1   = (const float*)d_in[10];
    const float* be1  = (const float*)d_in[11];
    const float* g2   = (const float*)d_in[12];
    const float* be2  = (const float*)d_in[13];
    float* out = (float*)d_out;

    __half *h, *qkv, *attn, *h2, *ff1, *wqkv, *wo, *w1, *w2;
    float *x2;
    cudaGetSymbolAddress((void**)&h,    g_h);
    cudaGetSymbolAddress((void**)&qkv,  g_qkv);
    cudaGetSymbolAddress((void**)&attn, g_attn);
    cudaGetSymbolAddress((void**)&x2,   g_x2);
    cudaGetSymbolAddress((void**)&h2,   g_h2);
    cudaGetSymbolAddress((void**)&ff1,  g_ff1);
    cudaGetSymbolAddress((void**)&wqkv, g_wqkv);
    cudaGetSymbolAddress((void**)&wo,   g_wo);
    cudaGetSymbolAddress((void**)&w1,   g_w1);
    cudaGetSymbolAddress((void**)&w2,   g_w2);

    cudaFuncSetAttribute(attn_h,
                         cudaFuncAttributeMaxDynamicSharedMemorySize, ATTN_SMEM);
    cudaFuncSetAttribute(gemm_h,
                         cudaFuncAttributeMaxDynamicSharedMemorySize, GEMM_SMEM);

    // 0) weight preprocessing: all transposes in one launch
    transpose_all_kernel<<<12288, 256>>>(Wq, Wk, Wv, Wo, W1, W2,
                                         wqkv, wo, w1, w2);

    // 1) LN1 -> fp16
    layernorm_kernel<<<MM, 256>>>(x, g1, be1, h);

    // 2) fused QKV projection -> fp16
    gemm_h<<<dim3(3 * DD / 256, MM / 128), 256, GEMM_SMEM>>>(
        h, wqkv, nullptr, nullptr, qkv, 3 * DD, DD, 3);

    // 3) causal attention (fp16 tensor cores, P-in-registers)
    attn_h<<<dim3(TT / 64, BB * HH), 128, ATTN_SMEM>>>(qkv, attn);

    // 4) output projection + bias + residual(x) -> fp32
    dim3 gDD(DD / 256, MM / 128);
    gemm_h<<<gDD, 256, GEMM_SMEM>>>(attn, wo, bo, x, x2, DD, DD, 2);

    // 5) LN2 -> fp16
    layernorm_kernel<<<MM, 256>>>(x2, g2, be2, h2);

    // 6) FFN1 + bias + GELU -> fp16
    gemm_h<<<dim3(FF / 256, MM / 128), 256, GEMM_SMEM>>>(
        h2, w1, b1, nullptr, ff1, FF, DD, 1);

    // 7) FFN2 + bias + residual(x2) -> out (fp32)
    gemm_h<<<gDD, 256, GEMM_SMEM>>>(ff1, w2, b2, x2, out, DD, FF, 2);
}

// round 13
// speedup vs baseline: 7.1411x; 1.1138x over previous
#include <cuda_runtime.h>
#include <cuda_fp16.h>
#include <math.h>
#include <stdint.h>

// ---------------------------------------------------------------------------
// Problem constants
// ---------------------------------------------------------------------------
#define BB 4
#define TT 2048
#define DD 1024
#define HH 16
#define HD 64
#define FF 4096
#define MM (BB * TT)       // 8192 rows
#define EPS 1e-5f

// ---------------------------------------------------------------------------
// Scratch (allocation-free: __device__ globals)
// ---------------------------------------------------------------------------
__device__ __half g_h   [(size_t)MM * DD];      // LN1 out (fp16)
__device__ __half g_qkv [(size_t)MM * 3 * DD];  // QKV out (fp16)
__device__ __half g_attn[(size_t)MM * DD];      // attention out (fp16)
__device__ float  g_x2  [(size_t)MM * DD];      // residual stream 2 (fp32)
__device__ __half g_h2  [(size_t)MM * DD];      // LN2 out (fp16)
__device__ __half g_ff1 [(size_t)MM * FF];      // FFN1 out (fp16)
// fp16 weights, transposed to [N][K]
__device__ __half g_wqkv[(size_t)(3 * DD) * DD];
__device__ __half g_wo  [(size_t)DD * DD];
__device__ __half g_w1  [(size_t)FF * DD];
__device__ __half g_w2  [(size_t)DD * FF];

// ---------------------------------------------------------------------------
// helpers
// ---------------------------------------------------------------------------
__device__ __forceinline__ void mma_f16(float c[4], const uint32_t a[4],
                                        const uint32_t b[2]) {
    asm volatile(
        "mma.sync.aligned.m16n8k16.row.col.f32.f16.f16.f32 "
        "{%0,%1,%2,%3}, {%4,%5,%6,%7}, {%8,%9}, {%0,%1,%2,%3};"
        : "+f"(c[0]), "+f"(c[1]), "+f"(c[2]), "+f"(c[3])
        : "r"(a[0]), "r"(a[1]), "r"(a[2]), "r"(a[3]), "r"(b[0]), "r"(b[1]));
}
__device__ __forceinline__ void ldsm_x4(uint32_t r[4], uint32_t saddr) {
    asm volatile("ldmatrix.sync.aligned.m8n8.x4.shared.b16 {%0,%1,%2,%3}, [%4];"
        : "=r"(r[0]), "=r"(r[1]), "=r"(r[2]), "=r"(r[3]) : "r"(saddr));
}
__device__ __forceinline__ void ldsm_x4_t(uint32_t r[4], uint32_t saddr) {
    asm volatile("ldmatrix.sync.aligned.m8n8.x4.trans.shared.b16 {%0,%1,%2,%3}, [%4];"
        : "=r"(r[0]), "=r"(r[1]), "=r"(r[2]), "=r"(r[3]) : "r"(saddr));
}
__device__ __forceinline__ void cp_async16(uint32_t saddr, const void* gptr) {
    asm volatile("cp.async.cg.shared.global [%0], [%1], 16;"
                 :: "r"(saddr), "l"(gptr) : "memory");
}
__device__ __forceinline__ void cp_commit() {
    asm volatile("cp.async.commit_group;" ::: "memory");
}
template <int N>
__device__ __forceinline__ void cp_wait() {
    asm volatile("cp.async.wait_group %0;" :: "n"(N) : "memory");
}
__device__ __forceinline__ uint32_t smem_u32(const void* p) {
    uint32_t a;
    asm("{ .reg .u64 t; cvta.to.shared.u64 t, %1; cvt.u32.u64 %0, t; }"
        : "=r"(a) : "l"(p));
    return a;
}
__device__ __forceinline__ uint32_t pack_h2(float a, float b) {
    __half2 h = __floats2half2_rn(a, b);
    return *(uint32_t*)&h;
}

// ---------------------------------------------------------------------------
// Weight preprocessing: all 6 transposes ([R][C] fp32 -> [C][R] fp16) fused
// into one launch.
// ---------------------------------------------------------------------------
__global__ __launch_bounds__(256) void transpose_all_kernel(
    const float* __restrict__ Wq, const float* __restrict__ Wk,
    const float* __restrict__ Wv, const float* __restrict__ Wo,
    const float* __restrict__ W1, const float* __restrict__ W2,
    __half* __restrict__ wqkv, __half* __restrict__ wo,
    __half* __restrict__ w1, __half* __restrict__ w2)
{
    const int id = blockIdx.x;
    const float* in;
    __half* out;
    int R, C, bx, by;
    if (id < 4096) {
        const int w = id >> 10, t = id & 1023;
        bx = t & 31; by = t >> 5;
        R = DD; C = DD;
        if (w == 0)      { in = Wq; out = wqkv; }
        else if (w == 1) { in = Wk; out = wqkv + (size_t)DD * DD; }
        else if (w == 2) { in = Wv; out = wqkv + (size_t)2 * DD * DD; }
        else             { in = Wo; out = wo; }
    } else if (id < 8192) {
        const int t = id - 4096;
        bx = t & 127; by = t >> 7;
        in = W1; out = w1; R = DD; C = FF;
    } else {
        const int t = id - 8192;
        bx = t & 31; by = t >> 5;
        in = W2; out = w2; R = FF; C = DD;
    }

    __shared__ float tl[32][33];
    const int c0 = bx * 32;
    const int r0 = by * 32;
    const int tx = threadIdx.x & 31, ty = threadIdx.x >> 5;
    #pragma unroll
    for (int i = 0; i < 32; i += 8)
        tl[ty + i][tx] = in[(size_t)(r0 + ty + i) * C + c0 + tx];
    __syncthreads();
    #pragma unroll
    for (int i = 0; i < 32; i += 8)
        out[(size_t)(c0 + ty + i) * R + r0 + tx] = __float2half_rn(tl[tx][ty + i]);
}

// ---------------------------------------------------------------------------
// LayerNorm: one block (256 threads) per row of 1024; writes fp16
// ---------------------------------------------------------------------------
__global__ __launch_bounds__(256) void layernorm_kernel(
    const float* __restrict__ x, const float* __restrict__ gamma,
    const float* __restrict__ beta, __half* __restrict__ out)
{
    __shared__ float shs[8], shss[8];
    __shared__ float s_mean, s_inv;
    const int row = blockIdx.x;
    const int tid = threadIdx.x;

    const float4 xv = *(const float4*)(x + (size_t)row * DD + tid * 4);
    float s  = xv.x + xv.y + xv.z + xv.w;
    float ss = xv.x * xv.x + xv.y * xv.y + xv.z * xv.z + xv.w * xv.w;
    #pragma unroll
    for (int o = 16; o > 0; o >>= 1) {
        s  += __shfl_down_sync(0xffffffffu, s, o);
        ss += __shfl_down_sync(0xffffffffu, ss, o);
    }
    if ((tid & 31) == 0) { shs[tid >> 5] = s; shss[tid >> 5] = ss; }
    __syncthreads();
    if (tid == 0) {
        float S = 0.f, SS = 0.f;
        #pragma unroll
        for (int i = 0; i < 8; i++) { S += shs[i]; SS += shss[i]; }
        float mean = S * (1.0f / DD);
        float var  = SS * (1.0f / DD) - mean * mean;
        s_mean = mean;
        s_inv  = rsqrtf(var + EPS);
    }
    __syncthreads();
    const float mean = s_mean, inv = s_inv;
    const float4 gv = *(const float4*)(gamma + tid * 4);
    const float4 bv = *(const float4*)(beta  + tid * 4);
    __half2 o01 = __floats2half2_rn(gv.x * (xv.x - mean) * inv + bv.x,
                                    gv.y * (xv.y - mean) * inv + bv.y);
    __half2 o23 = __floats2half2_rn(gv.z * (xv.z - mean) * inv + bv.z,
                                    gv.w * (xv.w - mean) * inv + bv.w);
    *(__half2*)(out + (size_t)row * DD + tid * 4)     = o01;
    *(__half2*)(out + (size_t)row * DD + tid * 4 + 2) = o23;
}

// ---------------------------------------------------------------------------
// GELU (tanh approximation, matches reference)
// ---------------------------------------------------------------------------
__device__ __forceinline__ float gelu_f(float x)
{
    const float c = 0.7978845608028654f;  // sqrt(2/pi)
    float inner = c * (x + 0.044715f * x * x * x);
    return 0.5f * x * (1.0f + tanhf(inner));
}

// ---------------------------------------------------------------------------
// fp16 tensor-core GEMM:  C[M,N] = A[M,K] @ Bt[N,K]^T  (+bias)(+gelu)(+resid)
// CTA tile 128x256, BK=32 — now with 512 threads / 16 warps (4 per SMSP)
// in a 4x4 warp grid, warp tile 32x64 (acc 64 regs/thread). Same fragment
// mappings as the 256-thread version, mt range halved. cp.async 4-stage.
// mode: 0 = fp32 out plain, 1 = fp16 out bias+gelu, 2 = fp32 out bias+resid,
//       3 = fp16 out plain
// ---------------------------------------------------------------------------
#define A_BYTES (128 * 80)          // 10240
#define B_BYTES (256 * 80)          // 20480
#define STG (A_BYTES + B_BYTES)     // 30720
#define NSF 4
#define GEMM_SMEM (NSF * STG)       // 122880

__global__ __launch_bounds__(512, 1) void gemm_h(
    const __half* __restrict__ A, const __half* __restrict__ Bt,
    const float* __restrict__ bias,   // may be null
    const float* __restrict__ resid,  // may be null
    void* __restrict__ Cout,
    int Ndim, int Kdim, int mode)
{
    extern __shared__ __align__(16) char smg[];
    const uint32_t sbase = smem_u32(smg);
    const int tid  = threadIdx.x;
    const int lane = tid & 31;
    const int warp = tid >> 5;      // 0..15
    const int wm   = warp >> 2;     // 0..3  (32-row slab)
    const int wn   = warp & 3;      // 0..3  (64-col slab)
    const int gid  = lane >> 2;     // 0..7
    const int tg   = lane & 3;      // 0..3
    const int m0 = blockIdx.y * 128;
    const int n0 = blockIdx.x * 256;

    // ldmatrix per-lane offsets (within a stage)
    const uint32_t aoff = (uint32_t)(wm * 32 + (lane & 15)) * 80 + (lane >> 4) * 16;
    const uint32_t boff = A_BYTES +
        (uint32_t)(wn * 64 + (lane & 7) + (lane >> 4) * 8) * 80 +
        ((lane >> 3) & 1) * 16;

    float acc[2][8][4];
    #pragma unroll
    for (int mt = 0; mt < 2; mt++)
        #pragma unroll
        for (int nt = 0; nt < 8; nt++)
            #pragma unroll
            for (int r = 0; r < 4; r++) acc[mt][nt][r] = 0.f;

    const int nkb = Kdim / 32;

    auto issue = [&](int kb, int slot) {
        const uint32_t sb = sbase + slot * STG;
        {   // A: 512 chunks of 16B, one per thread
            const int row = tid >> 2, cc = tid & 3;
            cp_async16(sb + row * 80 + cc * 16,
                       A + (size_t)(m0 + row) * Kdim + kb * 32 + cc * 8);
        }
        #pragma unroll
        for (int p = 0; p < 2; p++) {   // B: 1024 chunks, two per thread
            const int id = tid + 512 * p;
            const int row = id >> 2, cc = id & 3;
            cp_async16(sb + A_BYTES + row * 80 + cc * 16,
                       Bt + (size_t)(n0 + row) * Kdim + kb * 32 + cc * 8);
        }
    };

    issue(0, 0); cp_commit();
    issue(1, 1); cp_commit();
    issue(2, 2); cp_commit();

    int s_cur = 0, s_nxt = 3;

    for (int kb = 0; kb < nkb; kb++) {
        cp_wait<2>();
        __syncthreads();
        if (kb + 3 < nkb) issue(kb + 3, s_nxt);
        cp_commit();

        const uint32_t sA = sbase + s_cur * STG + aoff;
        const uint32_t sB = sbase + s_cur * STG + boff;

        #pragma unroll
        for (int ks = 0; ks < 2; ks++) {
            uint32_t af[2][4], bf[8][2];
            #pragma unroll
            for (int mt = 0; mt < 2; mt++)
                ldsm_x4(af[mt], sA + mt * 1280 + ks * 32);
            #pragma unroll
            for (int ntp = 0; ntp < 4; ntp++) {
                uint32_t t[4];
                ldsm_x4(t, sB + ntp * 1280 + ks * 32);
                bf[2 * ntp][0] = t[0]; bf[2 * ntp][1] = t[1];
                bf[2 * ntp + 1][0] = t[2]; bf[2 * ntp + 1][1] = t[3];
            }
            #pragma unroll
            for (int mt = 0; mt < 2; mt++)
                #pragma unroll
                for (int nt = 0; nt < 8; nt++)
                    mma_f16(acc[mt][nt], af[mt], bf[nt]);
        }

        s_cur = s_cur + 1 == NSF ? 0 : s_cur + 1;
        s_nxt = s_nxt + 1 == NSF ? 0 : s_nxt + 1;
    }

    // epilogue
    #pragma unroll
    for (int mt = 0; mt < 2; mt++) {
        #pragma unroll
        for (int half = 0; half < 2; half++) {
            const int row = m0 + wm * 32 + mt * 16 + gid + half * 8;
            #pragma unroll
            for (int nt = 0; nt < 8; nt++) {
                const int col = n0 + wn * 64 + nt * 8 + 2 * tg;
                float v0 = acc[mt][nt][half * 2 + 0];
                float v1 = acc[mt][nt][half * 2 + 1];
                if (bias) { v0 += bias[col]; v1 += bias[col + 1]; }
                if (mode == 1) {
                    __half2 h2 = __floats2half2_rn(gelu_f(v0), gelu_f(v1));
                    *(__half2*)((__half*)Cout + (size_t)row * Ndim + col) = h2;
                } else if (mode == 3) {
                    __half2 h2 = __floats2half2_rn(v0, v1);
                    *(__half2*)((__half*)Cout + (size_t)row * Ndim + col) = h2;
                } else {
                    if (resid) {
                        const float* Rr = resid + (size_t)row * Ndim;
                        v0 += Rr[col]; v1 += Rr[col + 1];
                    }
                    float2 o; o.x = v0; o.y = v1;
                    *(float2*)((float*)Cout + (size_t)row * Ndim + col) = o;
                }
            }
        }
    }
}

// ---------------------------------------------------------------------------
// fp16 tensor-core causal flash attention (m16n8k16, fp32 accum/softmax).
// P in registers, exp2-domain softmax, K/V double buffered. (unchanged R12)
// ---------------------------------------------------------------------------
#define AQSTR (3 * DD)
#define ARSTR 144                   // bytes per smem row
#define ATILE_B (64 * ARSTR)        // 9216
#define ATTN_SMEM (5 * ATILE_B)     // 46080

__global__ __launch_bounds__(128, 4) void attn_h(
    const __half* __restrict__ qkv, __half* __restrict__ out)
{
    extern __shared__ __align__(16) char sma[];
    const uint32_t sb = smem_u32(sma);
    const uint32_t Qb = sb;

    const int tid  = threadIdx.x;
    const int lane = tid & 31;
    const int warp = tid >> 5;
    const int gid  = lane >> 2;
    const int tg   = lane & 3;
    const int bh = blockIdx.y;
    const int b  = bh / HH;
    const int h  = bh % HH;
    const int qt = gridDim.x - 1 - blockIdx.x;   // heavy tiles first
    const int q0 = qt * 64;

    const size_t qbase = ((size_t)b * TT) * AQSTR + (size_t)h * HD;
    const size_t obase = ((size_t)b * TT) * DD + (size_t)h * HD;

    auto issue_kv = [&](int kt_i, int buf) {
        const int k0i = kt_i * 64;
        const uint32_t Kb = sb + (1 + 2 * buf) * ATILE_B;
        const uint32_t Vb = sb + (2 + 2 * buf) * ATILE_B;
        const __half* ksrc = qkv + qbase + DD     + (size_t)k0i * AQSTR;
        const __half* vsrc = qkv + qbase + 2 * DD + (size_t)k0i * AQSTR;
        #pragma unroll
        for (int p = 0; p < 4; p++) {
            const int id = tid + 128 * p;
            const int r = id >> 3, c = id & 7;
            cp_async16(Kb + r * ARSTR + c * 16, ksrc + (size_t)r * AQSTR + c * 8);
        }
        #pragma unroll
        for (int p = 0; p < 4; p++) {
            const int id = tid + 128 * p;
            const int r = id >> 3, c = id & 7;
            cp_async16(Vb + r * ARSTR + c * 16, vsrc + (size_t)r * AQSTR + c * 8);
        }
    };

    {
        const __half* src = qkv + qbase + (size_t)q0 * AQSTR;
        #pragma unroll
        for (int p = 0; p < 4; p++) {
            const int id = tid + 128 * p;
            const int r = id >> 3, c = id & 7;
            cp_async16(Qb + r * ARSTR + c * 16, src + (size_t)r * AQSTR + c * 8);
        }
        cp_commit();
    }
    issue_kv(0, 0);
    cp_commit();

    float mrow[2] = {-1e30f, -1e30f};
    float lrow[2] = {0.f, 0.f};
    float o[8][4];
    #pragma unroll
    for (int nf = 0; nf < 8; nf++)
        #pragma unroll
        for (int c = 0; c < 4; c++) o[nf][c] = 0.f;

    const uint32_t qp_off = (uint32_t)(warp * 16 + (lane & 15)) * ARSTR +
                            (lane >> 4) * 16;
    const uint32_t kp_off = (uint32_t)((lane & 7) + (lane >> 4) * 8) * ARSTR +
                            ((lane >> 3) & 1) * 16;
    const uint32_t vp_off = (uint32_t)((lane & 7) + ((lane >> 3) & 1) * 8) * ARSTR +
                            (lane >> 4) * 16;

    const float SC2 = 0.125f * 1.4426950408889634f;

    for (int kt = 0; kt <= qt; kt++) {
        const int cur = kt & 1;
        __syncthreads();
        if (kt < qt) {
            issue_kv(kt + 1, cur ^ 1);
            cp_commit();
            cp_wait<1>();
        } else {
            cp_wait<0>();
        }
        __syncthreads();

        const uint32_t Kc = sb + (1 + 2 * cur) * ATILE_B;
        const uint32_t Vc = sb + (2 + 2 * cur) * ATILE_B;

        float s[8][4];
        #pragma unroll
        for (int nf = 0; nf < 8; nf++)
            #pragma unroll
            for (int c = 0; c < 4; c++) s[nf][c] = 0.f;
        #pragma unroll
        for (int ks = 0; ks < 4; ks++) {
            uint32_t aq[4];
            ldsm_x4(aq, Qb + qp_off + ks * 32);
            #pragma unroll
            for (int ntp = 0; ntp < 4; ntp++) {
                uint32_t t[4];
                ldsm_x4(t, Kc + kp_off + ntp * 16 * ARSTR + ks * 32);
                uint32_t b0[2] = {t[0], t[1]};
                uint32_t b1[2] = {t[2], t[3]};
                mma_f16(s[2 * ntp],     aq, b0);
                mma_f16(s[2 * ntp + 1], aq, b1);
            }
        }

        const bool diag = (kt == qt);
        #pragma unroll
        for (int nf = 0; nf < 8; nf++) {
            #pragma unroll
            for (int c = 0; c < 4; c++) {
                float val = s[nf][c] * SC2;
                if (diag) {
                    int row = warp * 16 + gid + (c >= 2 ? 8 : 0);
                    int col = nf * 8 + 2 * tg + (c & 1);
                    if (col > row) val = -1e30f;
                }
                s[nf][c] = val;
            }
        }

        float mx0 = -1e30f, mx1 = -1e30f;
        #pragma unroll
        for (int nf = 0; nf < 8; nf++) {
            mx0 = fmaxf(mx0, fmaxf(s[nf][0], s[nf][1]));
            mx1 = fmaxf(mx1, fmaxf(s[nf][2], s[nf][3]));
        }
        #pragma unroll
        for (int w = 1; w <= 2; w <<= 1) {
            mx0 = fmaxf(mx0, __shfl_xor_sync(0xffffffffu, mx0, w));
            mx1 = fmaxf(mx1, __shfl_xor_sync(0xffffffffu, mx1, w));
        }
        float mn0 = fmaxf(mrow[0], mx0);
        float mn1 = fmaxf(mrow[1], mx1);
        float al0 = exp2f(mrow[0] - mn0);
        float al1 = exp2f(mrow[1] - mn1);

        float sum0 = 0.f, sum1 = 0.f;
        #pragma unroll
        for (int nf = 0; nf < 8; nf++) {
            s[nf][0] = exp2f(s[nf][0] - mn0);
            s[nf][1] = exp2f(s[nf][1] - mn0);
            s[nf][2] = exp2f(s[nf][2] - mn1);
            s[nf][3] = exp2f(s[nf][3] - mn1);
            sum0 += s[nf][0] + s[nf][1];
            sum1 += s[nf][2] + s[nf][3];
        }
        #pragma unroll
        for (int w = 1; w <= 2; w <<= 1) {
            sum0 += __shfl_xor_sync(0xffffffffu, sum0, w);
            sum1 += __shfl_xor_sync(0xffffffffu, sum1, w);
        }
        lrow[0] = lrow[0] * al0 + sum0;
        lrow[1] = lrow[1] * al1 + sum1;
        mrow[0] = mn0;
        mrow[1] = mn1;

        #pragma unroll
        for (int nf = 0; nf < 8; nf++) {
            o[nf][0] *= al0; o[nf][1] *= al0;
            o[nf][2] *= al1; o[nf][3] *= al1;
        }

        #pragma unroll
        for (int ks = 0; ks < 4; ks++) {
            uint32_t ap[4];
            ap[0] = pack_h2(s[2 * ks][0],     s[2 * ks][1]);
            ap[1] = pack_h2(s[2 * ks][2],     s[2 * ks][3]);
            ap[2] = pack_h2(s[2 * ks + 1][0], s[2 * ks + 1][1]);
            ap[3] = pack_h2(s[2 * ks + 1][2], s[2 * ks + 1][3]);
            #pragma unroll
            for (int ntp = 0; ntp < 4; ntp++) {
                uint32_t t[4];
                ldsm_x4_t(t, Vc + vp_off + ks * 16 * ARSTR + ntp * 32);
                uint32_t b0[2] = {t[0], t[1]};
                uint32_t b1[2] = {t[2], t[3]};
                mma_f16(o[2 * ntp],     ap, b0);
                mma_f16(o[2 * ntp + 1], ap, b1);
            }
        }
    }

    const float inv0 = 1.0f / lrow[0];
    const float inv1 = 1.0f / lrow[1];
    const int r0 = q0 + warp * 16 + gid;
    #pragma unroll
    for (int nf = 0; nf < 8; nf++) {
        const int col = nf * 8 + 2 * tg;
        __half2 w0 = __floats2half2_rn(o[nf][0] * inv0, o[nf][1] * inv0);
        __half2 w1 = __floats2half2_rn(o[nf][2] * inv1, o[nf][3] * inv1);
        *(__half2*)(out + obase + (size_t)r0 * DD + col)       = w0;
        *(__half2*)(out + obase + (size_t)(r0 + 8) * DD + col) = w1;
    }
}

// ---------------------------------------------------------------------------
// Host launch
// ---------------------------------------------------------------------------
extern "C" void kernel_launch(void* const* d_in, const int* in_sizes, int n_in,
                              void* d_out, int out_size)
{
    const float* x    = (const float*)d_in[0];
    const float* Wq   = (const float*)d_in[1];
    const float* Wk   = (const float*)d_in[2];
    const float* Wv   = (const float*)d_in[3];
    const float* Wo   = (const float*)d_in[4];
    const float* bo   = (const float*)d_in[5];
    const float* W1   = (const float*)d_in[6];
    const float* b1   = (const float*)d_in[7];
    const float* W2   = (const float*)d_in[8];
    const float* b2   = (const float*)d_in[9];
    const float* g1   = (const float*)d_in[10];
    const float* be1  = (const float*)d_in[11];
    const float* g2   = (const float*)d_in[12];
    const float* be2  = (const float*)d_in[13];
    float* out = (float*)d_out;

    __half *h, *qkv, *attn, *h2, *ff1, *wqkv, *wo, *w1, *w2;
    float *x2;
    cudaGetSymbolAddress((void**)&h,    g_h);
    cudaGetSymbolAddress((void**)&qkv,  g_qkv);
    cudaGetSymbolAddress((void**)&attn, g_attn);
    cudaGetSymbolAddress((void**)&x2,   g_x2);
    cudaGetSymbolAddress((void**)&h2,   g_h2);
    cudaGetSymbolAddress((void**)&ff1,  g_ff1);
    cudaGetSymbolAddress((void**)&wqkv, g_wqkv);
    cudaGetSymbolAddress((void**)&wo,   g_wo);
    cudaGetSymbolAddress((void**)&w1,   g_w1);
    cudaGetSymbolAddress((void**)&w2,   g_w2);

    cudaFuncSetAttribute(attn_h,
                         cudaFuncAttributeMaxDynamicSharedMemorySize, ATTN_SMEM);
    cudaFuncSetAttribute(gemm_h,
                         cudaFuncAttributeMaxDynamicSharedMemorySize, GEMM_SMEM);

    // 0) weight preprocessing: all transposes in one launch
    transpose_all_kernel<<<12288, 256>>>(Wq, Wk, Wv, Wo, W1, W2,
                                         wqkv, wo, w1, w2);

    // 1) LN1 -> fp16
    layernorm_kernel<<<MM, 256>>>(x, g1, be1, h);

    // 2) fused QKV projection -> fp16
    gemm_h<<<dim3(3 * DD / 256, MM / 128), 512, GEMM_SMEM>>>(
        h, wqkv, nullptr, nullptr, qkv, 3 * DD, DD, 3);

    // 3) causal attention (fp16 tensor cores, P-in-registers)
    attn_h<<<dim3(TT / 64, BB * HH), 128, ATTN_SMEM>>>(qkv, attn);

    // 4) output projection + bias + residual(x) -> fp32
    dim3 gDD(DD / 256, MM / 128);
    gemm_h<<<gDD, 512, GEMM_SMEM>>>(attn, wo, bo, x, x2, DD, DD, 2);

    // 5) LN2 -> fp16
    layernorm_kernel<<<MM, 256>>>(x2, g2, be2, h2);

    // 6) FFN1 + bias + GELU -> fp16
    gemm_h<<<dim3(FF / 256, MM / 128), 512, GEMM_SMEM>>>(
        h2, w1, b1, nullptr, ff1, FF, DD, 1);

    // 7) FFN2 + bias + residual(x2) -> out (fp32)
    gemm_h<<<gDD, 512, GEMM_SMEM>>>(ff1, w2, b2, x2, out, DD, FF, 2);
}